// round 2
// baseline (speedup 1.0000x reference)
#include <cuda_runtime.h>
#include <math.h>

#define BB 4
#define KQn 192
#define KPn 192
#define Hn 256
#define Tn 32
#define Rn 768
#define NEGV (-1e9f)
#define SCALEV (0.17677669529663687f)   // 1/sqrt(32)

// ---------------- scratch (static device globals; no runtime allocation) ----------------
static __device__ float g_A1[BB * KQn * Tn];       // Eq @ W1^T
static __device__ float g_A2[BB * KPn * Tn];       // Ep @ W2^T
static __device__ float g_u1[BB * KQn];            // Eq . w_out[0:H]
static __device__ float g_u2[BB * KPn];            // Ep . w_out[H:2H]
static __device__ float g_fq[BB * KPn * KQn * Tn];
static __device__ float g_fk[BB * KPn * KQn * Tn]; // pre-scaled by obv*SCALE
static __device__ float g_fv[BB * KPn * KQn * Tn];
static __device__ float g_M[BB * KPn * KQn * Tn];  // horizontal contribution only
static __device__ float g_Um[BB * KPn * KQn];      // M_total . w4
static __device__ float g_U[BB * KPn * KQn];
static __device__ float g_Gl[BB * KPn * Rn];
static __device__ float g_Gr[BB * KQn * Rn];
static __device__ float g_left[BB * KPn * Rn];
static __device__ float g_right[BB * KQn * Rn];
static __device__ float g_part[4 * BB * KPn * KQn]; // k7 split-K partials

__device__ __forceinline__ float dot4(float4 a, float4 b) {
    return a.x * b.x + a.y * b.y + a.z * b.z + a.w * b.w;
}

// ---------------- K0: per-row projections A1/A2 and u1/u2 ----------------
__global__ __launch_bounds__(256) void k0_rowproj(
    const float* __restrict__ Eq, const float* __restrict__ Ep,
    const float* __restrict__ W_in, const float* __restrict__ W_out)
{
    const int b = blockIdx.x;
    const int side = blockIdx.y;
    const float* src = side ? (Ep + b * KPn * Hn) : (Eq + b * KQn * Hn);
    const int woff = side ? Hn : 0;
    float* A = side ? (g_A2 + b * KPn * Tn) : (g_A1 + b * KQn * Tn);
    float* u = side ? (g_u2 + b * KPn) : (g_u1 + b * KQn);

    __shared__ float sW[Tn][Hn + 1];
    __shared__ float swv[Hn];
    const int tid = threadIdx.y * 32 + threadIdx.x;
    for (int i = tid; i < Tn * Hn; i += 256) {
        int t = i >> 8, h = i & 255;
        sW[t][h] = W_in[t * Rn + woff + h];
    }
    for (int i = tid; i < Hn; i += 256) swv[i] = W_out[woff + i];
    __syncthreads();

    const int t = threadIdx.x;
    for (int y = threadIdx.y; y < 192; y += 8) {
        const float* row = src + y * Hn;
        float acc = 0.f, up = 0.f;
        for (int h = 0; h < Hn; h++) acc += row[h] * sW[t][h];
        for (int h = t; h < Hn; h += 32) up += row[h] * swv[h];
        #pragma unroll
        for (int o = 16; o; o >>= 1) up += __shfl_down_sync(0xffffffffu, up, o);
        A[y * Tn + t] = acc;
        if (t == 0) u[y] = up;
    }
}

// dst = (e1 @ W^T + bias) * scale
__device__ __forceinline__ void small_mm_store(const float* e1, const float* __restrict__ W,
                                               const float* __restrict__ bias, float scale,
                                               float* __restrict__ dst)
{
    float4* d = reinterpret_cast<float4*>(dst);
    #pragma unroll
    for (int u4 = 0; u4 < 8; u4++) {
        float r[4];
        #pragma unroll
        for (int uu = 0; uu < 4; uu++) {
            const int u = u4 * 4 + uu;
            float s = bias[u];
            const float4* w4 = reinterpret_cast<const float4*>(W + u * Tn);
            #pragma unroll
            for (int t4 = 0; t4 < 8; t4++) {
                float4 w = w4[t4];
                s += e1[t4 * 4 + 0] * w.x + e1[t4 * 4 + 1] * w.y
                   + e1[t4 * 4 + 2] * w.z + e1[t4 * 4 + 3] * w.w;
            }
            r[uu] = s * scale;
        }
        d[u4] = make_float4(r[0], r[1], r[2], r[3]);
    }
}

// ---------------- K1: per (b,p): bilinear E1 + fq/fk(scaled)/fv fused; 2 queries/thread ----------------
__global__ __launch_bounds__(96) void k1_pair(
    const float* __restrict__ Eq, const float* __restrict__ Ep,
    const float* __restrict__ W_in,
    const float* __restrict__ Wq, const float* __restrict__ bq,
    const float* __restrict__ Wk, const float* __restrict__ bk,
    const float* __restrict__ Wv, const float* __restrict__ bv,
    const float* __restrict__ Wo1, const float* __restrict__ bo1,
    const float* __restrict__ Wo2, const float* __restrict__ bo2)
{
    const int b = blockIdx.x, p = blockIdx.y;
    __shared__ __align__(16) float sEp[Hn];
    __shared__ __align__(16) float sW3[Tn][Hn];
    __shared__ float sA2[Tn];
    const int tid = threadIdx.x;

    {
        const float4* eprow = reinterpret_cast<const float4*>(Ep + (b * KPn + p) * Hn);
        float4* sEp4w = reinterpret_cast<float4*>(sEp);
        for (int i = tid; i < Hn / 4; i += 96) sEp4w[i] = eprow[i];
        for (int i = tid; i < Tn; i += 96) sA2[i] = g_A2[(b * KPn + p) * Tn + i];
        for (int i4 = tid; i4 < Tn * Hn / 4; i4 += 96) {
            int t = i4 >> 6, h4 = i4 & 63;
            reinterpret_cast<float4*>(&sW3[t][0])[h4] =
                reinterpret_cast<const float4*>(W_in + t * Rn + 2 * Hn)[h4];
        }
    }
    __syncthreads();

    const int q0 = tid, q1 = tid + 96;
    float acc0[Tn], acc1[Tn];
    #pragma unroll
    for (int t = 0; t < Tn; t++) { acc0[t] = 0.f; acc1[t] = 0.f; }

    const float4* eq0 = reinterpret_cast<const float4*>(Eq + (b * KQn + q0) * Hn);
    const float4* eq1 = reinterpret_cast<const float4*>(Eq + (b * KQn + q1) * Hn);
    const float4* sEp4 = reinterpret_cast<const float4*>(sEp);
    for (int h4 = 0; h4 < Hn / 4; h4++) {
        float4 pp = sEp4[h4];
        float4 e0 = eq0[h4], e1 = eq1[h4];
        float4 ev0 = make_float4(e0.x * pp.x, e0.y * pp.y, e0.z * pp.z, e0.w * pp.w);
        float4 ev1 = make_float4(e1.x * pp.x, e1.y * pp.y, e1.z * pp.z, e1.w * pp.w);
        #pragma unroll
        for (int t = 0; t < Tn; t++) {
            const float4 w = *reinterpret_cast<const float4*>(&sW3[t][h4 * 4]);
            acc0[t] += ev0.x * w.x + ev0.y * w.y + ev0.z * w.z + ev0.w * w.w;
            acc1[t] += ev1.x * w.x + ev1.y * w.y + ev1.z * w.z + ev1.w * w.w;
        }
    }
    {
        const float4* a10 = reinterpret_cast<const float4*>(g_A1 + (b * KQn + q0) * Tn);
        const float4* a11 = reinterpret_cast<const float4*>(g_A1 + (b * KQn + q1) * Tn);
        #pragma unroll
        for (int t4 = 0; t4 < 8; t4++) {
            float4 a0 = a10[t4], a1v = a11[t4];
            acc0[t4 * 4 + 0] += a0.x + sA2[t4 * 4 + 0];
            acc0[t4 * 4 + 1] += a0.y + sA2[t4 * 4 + 1];
            acc0[t4 * 4 + 2] += a0.z + sA2[t4 * 4 + 2];
            acc0[t4 * 4 + 3] += a0.w + sA2[t4 * 4 + 3];
            acc1[t4 * 4 + 0] += a1v.x + sA2[t4 * 4 + 0];
            acc1[t4 * 4 + 1] += a1v.y + sA2[t4 * 4 + 1];
            acc1[t4 * 4 + 2] += a1v.z + sA2[t4 * 4 + 2];
            acc1[t4 * 4 + 3] += a1v.w + sA2[t4 * 4 + 3];
        }
    }

    // obv for both queries
    float ob0 = bo2[0], ob1 = bo2[0];
    #pragma unroll
    for (int u = 0; u < Tn; u++) {
        float s0 = bo1[u], s1 = bo1[u];
        const float4* w4 = reinterpret_cast<const float4*>(Wo1 + u * Tn);
        #pragma unroll
        for (int t4 = 0; t4 < 8; t4++) {
            float4 w = w4[t4];
            s0 += acc0[t4 * 4 + 0] * w.x + acc0[t4 * 4 + 1] * w.y
                + acc0[t4 * 4 + 2] * w.z + acc0[t4 * 4 + 3] * w.w;
            s1 += acc1[t4 * 4 + 0] * w.x + acc1[t4 * 4 + 1] * w.y
                + acc1[t4 * 4 + 2] * w.z + acc1[t4 * 4 + 3] * w.w;
        }
        const float wo = Wo2[u];
        ob0 += fmaxf(s0, 0.f) * wo;
        ob1 += fmaxf(s1, 0.f) * wo;
    }
    const float sc0 = SCALEV / (1.f + __expf(-ob0));
    const float sc1 = SCALEV / (1.f + __expf(-ob1));

    const int base = (b * KPn + p) * KQn;
    small_mm_store(acc0, Wq, bq, 1.f, g_fq + (base + q0) * Tn);
    small_mm_store(acc1, Wq, bq, 1.f, g_fq + (base + q1) * Tn);
    small_mm_store(acc0, Wk, bk, sc0, g_fk + (base + q0) * Tn);
    small_mm_store(acc1, Wk, bk, sc1, g_fk + (base + q1) * Tn);
    small_mm_store(acc0, Wv, bv, 1.f, g_fv + (base + q0) * Tn);
    small_mm_store(acc1, Wv, bv, 1.f, g_fv + (base + q1) * Tn);
}

// ---------------- K2: horizontal attention, single-pass softmax, 2 queries/thread ----------------
__global__ __launch_bounds__(96) void k2_attn_h(const float* __restrict__ mask)
{
    extern __shared__ char smem[];
    float4* sfk = reinterpret_cast<float4*>(smem);
    float4* sfv = sfk + KQn * 8;
    float* sbias = reinterpret_cast<float*>(sfv + KQn * 8);

    const int b = blockIdx.x, p = blockIdx.y;
    const int tid = threadIdx.x;
    const int base = (b * KPn + p) * KQn;

    const float4* fk4 = reinterpret_cast<const float4*>(g_fk + base * Tn);
    const float4* fv4 = reinterpret_cast<const float4*>(g_fv + base * Tn);
    for (int i = tid; i < KQn * 8; i += 96) { sfk[i] = fk4[i]; sfv[i] = fv4[i]; }
    for (int i = tid; i < KQn; i += 96) sbias[i] = (mask[base + i] < 0.5f) ? NEGV : 0.f;
    __syncthreads();

    const int q0 = tid, q1 = tid + 96;
    float4 f0[8], f1[8], a0[8], a1[8];
    {
        const float4* r0 = reinterpret_cast<const float4*>(g_fq + (base + q0) * Tn);
        const float4* r1 = reinterpret_cast<const float4*>(g_fq + (base + q1) * Tn);
        #pragma unroll
        for (int i = 0; i < 8; i++) {
            f0[i] = r0[i]; f1[i] = r1[i];
            a0[i] = make_float4(0.f, 0.f, 0.f, 0.f);
            a1[i] = make_float4(0.f, 0.f, 0.f, 0.f);
        }
    }
    float s0 = 0.f, s1 = 0.f;

    for (int k = 0; k < KQn; k++) {
        const float4* kk = &sfk[k * 8];
        float l0 = sbias[k], l1 = l0;
        #pragma unroll
        for (int i = 0; i < 8; i++) { l0 += dot4(f0[i], kk[i]); l1 += dot4(f1[i], kk[i]); }
        const float e0 = __expf(l0), e1 = __expf(l1);
        s0 += e0; s1 += e1;
        const float4* vv = &sfv[k * 8];
        #pragma unroll
        for (int i = 0; i < 8; i++) {
            float4 v = vv[i];
            a0[i].x += e0 * v.x; a0[i].y += e0 * v.y; a0[i].z += e0 * v.z; a0[i].w += e0 * v.w;
            a1[i].x += e1 * v.x; a1[i].y += e1 * v.y; a1[i].z += e1 * v.z; a1[i].w += e1 * v.w;
        }
    }
    const float i0 = 1.f / s0, i1 = 1.f / s1;
    float4* o0 = reinterpret_cast<float4*>(g_M + (base + q0) * Tn);
    float4* o1 = reinterpret_cast<float4*>(g_M + (base + q1) * Tn);
    #pragma unroll
    for (int i = 0; i < 8; i++) {
        o0[i] = make_float4(a0[i].x * i0, a0[i].y * i0, a0[i].z * i0, a0[i].w * i0);
        o1[i] = make_float4(a1[i].x * i1, a1[i].y * i1, a1[i].z * i1, a1[i].w * i1);
    }
}

// ---------------- K3: vertical attention + M-total epilogue -> g_Um ----------------
__global__ __launch_bounds__(96) void k3_attn_v(const float* __restrict__ mask,
                                                const float* __restrict__ W_out)
{
    extern __shared__ char smem[];
    float4* sfk = reinterpret_cast<float4*>(smem);
    float4* sfv = sfk + KPn * 8;
    float* sbias = reinterpret_cast<float*>(sfv + KPn * 8);
    float* sw4 = sbias + KPn;

    const int b = blockIdx.x, q = blockIdx.y;
    const int tid = threadIdx.x;

    const float4* fkg = reinterpret_cast<const float4*>(g_fk);
    const float4* fvg = reinterpret_cast<const float4*>(g_fv);
    for (int i = tid; i < KPn * 8; i += 96) {
        const int k = i >> 3, t4 = i & 7;
        const int ridx = ((b * KPn + k) * KQn + q) * 8 + t4;
        sfk[i] = fkg[ridx];
        sfv[i] = fvg[ridx];
    }
    for (int i = tid; i < KPn; i += 96)
        sbias[i] = (mask[(b * KPn + i) * KQn + q] < 0.5f) ? NEGV : 0.f;
    for (int i = tid; i < Tn; i += 96) sw4[i] = W_out[Rn + i];
    __syncthreads();

    const int p0 = tid, p1 = tid + 96;
    float4 f0[8], f1[8], a0[8], a1[8];
    {
        const float4* r0 = reinterpret_cast<const float4*>(g_fq + ((b * KPn + p0) * KQn + q) * Tn);
        const float4* r1 = reinterpret_cast<const float4*>(g_fq + ((b * KPn + p1) * KQn + q) * Tn);
        #pragma unroll
        for (int i = 0; i < 8; i++) {
            f0[i] = r0[i]; f1[i] = r1[i];
            a0[i] = make_float4(0.f, 0.f, 0.f, 0.f);
            a1[i] = make_float4(0.f, 0.f, 0.f, 0.f);
        }
    }
    float s0 = 0.f, s1 = 0.f;

    for (int k = 0; k < KPn; k++) {
        const float4* kk = &sfk[k * 8];
        float l0 = sbias[k], l1 = l0;
        #pragma unroll
        for (int i = 0; i < 8; i++) { l0 += dot4(f0[i], kk[i]); l1 += dot4(f1[i], kk[i]); }
        const float e0 = __expf(l0), e1 = __expf(l1);
        s0 += e0; s1 += e1;
        const float4* vv = &sfv[k * 8];
        #pragma unroll
        for (int i = 0; i < 8; i++) {
            float4 v = vv[i];
            a0[i].x += e0 * v.x; a0[i].y += e0 * v.y; a0[i].z += e0 * v.z; a0[i].w += e0 * v.w;
            a1[i].x += e1 * v.x; a1[i].y += e1 * v.y; a1[i].z += e1 * v.z; a1[i].w += e1 * v.w;
        }
    }
    const float i0 = 1.f / s0, i1 = 1.f / s1;
    const float4* sw44 = reinterpret_cast<const float4*>(sw4);
    {
        const float4* hor = reinterpret_cast<const float4*>(g_M + ((b * KPn + p0) * KQn + q) * Tn);
        float um = 0.f;
        #pragma unroll
        for (int i = 0; i < 8; i++) {
            float4 h = hor[i], w = sw44[i];
            um += (h.x + a0[i].x * i0) * w.x + (h.y + a0[i].y * i0) * w.y
                + (h.z + a0[i].z * i0) * w.z + (h.w + a0[i].w * i0) * w.w;
        }
        g_Um[(b * KPn + p0) * KQn + q] = um;
    }
    {
        const float4* hor = reinterpret_cast<const float4*>(g_M + ((b * KPn + p1) * KQn + q) * Tn);
        float um = 0.f;
        #pragma unroll
        for (int i = 0; i < 8; i++) {
            float4 h = hor[i], w = sw44[i];
            um += (h.x + a1[i].x * i1) * w.x + (h.y + a1[i].y * i1) * w.y
                + (h.z + a1[i].z * i1) * w.z + (h.w + a1[i].w * i1) * w.w;
        }
        g_Um[(b * KPn + p1) * KQn + q] = um;
    }
}

// ---------------- K4: U = u1 + u2 + bilinear(w3) + Um, masked ----------------
__global__ __launch_bounds__(192) void k4_U(
    const float* __restrict__ Eq, const float* __restrict__ Ep,
    const float* __restrict__ W_out, const float* __restrict__ mask)
{
    const int b = blockIdx.x, p = blockIdx.y, q = threadIdx.x;
    __shared__ __align__(16) float sEpw[Hn];
    for (int i = q; i < Hn; i += 192) sEpw[i] = Ep[(b * KPn + p) * Hn + i] * W_out[2 * Hn + i];
    __syncthreads();

    const float4* eq4 = reinterpret_cast<const float4*>(Eq + (b * KQn + q) * Hn);
    const float4* ew4 = reinterpret_cast<const float4*>(sEpw);
    float u3 = 0.f;
    for (int h4 = 0; h4 < Hn / 4; h4++) u3 += dot4(eq4[h4], ew4[h4]);

    const int idx = (b * KPn + p) * KQn + q;
    float Uv = g_u1[b * KQn + q] + g_u2[b * KPn + p] + u3 + g_Um[idx];
    if (mask[idx] < 0.5f) Uv = NEGV;
    g_U[idx] = Uv;
}

// ---------------- K5a: softmax over q -> A''_p, build G_left ----------------
__global__ __launch_bounds__(256) void k5_rowsoft(const float* __restrict__ Eq, const float* __restrict__ Ep)
{
    const int b = blockIdx.x, p = blockIdx.y;
    __shared__ float sw[KQn];
    __shared__ float red[256];
    const int tid = threadIdx.x;
    const int base = (b * KPn + p) * KQn;

    float v = (tid < KQn) ? g_U[base + tid] : -3.4e38f;
    red[tid] = v; __syncthreads();
    for (int o = 128; o; o >>= 1) { if (tid < o) red[tid] = fmaxf(red[tid], red[tid + o]); __syncthreads(); }
    const float m = red[0]; __syncthreads();
    const float e = (tid < KQn) ? __expf(v - m) : 0.f;
    red[tid] = e; __syncthreads();
    for (int o = 128; o; o >>= 1) { if (tid < o) red[tid] += red[tid + o]; __syncthreads(); }
    const float inv = 1.f / red[0];
    if (tid < KQn) sw[tid] = e * inv;
    __syncthreads();

    const int h = tid;
    float a = 0.f;
    for (int k = 0; k < KQn; k++) a += sw[k] * Eq[(b * KQn + k) * Hn + h];
    const float ep = Ep[(b * KPn + p) * Hn + h];
    float* G = g_Gl + (b * KPn + p) * Rn;
    G[h] = ep; G[Hn + h] = a; G[2 * Hn + h] = ep * a;
}

// ---------------- K5b: softmax over p -> B''_p, build G_right ----------------
__global__ __launch_bounds__(256) void k5_colsoft(const float* __restrict__ Eq, const float* __restrict__ Ep)
{
    const int b = blockIdx.x, q = blockIdx.y;
    __shared__ float sw[KPn];
    __shared__ float red[256];
    const int tid = threadIdx.x;

    float v = (tid < KPn) ? g_U[(b * KPn + tid) * KQn + q] : -3.4e38f;
    red[tid] = v; __syncthreads();
    for (int o = 128; o; o >>= 1) { if (tid < o) red[tid] = fmaxf(red[tid], red[tid + o]); __syncthreads(); }
    const float m = red[0]; __syncthreads();
    const float e = (tid < KPn) ? __expf(v - m) : 0.f;
    red[tid] = e; __syncthreads();
    for (int o = 128; o; o >>= 1) { if (tid < o) red[tid] += red[tid + o]; __syncthreads(); }
    const float inv = 1.f / red[0];
    if (tid < KPn) sw[tid] = e * inv;
    __syncthreads();

    const int h = tid;
    float a = 0.f;
    for (int k = 0; k < KPn; k++) a += sw[k] * Ep[(b * KPn + k) * Hn + h];
    const float eq = Eq[(b * KQn + q) * Hn + h];
    float* G = g_Gr + (b * KQn + q) * Rn;
    G[h] = eq; G[Hn + h] = a; G[2 * Hn + h] = eq * a;
}

// ---------------- K6: gates, 128x128 tile, 8x8 per thread ----------------
__global__ __launch_bounds__(256) void k6_gate(
    const float* __restrict__ Wl, const float* __restrict__ bl,
    const float* __restrict__ Wr, const float* __restrict__ br)
{
    const int side = blockIdx.z;
    const float* __restrict__ G = side ? g_Gr : g_Gl;
    const float* __restrict__ W = side ? Wr : Wl;
    const float* __restrict__ bias = side ? br : bl;
    float* __restrict__ outp = side ? g_right : g_left;
    const int row0 = blockIdx.y * 128;
    const int col0 = blockIdx.x * 128;
    __shared__ float sA[128][17];
    __shared__ float sB[128][17];
    const int tid = threadIdx.x;
    const int tx = tid & 15, ty = tid >> 4;
    float c[8][8] = {};

    for (int kc = 0; kc < Rn; kc += 16) {
        float4 av[2], bv[2];
        #pragma unroll
        for (int h = 0; h < 2; h++) {
            const int i = tid + h * 256;
            const int r = i >> 2, k4 = (i & 3) * 4;
            av[h] = *reinterpret_cast<const float4*>(G + (row0 + r) * Rn + kc + k4);
            bv[h] = *reinterpret_cast<const float4*>(W + (col0 + r) * Rn + kc + k4);
        }
        __syncthreads();
        #pragma unroll
        for (int h = 0; h < 2; h++) {
            const int i = tid + h * 256;
            const int r = i >> 2, k4 = (i & 3) * 4;
            sA[r][k4] = av[h].x; sA[r][k4 + 1] = av[h].y; sA[r][k4 + 2] = av[h].z; sA[r][k4 + 3] = av[h].w;
            sB[r][k4] = bv[h].x; sB[r][k4 + 1] = bv[h].y; sB[r][k4 + 2] = bv[h].z; sB[r][k4 + 3] = bv[h].w;
        }
        __syncthreads();
        #pragma unroll
        for (int kk = 0; kk < 16; kk++) {
            float a[8], bb[8];
            #pragma unroll
            for (int i = 0; i < 8; i++) a[i] = sA[ty + 16 * i][kk];
            #pragma unroll
            for (int j = 0; j < 8; j++) bb[j] = sB[tx + 16 * j][kk];
            #pragma unroll
            for (int i = 0; i < 8; i++)
                #pragma unroll
                for (int j = 0; j < 8; j++) c[i][j] += a[i] * bb[j];
        }
    }
    #pragma unroll
    for (int i = 0; i < 8; i++) {
        const int r = row0 + ty + 16 * i;
        #pragma unroll
        for (int j = 0; j < 8; j++) {
            const int cc = col0 + tx + 16 * j;
            const float g = G[r * Rn + cc];
            const float s = 1.f / (1.f + __expf(-(c[i][j] + bias[cc])));
            outp[r * Rn + cc] = s * g;
        }
    }
}

// ---------------- K7: split-K partials of left @ right^T ----------------
__global__ __launch_bounds__(256) void k7_partial()
{
    const int z = blockIdx.z;
    const int b = z >> 2, ks = z & 3;
    const int kbase = ks * 192;
    const float* __restrict__ A = g_left + b * KPn * Rn;
    const float* __restrict__ Bm = g_right + b * KQn * Rn;
    const int row0 = blockIdx.y * 64;
    const int col0 = blockIdx.x * 64;
    __shared__ float sA[64][17];
    __shared__ float sB[64][17];
    const int tid = threadIdx.x;
    const int tx = tid & 15, ty = tid >> 4;
    float c[4][4] = {};

    for (int kc = kbase; kc < kbase + 192; kc += 16) {
        const int r = tid >> 2, k4 = (tid & 3) * 4;
        float4 av = *reinterpret_cast<const float4*>(A + (row0 + r) * Rn + kc + k4);
        float4 bv = *reinterpret_cast<const float4*>(Bm + (col0 + r) * Rn + kc + k4);
        __syncthreads();
        sA[r][k4] = av.x; sA[r][k4 + 1] = av.y; sA[r][k4 + 2] = av.z; sA[r][k4 + 3] = av.w;
        sB[r][k4] = bv.x; sB[r][k4 + 1] = bv.y; sB[r][k4 + 2] = bv.z; sB[r][k4 + 3] = bv.w;
        __syncthreads();
        #pragma unroll
        for (int kk = 0; kk < 16; kk++) {
            float a[4], bb[4];
            #pragma unroll
            for (int i = 0; i < 4; i++) a[i] = sA[ty + 16 * i][kk];
            #pragma unroll
            for (int j = 0; j < 4; j++) bb[j] = sB[tx + 16 * j][kk];
            #pragma unroll
            for (int i = 0; i < 4; i++)
                #pragma unroll
                for (int j = 0; j < 4; j++) c[i][j] += a[i] * bb[j];
        }
    }
    float* dst = g_part + ks * (BB * KPn * KQn) + b * (KPn * KQn);
    #pragma unroll
    for (int i = 0; i < 4; i++) {
        const int r = row0 + ty + 16 * i;
        #pragma unroll
        for (int j = 0; j < 4; j++) {
            const int cc = col0 + tx + 16 * j;
            dst[r * KQn + cc] = c[i][j];
        }
    }
}

// ---------------- K8: reduce split-K + relu ----------------
__global__ __launch_bounds__(256) void k8_reduce(float* __restrict__ outp)
{
    const int idx = blockIdx.x * 256 + threadIdx.x;
    const int n = BB * KPn * KQn;
    if (idx < n) {
        float s = g_part[idx] + g_part[n + idx] + g_part[2 * n + idx] + g_part[3 * n + idx];
        outp[idx] = fmaxf(s, 0.f);
    }
}

// ---------------- launch ----------------
extern "C" void kernel_launch(void* const* d_in, const int* in_sizes, int n_in,
                              void* d_out, int out_size)
{
    const float* Eq    = (const float*)d_in[0];
    const float* Ep    = (const float*)d_in[1];
    const float* mask  = (const float*)d_in[2];
    const float* W_in  = (const float*)d_in[3];
    const float* Wq    = (const float*)d_in[4];
    const float* bq    = (const float*)d_in[5];
    const float* Wk    = (const float*)d_in[6];
    const float* bk    = (const float*)d_in[7];
    const float* Wv    = (const float*)d_in[8];
    const float* bv    = (const float*)d_in[9];
    const float* Wo1   = (const float*)d_in[10];
    const float* bo1   = (const float*)d_in[11];
    const float* Wo2   = (const float*)d_in[12];
    const float* bo2   = (const float*)d_in[13];
    const float* W_out = (const float*)d_in[14];
    const float* Wl    = (const float*)d_in[15];
    const float* bl    = (const float*)d_in[16];
    const float* Wr    = (const float*)d_in[17];
    const float* br    = (const float*)d_in[18];
    float* outp = (float*)d_out;

    const int smem2 = (KQn * 8 * 16) * 2 + KQn * 4;             // 49920
    const int smem3 = (KPn * 8 * 16) * 2 + KPn * 4 + Tn * 4;    // 50048
    cudaFuncSetAttribute(k2_attn_h, cudaFuncAttributeMaxDynamicSharedMemorySize, smem2);
    cudaFuncSetAttribute(k3_attn_v, cudaFuncAttributeMaxDynamicSharedMemorySize, smem3);

    k0_rowproj<<<dim3(BB, 2), dim3(32, 8)>>>(Eq, Ep, W_in, W_out);
    k1_pair<<<dim3(BB, KPn), 96>>>(Eq, Ep, W_in, Wq, bq, Wk, bk, Wv, bv, Wo1, bo1, Wo2, bo2);
    k2_attn_h<<<dim3(BB, KPn), 96, smem2>>>(mask);
    k3_attn_v<<<dim3(BB, KQn), 96, smem3>>>(mask, W_out);
    k4_U<<<dim3(BB, KPn), 192>>>(Eq, Ep, W_out, mask);
    k5_rowsoft<<<dim3(BB, KPn), 256>>>(Eq, Ep);
    k5_colsoft<<<dim3(BB, KQn), 256>>>(Eq, Ep);
    k6_gate<<<dim3(6, 6, 2), 256>>>(Wl, bl, Wr, br);
    k7_partial<<<dim3(3, 3, 16), 256>>>();
    k8_reduce<<<dim3(576), 256>>>(outp);
}

// round 3
// speedup vs baseline: 1.5789x; 1.5789x over previous
#include <cuda_runtime.h>
#include <math.h>

#define BB 4
#define KQn 192
#define KPn 192
#define Hn 256
#define Tn 32
#define Rn 768
#define NEGV (-1e9f)
#define SCALEV (0.17677669529663687f)   // 1/sqrt(32)

// ---------------- scratch (static device globals; no runtime allocation) ----------------
static __device__ float g_A1[BB * KQn * Tn];
static __device__ float g_A2[BB * KPn * Tn];
static __device__ float g_u1[BB * KQn];
static __device__ float g_u2[BB * KPn];
static __device__ float g_fq[BB * KPn * KQn * Tn];
static __device__ float g_fk[BB * KPn * KQn * Tn]; // pre-scaled by obv*SCALE
static __device__ float g_fv[BB * KPn * KQn * Tn];
static __device__ float g_M[BB * KPn * KQn * Tn];  // horizontal contribution only
static __device__ float g_Um[BB * KPn * KQn];      // M_total . w4
static __device__ float g_U[BB * KPn * KQn];
static __device__ float g_Gl[BB * KPn * Rn];
static __device__ float g_Gr[BB * KQn * Rn];
static __device__ float g_left[BB * KPn * Rn];
static __device__ float g_right[BB * KQn * Rn];
static __device__ float g_part[4 * BB * KPn * KQn];

__device__ __forceinline__ float dot4(float4 a, float4 b) {
    return a.x * b.x + a.y * b.y + a.z * b.z + a.w * b.w;
}

// ---------------- K0: per-row projections A1/A2 and u1/u2 ----------------
__global__ __launch_bounds__(256) void k0_rowproj(
    const float* __restrict__ Eq, const float* __restrict__ Ep,
    const float* __restrict__ W_in, const float* __restrict__ W_out)
{
    const int b = blockIdx.x;
    const int side = blockIdx.y;
    const float* src = side ? (Ep + b * KPn * Hn) : (Eq + b * KQn * Hn);
    const int woff = side ? Hn : 0;
    float* A = side ? (g_A2 + b * KPn * Tn) : (g_A1 + b * KQn * Tn);
    float* u = side ? (g_u2 + b * KPn) : (g_u1 + b * KQn);

    __shared__ float sW[Tn][Hn + 1];
    __shared__ float swv[Hn];
    const int tid = threadIdx.y * 32 + threadIdx.x;
    for (int i = tid; i < Tn * Hn; i += 256) {
        int t = i >> 8, h = i & 255;
        sW[t][h] = W_in[t * Rn + woff + h];
    }
    for (int i = tid; i < Hn; i += 256) swv[i] = W_out[woff + i];
    __syncthreads();

    const int t = threadIdx.x;
    for (int y = threadIdx.y; y < 192; y += 8) {
        const float* row = src + y * Hn;
        float acc = 0.f, up = 0.f;
        for (int h = 0; h < Hn; h++) acc += row[h] * sW[t][h];
        for (int h = t; h < Hn; h += 32) up += row[h] * swv[h];
        #pragma unroll
        for (int o = 16; o; o >>= 1) up += __shfl_down_sync(0xffffffffu, up, o);
        A[y * Tn + t] = acc;
        if (t == 0) u[y] = up;
    }
}

// dst = (e1 @ W^T + bias) * scale
__device__ __forceinline__ void small_mm_store(const float* e1, const float* __restrict__ W,
                                               const float* __restrict__ bias, float scale,
                                               float* __restrict__ dst)
{
    float4* d = reinterpret_cast<float4*>(dst);
    #pragma unroll
    for (int u4 = 0; u4 < 8; u4++) {
        float r[4];
        #pragma unroll
        for (int uu = 0; uu < 4; uu++) {
            const int u = u4 * 4 + uu;
            float s = bias[u];
            const float4* w4 = reinterpret_cast<const float4*>(W + u * Tn);
            #pragma unroll
            for (int t4 = 0; t4 < 8; t4++) {
                float4 w = w4[t4];
                s += e1[t4 * 4 + 0] * w.x + e1[t4 * 4 + 1] * w.y
                   + e1[t4 * 4 + 2] * w.z + e1[t4 * 4 + 3] * w.w;
            }
            r[uu] = s * scale;
        }
        d[u4] = make_float4(r[0], r[1], r[2], r[3]);
    }
}

// ---------------- K1: per (b,p): bilinear E1 + fq/fk(scaled)/fv fused; 1 query/thread ----------------
__global__ __launch_bounds__(192) void k1_pair(
    const float* __restrict__ Eq, const float* __restrict__ Ep,
    const float* __restrict__ W_in,
    const float* __restrict__ Wq, const float* __restrict__ bq,
    const float* __restrict__ Wk, const float* __restrict__ bk,
    const float* __restrict__ Wv, const float* __restrict__ bv,
    const float* __restrict__ Wo1, const float* __restrict__ bo1,
    const float* __restrict__ Wo2, const float* __restrict__ bo2)
{
    const int b = blockIdx.x, p = blockIdx.y;
    __shared__ __align__(16) float sEp[Hn];
    __shared__ __align__(16) float sW3[Tn][Hn];
    __shared__ float sA2[Tn];
    const int tid = threadIdx.x;

    {
        const float4* eprow = reinterpret_cast<const float4*>(Ep + (b * KPn + p) * Hn);
        float4* sEp4w = reinterpret_cast<float4*>(sEp);
        for (int i = tid; i < Hn / 4; i += 192) sEp4w[i] = eprow[i];
        for (int i = tid; i < Tn; i += 192) sA2[i] = g_A2[(b * KPn + p) * Tn + i];
        for (int i4 = tid; i4 < Tn * Hn / 4; i4 += 192) {
            int t = i4 >> 6, h4 = i4 & 63;
            reinterpret_cast<float4*>(&sW3[t][0])[h4] =
                reinterpret_cast<const float4*>(W_in + t * Rn + 2 * Hn)[h4];
        }
    }
    __syncthreads();

    const int q = tid;
    float acc[Tn];
    #pragma unroll
    for (int t = 0; t < Tn; t++) acc[t] = 0.f;

    const float4* eq4 = reinterpret_cast<const float4*>(Eq + (b * KQn + q) * Hn);
    const float4* sEp4 = reinterpret_cast<const float4*>(sEp);
    for (int h4 = 0; h4 < Hn / 4; h4++) {
        float4 e = eq4[h4];
        float4 pp = sEp4[h4];
        float4 ev = make_float4(e.x * pp.x, e.y * pp.y, e.z * pp.z, e.w * pp.w);
        #pragma unroll
        for (int t = 0; t < Tn; t++) {
            const float4 w = *reinterpret_cast<const float4*>(&sW3[t][h4 * 4]);
            acc[t] += ev.x * w.x + ev.y * w.y + ev.z * w.z + ev.w * w.w;
        }
    }
    {
        const float4* a1 = reinterpret_cast<const float4*>(g_A1 + (b * KQn + q) * Tn);
        #pragma unroll
        for (int t4 = 0; t4 < 8; t4++) {
            float4 a = a1[t4];
            acc[t4 * 4 + 0] += a.x + sA2[t4 * 4 + 0];
            acc[t4 * 4 + 1] += a.y + sA2[t4 * 4 + 1];
            acc[t4 * 4 + 2] += a.z + sA2[t4 * 4 + 2];
            acc[t4 * 4 + 3] += a.w + sA2[t4 * 4 + 3];
        }
    }

    // obv = sigmoid( relu(E1@Wo1^T+bo1) . Wo2 + bo2 ), folded into fk scale
    float ob = bo2[0];
    #pragma unroll
    for (int u = 0; u < Tn; u++) {
        float s = bo1[u];
        const float4* w4 = reinterpret_cast<const float4*>(Wo1 + u * Tn);
        #pragma unroll
        for (int t4 = 0; t4 < 8; t4++) {
            float4 w = w4[t4];
            s += acc[t4 * 4 + 0] * w.x + acc[t4 * 4 + 1] * w.y
               + acc[t4 * 4 + 2] * w.z + acc[t4 * 4 + 3] * w.w;
        }
        ob += fmaxf(s, 0.f) * Wo2[u];
    }
    const float sc = SCALEV / (1.f + __expf(-ob));

    const int pairbase = (b * KPn + p) * KQn + q;
    small_mm_store(acc, Wq, bq, 1.f, g_fq + pairbase * Tn);
    small_mm_store(acc, Wk, bk, sc,  g_fk + pairbase * Tn);
    small_mm_store(acc, Wv, bv, 1.f, g_fv + pairbase * Tn);
}

// ---------------- K2: horizontal attention, single-pass softmax, 2 queries/thread ----------------
__global__ __launch_bounds__(96) void k2_attn_h(const float* __restrict__ mask)
{
    extern __shared__ char smem[];
    float4* sfk = reinterpret_cast<float4*>(smem);
    float4* sfv = sfk + KQn * 8;
    float* sbias = reinterpret_cast<float*>(sfv + KQn * 8);

    const int b = blockIdx.x, p = blockIdx.y;
    const int tid = threadIdx.x;
    const int base = (b * KPn + p) * KQn;

    const float4* fk4 = reinterpret_cast<const float4*>(g_fk + base * Tn);
    const float4* fv4 = reinterpret_cast<const float4*>(g_fv + base * Tn);
    for (int i = tid; i < KQn * 8; i += 96) { sfk[i] = fk4[i]; sfv[i] = fv4[i]; }
    for (int i = tid; i < KQn; i += 96) sbias[i] = (mask[base + i] < 0.5f) ? NEGV : 0.f;
    __syncthreads();

    const int q0 = tid, q1 = tid + 96;
    float4 f0[8], f1[8], a0[8], a1[8];
    {
        const float4* r0 = reinterpret_cast<const float4*>(g_fq + (base + q0) * Tn);
        const float4* r1 = reinterpret_cast<const float4*>(g_fq + (base + q1) * Tn);
        #pragma unroll
        for (int i = 0; i < 8; i++) {
            f0[i] = r0[i]; f1[i] = r1[i];
            a0[i] = make_float4(0.f, 0.f, 0.f, 0.f);
            a1[i] = make_float4(0.f, 0.f, 0.f, 0.f);
        }
    }
    float s0 = 0.f, s1 = 0.f;

    for (int k = 0; k < KQn; k++) {
        const float4* kk = &sfk[k * 8];
        float l0 = sbias[k], l1 = l0;
        #pragma unroll
        for (int i = 0; i < 8; i++) { l0 += dot4(f0[i], kk[i]); l1 += dot4(f1[i], kk[i]); }
        const float e0 = __expf(l0), e1 = __expf(l1);
        s0 += e0; s1 += e1;
        const float4* vv = &sfv[k * 8];
        #pragma unroll
        for (int i = 0; i < 8; i++) {
            float4 v = vv[i];
            a0[i].x += e0 * v.x; a0[i].y += e0 * v.y; a0[i].z += e0 * v.z; a0[i].w += e0 * v.w;
            a1[i].x += e1 * v.x; a1[i].y += e1 * v.y; a1[i].z += e1 * v.z; a1[i].w += e1 * v.w;
        }
    }
    const float i0 = 1.f / s0, i1 = 1.f / s1;
    float4* o0 = reinterpret_cast<float4*>(g_M + (base + q0) * Tn);
    float4* o1 = reinterpret_cast<float4*>(g_M + (base + q1) * Tn);
    #pragma unroll
    for (int i = 0; i < 8; i++) {
        o0[i] = make_float4(a0[i].x * i0, a0[i].y * i0, a0[i].z * i0, a0[i].w * i0);
        o1[i] = make_float4(a1[i].x * i1, a1[i].y * i1, a1[i].z * i1, a1[i].w * i1);
    }
}

// ---------------- K3: vertical attention + M-total epilogue -> g_Um ----------------
__global__ __launch_bounds__(96) void k3_attn_v(const float* __restrict__ mask,
                                                const float* __restrict__ W_out)
{
    extern __shared__ char smem[];
    float4* sfk = reinterpret_cast<float4*>(smem);
    float4* sfv = sfk + KPn * 8;
    float* sbias = reinterpret_cast<float*>(sfv + KPn * 8);
    float* sw4 = sbias + KPn;

    const int b = blockIdx.x, q = blockIdx.y;
    const int tid = threadIdx.x;

    const float4* fkg = reinterpret_cast<const float4*>(g_fk);
    const float4* fvg = reinterpret_cast<const float4*>(g_fv);
    for (int i = tid; i < KPn * 8; i += 96) {
        const int k = i >> 3, t4 = i & 7;
        const int ridx = ((b * KPn + k) * KQn + q) * 8 + t4;
        sfk[i] = fkg[ridx];
        sfv[i] = fvg[ridx];
    }
    for (int i = tid; i < KPn; i += 96)
        sbias[i] = (mask[(b * KPn + i) * KQn + q] < 0.5f) ? NEGV : 0.f;
    for (int i = tid; i < Tn; i += 96) sw4[i] = W_out[Rn + i];
    __syncthreads();

    const int p0 = tid, p1 = tid + 96;
    float4 f0[8], f1[8], a0[8], a1[8];
    {
        const float4* r0 = reinterpret_cast<const float4*>(g_fq + ((b * KPn + p0) * KQn + q) * Tn);
        const float4* r1 = reinterpret_cast<const float4*>(g_fq + ((b * KPn + p1) * KQn + q) * Tn);
        #pragma unroll
        for (int i = 0; i < 8; i++) {
            f0[i] = r0[i]; f1[i] = r1[i];
            a0[i] = make_float4(0.f, 0.f, 0.f, 0.f);
            a1[i] = make_float4(0.f, 0.f, 0.f, 0.f);
        }
    }
    float s0 = 0.f, s1 = 0.f;

    for (int k = 0; k < KPn; k++) {
        const float4* kk = &sfk[k * 8];
        float l0 = sbias[k], l1 = l0;
        #pragma unroll
        for (int i = 0; i < 8; i++) { l0 += dot4(f0[i], kk[i]); l1 += dot4(f1[i], kk[i]); }
        const float e0 = __expf(l0), e1 = __expf(l1);
        s0 += e0; s1 += e1;
        const float4* vv = &sfv[k * 8];
        #pragma unroll
        for (int i = 0; i < 8; i++) {
            float4 v = vv[i];
            a0[i].x += e0 * v.x; a0[i].y += e0 * v.y; a0[i].z += e0 * v.z; a0[i].w += e0 * v.w;
            a1[i].x += e1 * v.x; a1[i].y += e1 * v.y; a1[i].z += e1 * v.z; a1[i].w += e1 * v.w;
        }
    }
    const float i0 = 1.f / s0, i1 = 1.f / s1;
    const float4* sw44 = reinterpret_cast<const float4*>(sw4);
    {
        const float4* hor = reinterpret_cast<const float4*>(g_M + ((b * KPn + p0) * KQn + q) * Tn);
        float um = 0.f;
        #pragma unroll
        for (int i = 0; i < 8; i++) {
            float4 h = hor[i], w = sw44[i];
            um += (h.x + a0[i].x * i0) * w.x + (h.y + a0[i].y * i0) * w.y
                + (h.z + a0[i].z * i0) * w.z + (h.w + a0[i].w * i0) * w.w;
        }
        g_Um[(b * KPn + p0) * KQn + q] = um;
    }
    {
        const float4* hor = reinterpret_cast<const float4*>(g_M + ((b * KPn + p1) * KQn + q) * Tn);
        float um = 0.f;
        #pragma unroll
        for (int i = 0; i < 8; i++) {
            float4 h = hor[i], w = sw44[i];
            um += (h.x + a1[i].x * i1) * w.x + (h.y + a1[i].y * i1) * w.y
                + (h.z + a1[i].z * i1) * w.z + (h.w + a1[i].w * i1) * w.w;
        }
        g_Um[(b * KPn + p1) * KQn + q] = um;
    }
}

// ---------------- K4: U = u1 + u2 + bilinear(w3) + Um, masked ----------------
__global__ __launch_bounds__(192) void k4_U(
    const float* __restrict__ Eq, const float* __restrict__ Ep,
    const float* __restrict__ W_out, const float* __restrict__ mask)
{
    const int b = blockIdx.x, p = blockIdx.y, q = threadIdx.x;
    __shared__ __align__(16) float sEpw[Hn];
    for (int i = q; i < Hn; i += 192) sEpw[i] = Ep[(b * KPn + p) * Hn + i] * W_out[2 * Hn + i];
    __syncthreads();

    const float4* eq4 = reinterpret_cast<const float4*>(Eq + (b * KQn + q) * Hn);
    const float4* ew4 = reinterpret_cast<const float4*>(sEpw);
    float u3 = 0.f;
    for (int h4 = 0; h4 < Hn / 4; h4++) u3 += dot4(eq4[h4], ew4[h4]);

    const int idx = (b * KPn + p) * KQn + q;
    float Uv = g_u1[b * KQn + q] + g_u2[b * KPn + p] + u3 + g_Um[idx];
    if (mask[idx] < 0.5f) Uv = NEGV;
    g_U[idx] = Uv;
}

// ---------------- K5a: softmax over q -> A''_p, build G_left ----------------
__global__ __launch_bounds__(256) void k5_rowsoft(const float* __restrict__ Eq, const float* __restrict__ Ep)
{
    const int b = blockIdx.x, p = blockIdx.y;
    __shared__ float sw[KQn];
    __shared__ float red[256];
    const int tid = threadIdx.x;
    const int base = (b * KPn + p) * KQn;

    float v = (tid < KQn) ? g_U[base + tid] : -3.4e38f;
    red[tid] = v; __syncthreads();
    for (int o = 128; o; o >>= 1) { if (tid < o) red[tid] = fmaxf(red[tid], red[tid + o]); __syncthreads(); }
    const float m = red[0]; __syncthreads();
    const float e = (tid < KQn) ? __expf(v - m) : 0.f;
    red[tid] = e; __syncthreads();
    for (int o = 128; o; o >>= 1) { if (tid < o) red[tid] += red[tid + o]; __syncthreads(); }
    const float inv = 1.f / red[0];
    if (tid < KQn) sw[tid] = e * inv;
    __syncthreads();

    const int h = tid;
    float a = 0.f;
    for (int k = 0; k < KQn; k++) a += sw[k] * Eq[(b * KQn + k) * Hn + h];
    const float ep = Ep[(b * KPn + p) * Hn + h];
    float* G = g_Gl + (b * KPn + p) * Rn;
    G[h] = ep; G[Hn + h] = a; G[2 * Hn + h] = ep * a;
}

// ---------------- K5b: softmax over p -> B''_p, build G_right ----------------
__global__ __launch_bounds__(256) void k5_colsoft(const float* __restrict__ Eq, const float* __restrict__ Ep)
{
    const int b = blockIdx.x, q = blockIdx.y;
    __shared__ float sw[KPn];
    __shared__ float red[256];
    const int tid = threadIdx.x;

    float v = (tid < KPn) ? g_U[(b * KPn + tid) * KQn + q] : -3.4e38f;
    red[tid] = v; __syncthreads();
    for (int o = 128; o; o >>= 1) { if (tid < o) red[tid] = fmaxf(red[tid], red[tid + o]); __syncthreads(); }
    const float m = red[0]; __syncthreads();
    const float e = (tid < KPn) ? __expf(v - m) : 0.f;
    red[tid] = e; __syncthreads();
    for (int o = 128; o; o >>= 1) { if (tid < o) red[tid] += red[tid + o]; __syncthreads(); }
    const float inv = 1.f / red[0];
    if (tid < KPn) sw[tid] = e * inv;
    __syncthreads();

    const int h = tid;
    float a = 0.f;
    for (int k = 0; k < KPn; k++) a += sw[k] * Ep[(b * KPn + k) * Hn + h];
    const float eq = Eq[(b * KQn + q) * Hn + h];
    float* G = g_Gr + (b * KQn + q) * Rn;
    G[h] = eq; G[Hn + h] = a; G[2 * Hn + h] = eq * a;
}

// ---------------- K6: gates, 128x64 tile, 8x4 per thread (144 blocks = 1 full wave) ----------------
__global__ __launch_bounds__(256) void k6_gate(
    const float* __restrict__ Wl, const float* __restrict__ bl,
    const float* __restrict__ Wr, const float* __restrict__ br)
{
    const int side = blockIdx.z;
    const float* __restrict__ G = side ? g_Gr : g_Gl;
    const float* __restrict__ W = side ? Wr : Wl;
    const float* __restrict__ bias = side ? br : bl;
    float* __restrict__ outp = side ? g_right : g_left;
    const int row0 = blockIdx.y * 128;
    const int col0 = blockIdx.x * 64;
    __shared__ float sA[128][17];
    __shared__ float sB[64][17];
    const int tid = threadIdx.x;
    const int tx = tid & 15, ty = tid >> 4;
    float c[8][4] = {};

    const int ra = tid >> 1, ka = (tid & 1) * 8;   // 2 float4 per thread into sA
    const int rb = tid >> 2, kb = (tid & 3) * 4;   // 1 float4 per thread into sB

    for (int kc = 0; kc < Rn; kc += 16) {
        float4 av0 = *reinterpret_cast<const float4*>(G + (row0 + ra) * Rn + kc + ka);
        float4 av1 = *reinterpret_cast<const float4*>(G + (row0 + ra) * Rn + kc + ka + 4);
        float4 bv = *reinterpret_cast<const float4*>(W + (col0 + rb) * Rn + kc + kb);
        __syncthreads();
        sA[ra][ka] = av0.x; sA[ra][ka + 1] = av0.y; sA[ra][ka + 2] = av0.z; sA[ra][ka + 3] = av0.w;
        sA[ra][ka + 4] = av1.x; sA[ra][ka + 5] = av1.y; sA[ra][ka + 6] = av1.z; sA[ra][ka + 7] = av1.w;
        sB[rb][kb] = bv.x; sB[rb][kb + 1] = bv.y; sB[rb][kb + 2] = bv.z; sB[rb][kb + 3] = bv.w;
        __syncthreads();
        #pragma unroll
        for (int kk = 0; kk < 16; kk++) {
            float a[8], bb[4];
            #pragma unroll
            for (int i = 0; i < 8; i++) a[i] = sA[ty + 16 * i][kk];
            #pragma unroll
            for (int j = 0; j < 4; j++) bb[j] = sB[tx + 16 * j][kk];
            #pragma unroll
            for (int i = 0; i < 8; i++)
                #pragma unroll
                for (int j = 0; j < 4; j++) c[i][j] += a[i] * bb[j];
        }
    }
    #pragma unroll
    for (int i = 0; i < 8; i++) {
        const int r = row0 + ty + 16 * i;
        #pragma unroll
        for (int j = 0; j < 4; j++) {
            const int cc = col0 + tx + 16 * j;
            const float g = G[r * Rn + cc];
            const float s = 1.f / (1.f + __expf(-(c[i][j] + bias[cc])));
            outp[r * Rn + cc] = s * g;
        }
    }
}

// ---------------- K7: split-K partials of left @ right^T ----------------
__global__ __launch_bounds__(256) void k7_partial()
{
    const int z = blockIdx.z;
    const int b = z >> 2, ks = z & 3;
    const int kbase = ks * 192;
    const float* __restrict__ A = g_left + b * KPn * Rn;
    const float* __restrict__ Bm = g_right + b * KQn * Rn;
    const int row0 = blockIdx.y * 64;
    const int col0 = blockIdx.x * 64;
    __shared__ float sA[64][17];
    __shared__ float sB[64][17];
    const int tid = threadIdx.x;
    const int tx = tid & 15, ty = tid >> 4;
    float c[4][4] = {};

    for (int kc = kbase; kc < kbase + 192; kc += 16) {
        const int r = tid >> 2, k4 = (tid & 3) * 4;
        float4 av = *reinterpret_cast<const float4*>(A + (row0 + r) * Rn + kc + k4);
        float4 bv = *reinterpret_cast<const float4*>(Bm + (col0 + r) * Rn + kc + k4);
        __syncthreads();
        sA[r][k4] = av.x; sA[r][k4 + 1] = av.y; sA[r][k4 + 2] = av.z; sA[r][k4 + 3] = av.w;
        sB[r][k4] = bv.x; sB[r][k4 + 1] = bv.y; sB[r][k4 + 2] = bv.z; sB[r][k4 + 3] = bv.w;
        __syncthreads();
        #pragma unroll
        for (int kk = 0; kk < 16; kk++) {
            float a[4], bb[4];
            #pragma unroll
            for (int i = 0; i < 4; i++) a[i] = sA[ty + 16 * i][kk];
            #pragma unroll
            for (int j = 0; j < 4; j++) bb[j] = sB[tx + 16 * j][kk];
            #pragma unroll
            for (int i = 0; i < 4; i++)
                #pragma unroll
                for (int j = 0; j < 4; j++) c[i][j] += a[i] * bb[j];
        }
    }
    float* dst = g_part + ks * (BB * KPn * KQn) + b * (KPn * KQn);
    #pragma unroll
    for (int i = 0; i < 4; i++) {
        const int r = row0 + ty + 16 * i;
        #pragma unroll
        for (int j = 0; j < 4; j++) {
            const int cc = col0 + tx + 16 * j;
            dst[r * KQn + cc] = c[i][j];
        }
    }
}

// ---------------- K8: reduce split-K + relu ----------------
__global__ __launch_bounds__(256) void k8_reduce(float* __restrict__ outp)
{
    const int idx = blockIdx.x * 256 + threadIdx.x;
    const int n = BB * KPn * KQn;
    if (idx < n) {
        float s = g_part[idx] + g_part[n + idx] + g_part[2 * n + idx] + g_part[3 * n + idx];
        outp[idx] = fmaxf(s, 0.f);
    }
}

// ---------------- launch ----------------
extern "C" void kernel_launch(void* const* d_in, const int* in_sizes, int n_in,
                              void* d_out, int out_size)
{
    const float* Eq    = (const float*)d_in[0];
    const float* Ep    = (const float*)d_in[1];
    const float* mask  = (const float*)d_in[2];
    const float* W_in  = (const float*)d_in[3];
    const float* Wq    = (const float*)d_in[4];
    const float* bq    = (const float*)d_in[5];
    const float* Wk    = (const float*)d_in[6];
    const float* bk    = (const float*)d_in[7];
    const float* Wv    = (const float*)d_in[8];
    const float* bv    = (const float*)d_in[9];
    const float* Wo1   = (const float*)d_in[10];
    const float* bo1   = (const float*)d_in[11];
    const float* Wo2   = (const float*)d_in[12];
    const float* bo2   = (const float*)d_in[13];
    const float* W_out = (const float*)d_in[14];
    const float* Wl    = (const float*)d_in[15];
    const float* bl    = (const float*)d_in[16];
    const float* Wr    = (const float*)d_in[17];
    const float* br    = (const float*)d_in[18];
    float* outp = (float*)d_out;

    const int smem2 = (KQn * 8 * 16) * 2 + KQn * 4;             // 49920
    const int smem3 = (KPn * 8 * 16) * 2 + KPn * 4 + Tn * 4;    // 50048
    cudaFuncSetAttribute(k2_attn_h, cudaFuncAttributeMaxDynamicSharedMemorySize, smem2);
    cudaFuncSetAttribute(k3_attn_v, cudaFuncAttributeMaxDynamicSharedMemorySize, smem3);

    k0_rowproj<<<dim3(BB, 2), dim3(32, 8)>>>(Eq, Ep, W_in, W_out);
    k1_pair<<<dim3(BB, KPn), 192>>>(Eq, Ep, W_in, Wq, bq, Wk, bk, Wv, bv, Wo1, bo1, Wo2, bo2);
    k2_attn_h<<<dim3(BB, KPn), 96, smem2>>>(mask);
    k3_attn_v<<<dim3(BB, KQn), 96, smem3>>>(mask, W_out);
    k4_U<<<dim3(BB, KPn), 192>>>(Eq, Ep, W_out, mask);
    k5_rowsoft<<<dim3(BB, KPn), 256>>>(Eq, Ep);
    k5_colsoft<<<dim3(BB, KQn), 256>>>(Eq, Ep);
    k6_gate<<<dim3(12, 6, 2), 256>>>(Wl, bl, Wr, br);
    k7_partial<<<dim3(3, 3, 16), 256>>>();
    k8_reduce<<<dim3(576), 256>>>(outp);
}

// round 5
// speedup vs baseline: 1.6598x; 1.0512x over previous
#include <cuda_runtime.h>
#include <math.h>

#define BB 4
#define KQn 192
#define KPn 192
#define Hn 256
#define Tn 32
#define Rn 768
#define NEGV (-1e9f)
#define SCALEV (0.17677669529663687f)   // 1/sqrt(32)

// ---------------- scratch ----------------
static __device__ float g_A1[BB * KQn * Tn];
static __device__ float g_A2[BB * KPn * Tn];
static __device__ float g_u1[BB * KQn];
static __device__ float g_u2[BB * KPn];
static __device__ float g_fq[BB * KPn * KQn * Tn];
static __device__ float g_fk[BB * KPn * KQn * Tn]; // pre-scaled by obv*SCALE
static __device__ float g_fv[BB * KPn * KQn * Tn];
static __device__ float g_Umh[BB * KPn * KQn];     // horizontal M . w4
static __device__ float g_Um[BB * KPn * KQn];      // total M . w4
static __device__ float g_U[BB * KPn * KQn];
static __device__ float g_Gl[BB * KPn * Rn];
static __device__ float g_Gr[BB * KQn * Rn];
static __device__ float g_left[BB * KPn * Rn];
static __device__ float g_right[BB * KQn * Rn];
static __device__ float g_part[4 * BB * KPn * KQn];

__device__ __forceinline__ float dot4(float4 a, float4 b) {
    return (a.x * b.x + a.y * b.y) + (a.z * b.z + a.w * b.w);   // depth-3 tree
}

// ---------------- K0: per-row projections A1/A2 and u1/u2 ----------------
__global__ __launch_bounds__(256) void k0_rowproj(
    const float* __restrict__ Eq, const float* __restrict__ Ep,
    const float* __restrict__ W_in, const float* __restrict__ W_out)
{
    const int b = blockIdx.x;
    const int side = blockIdx.y;
    const float* src = side ? (Ep + b * KPn * Hn) : (Eq + b * KQn * Hn);
    const int woff = side ? Hn : 0;
    float* A = side ? (g_A2 + b * KPn * Tn) : (g_A1 + b * KQn * Tn);
    float* u = side ? (g_u2 + b * KPn) : (g_u1 + b * KQn);

    __shared__ float sW[Tn][Hn + 1];
    __shared__ float swv[Hn];
    const int tid = threadIdx.y * 32 + threadIdx.x;
    for (int i = tid; i < Tn * Hn; i += 256) {
        int t = i >> 8, h = i & 255;
        sW[t][h] = W_in[t * Rn + woff + h];
    }
    for (int i = tid; i < Hn; i += 256) swv[i] = W_out[woff + i];
    __syncthreads();

    const int t = threadIdx.x;
    const int y0 = blockIdx.z * 48;
    for (int y = y0 + threadIdx.y; y < y0 + 48; y += 8) {
        const float* row = src + y * Hn;
        float p0 = 0.f, p1 = 0.f, p2 = 0.f, p3 = 0.f, up = 0.f;
        for (int h = 0; h < Hn; h += 4) {
            p0 += row[h] * sW[t][h];
            p1 += row[h + 1] * sW[t][h + 1];
            p2 += row[h + 2] * sW[t][h + 2];
            p3 += row[h + 3] * sW[t][h + 3];
        }
        for (int h = t; h < Hn; h += 32) up += row[h] * swv[h];
        #pragma unroll
        for (int o = 16; o; o >>= 1) up += __shfl_down_sync(0xffffffffu, up, o);
        A[y * Tn + t] = (p0 + p1) + (p2 + p3);
        if (t == 0) u[y] = up;
    }
}

// dst = (e1 @ W^T + bias) * scale, 2-way split accumulation
__device__ __forceinline__ void small_mm_store(const float* e1, const float* __restrict__ W,
                                               const float* __restrict__ bias, float scale,
                                               float* __restrict__ dst)
{
    float4* d = reinterpret_cast<float4*>(dst);
    #pragma unroll
    for (int u4 = 0; u4 < 8; u4++) {
        float r[4];
        #pragma unroll
        for (int uu = 0; uu < 4; uu++) {
            const int u = u4 * 4 + uu;
            float sa = bias[u], sb = 0.f;
            const float4* w4 = reinterpret_cast<const float4*>(W + u * Tn);
            #pragma unroll
            for (int t4 = 0; t4 < 4; t4++) {
                float4 w = w4[t4];
                sa += e1[t4 * 4 + 0] * w.x + e1[t4 * 4 + 1] * w.y
                    + e1[t4 * 4 + 2] * w.z + e1[t4 * 4 + 3] * w.w;
            }
            #pragma unroll
            for (int t4 = 4; t4 < 8; t4++) {
                float4 w = w4[t4];
                sb += e1[t4 * 4 + 0] * w.x + e1[t4 * 4 + 1] * w.y
                    + e1[t4 * 4 + 2] * w.z + e1[t4 * 4 + 3] * w.w;
            }
            r[uu] = (sa + sb) * scale;
        }
        d[u4] = make_float4(r[0], r[1], r[2], r[3]);
    }
}

// ---------------- K1: per (b,p): bilinear E1 + fq/fk(scaled)/fv; 1 query/thread ----------------
__global__ __launch_bounds__(192) void k1_pair(
    const float* __restrict__ Eq, const float* __restrict__ Ep,
    const float* __restrict__ W_in,
    const float* __restrict__ Wq, const float* __restrict__ bq,
    const float* __restrict__ Wk, const float* __restrict__ bk,
    const float* __restrict__ Wv, const float* __restrict__ bv,
    const float* __restrict__ Wo1, const float* __restrict__ bo1,
    const float* __restrict__ Wo2, const float* __restrict__ bo2)
{
    const int b = blockIdx.x, p = blockIdx.y;
    __shared__ __align__(16) float sEp[Hn];
    __shared__ __align__(16) float sW3[Tn][Hn];
    __shared__ float sA2[Tn];
    const int tid = threadIdx.x;

    {
        const float4* eprow = reinterpret_cast<const float4*>(Ep + (b * KPn + p) * Hn);
        float4* sEp4w = reinterpret_cast<float4*>(sEp);
        for (int i = tid; i < Hn / 4; i += 192) sEp4w[i] = eprow[i];
        for (int i = tid; i < Tn; i += 192) sA2[i] = g_A2[(b * KPn + p) * Tn + i];
        for (int i4 = tid; i4 < Tn * Hn / 4; i4 += 192) {
            int t = i4 >> 6, h4 = i4 & 63;
            reinterpret_cast<float4*>(&sW3[t][0])[h4] =
                reinterpret_cast<const float4*>(W_in + t * Rn + 2 * Hn)[h4];
        }
    }
    __syncthreads();

    const int q = tid;
    float acc[Tn];
    #pragma unroll
    for (int t = 0; t < Tn; t++) acc[t] = 0.f;

    const float4* eq4 = reinterpret_cast<const float4*>(Eq + (b * KQn + q) * Hn);
    const float4* sEp4 = reinterpret_cast<const float4*>(sEp);
    for (int h4 = 0; h4 < Hn / 4; h4++) {
        float4 e = eq4[h4];
        float4 pp = sEp4[h4];
        float4 ev = make_float4(e.x * pp.x, e.y * pp.y, e.z * pp.z, e.w * pp.w);
        #pragma unroll
        for (int t = 0; t < Tn; t++) {
            const float4 w = *reinterpret_cast<const float4*>(&sW3[t][h4 * 4]);
            acc[t] += ev.x * w.x + ev.y * w.y + ev.z * w.z + ev.w * w.w;
        }
    }
    {
        const float4* a1 = reinterpret_cast<const float4*>(g_A1 + (b * KQn + q) * Tn);
        #pragma unroll
        for (int t4 = 0; t4 < 8; t4++) {
            float4 a = a1[t4];
            acc[t4 * 4 + 0] += a.x + sA2[t4 * 4 + 0];
            acc[t4 * 4 + 1] += a.y + sA2[t4 * 4 + 1];
            acc[t4 * 4 + 2] += a.z + sA2[t4 * 4 + 2];
            acc[t4 * 4 + 3] += a.w + sA2[t4 * 4 + 3];
        }
    }

    // obv = sigmoid( relu(E1@Wo1^T+bo1) . Wo2 + bo2 ), folded into fk scale
    float ob = bo2[0];
    #pragma unroll 4
    for (int u = 0; u < Tn; u++) {
        float sa = bo1[u], sb = 0.f;
        const float4* w4 = reinterpret_cast<const float4*>(Wo1 + u * Tn);
        #pragma unroll
        for (int t4 = 0; t4 < 4; t4++) {
            float4 w = w4[t4];
            sa += acc[t4 * 4 + 0] * w.x + acc[t4 * 4 + 1] * w.y
                + acc[t4 * 4 + 2] * w.z + acc[t4 * 4 + 3] * w.w;
        }
        #pragma unroll
        for (int t4 = 4; t4 < 8; t4++) {
            float4 w = w4[t4];
            sb += acc[t4 * 4 + 0] * w.x + acc[t4 * 4 + 1] * w.y
                + acc[t4 * 4 + 2] * w.z + acc[t4 * 4 + 3] * w.w;
        }
        ob += fmaxf(sa + sb, 0.f) * Wo2[u];
    }
    const float sc = SCALEV / (1.f + __expf(-ob));

    const int pairbase = (b * KPn + p) * KQn + q;
    small_mm_store(acc, Wq, bq, 1.f, g_fq + pairbase * Tn);
    small_mm_store(acc, Wk, bk, sc,  g_fk + pairbase * Tn);
    small_mm_store(acc, Wv, bv, 1.f, g_fv + pairbase * Tn);
}

// ---------------- K2: horizontal attention -> Umh = (M_h . w4) ----------------
__global__ __launch_bounds__(96) void k2_attn_h(const float* __restrict__ mask,
                                               const float* __restrict__ W_out)
{
    extern __shared__ char smem[];
    float4* sfk = reinterpret_cast<float4*>(smem);
    float4* sfv = sfk + KQn * 8;
    float* sbias = reinterpret_cast<float*>(sfv + KQn * 8);
    float* sw4 = sbias + KQn;

    const int b = blockIdx.x, p = blockIdx.y;
    const int tid = threadIdx.x;
    const int base = (b * KPn + p) * KQn;

    const float4* fk4 = reinterpret_cast<const float4*>(g_fk + base * Tn);
    const float4* fv4 = reinterpret_cast<const float4*>(g_fv + base * Tn);
    for (int i = tid; i < KQn * 8; i += 96) { sfk[i] = fk4[i]; sfv[i] = fv4[i]; }
    for (int i = tid; i < KQn; i += 96) sbias[i] = (mask[base + i] < 0.5f) ? NEGV : 0.f;
    for (int i = tid; i < Tn; i += 96) sw4[i] = W_out[Rn + i];
    __syncthreads();

    const int q0 = tid, q1 = tid + 96;
    float4 f0[8], f1[8], a0[8], a1[8];
    {
        const float4* r0 = reinterpret_cast<const float4*>(g_fq + (base + q0) * Tn);
        const float4* r1 = reinterpret_cast<const float4*>(g_fq + (base + q1) * Tn);
        #pragma unroll
        for (int i = 0; i < 8; i++) {
            f0[i] = r0[i]; f1[i] = r1[i];
            a0[i] = make_float4(0.f, 0.f, 0.f, 0.f);
            a1[i] = make_float4(0.f, 0.f, 0.f, 0.f);
        }
    }
    float s0 = 0.f, s1 = 0.f;

    for (int k = 0; k < KQn; k++) {
        const float4* kk = &sfk[k * 8];
        const float d00 = dot4(f0[0], kk[0]) + dot4(f0[1], kk[1]);
        const float d01 = dot4(f0[2], kk[2]) + dot4(f0[3], kk[3]);
        const float d02 = dot4(f0[4], kk[4]) + dot4(f0[5], kk[5]);
        const float d03 = dot4(f0[6], kk[6]) + dot4(f0[7], kk[7]);
        const float d10 = dot4(f1[0], kk[0]) + dot4(f1[1], kk[1]);
        const float d11 = dot4(f1[2], kk[2]) + dot4(f1[3], kk[3]);
        const float d12 = dot4(f1[4], kk[4]) + dot4(f1[5], kk[5]);
        const float d13 = dot4(f1[6], kk[6]) + dot4(f1[7], kk[7]);
        const float l0 = sbias[k] + ((d00 + d01) + (d02 + d03));
        const float l1 = sbias[k] + ((d10 + d11) + (d12 + d13));
        const float e0 = __expf(l0), e1 = __expf(l1);
        s0 += e0; s1 += e1;
        const float4* vv = &sfv[k * 8];
        #pragma unroll
        for (int i = 0; i < 8; i++) {
            float4 v = vv[i];
            a0[i].x += e0 * v.x; a0[i].y += e0 * v.y; a0[i].z += e0 * v.z; a0[i].w += e0 * v.w;
            a1[i].x += e1 * v.x; a1[i].y += e1 * v.y; a1[i].z += e1 * v.z; a1[i].w += e1 * v.w;
        }
    }
    const float4* w44 = reinterpret_cast<const float4*>(sw4);
    float um0 = 0.f, um1 = 0.f;
    #pragma unroll
    for (int i = 0; i < 8; i++) {
        float4 w = w44[i];
        um0 += dot4(a0[i], w);
        um1 += dot4(a1[i], w);
    }
    g_Umh[base + q0] = um0 / s0;
    g_Umh[base + q1] = um1 / s1;
}

// ---------------- K3: vertical attention -> Um = Umh + (M_v . w4) ----------------
__global__ __launch_bounds__(96) void k3_attn_v(const float* __restrict__ mask,
                                                const float* __restrict__ W_out)
{
    extern __shared__ char smem[];
    float4* sfk = reinterpret_cast<float4*>(smem);
    float4* sfv = sfk + KPn * 8;
    float* sbias = reinterpret_cast<float*>(sfv + KPn * 8);
    float* sw4 = sbias + KPn;

    const int b = blockIdx.x, q = blockIdx.y;
    const int tid = threadIdx.x;

    const float4* fkg = reinterpret_cast<const float4*>(g_fk);
    const float4* fvg = reinterpret_cast<const float4*>(g_fv);
    for (int i = tid; i < KPn * 8; i += 96) {
        const int k = i >> 3, t4 = i & 7;
        const int ridx = ((b * KPn + k) * KQn + q) * 8 + t4;
        sfk[i] = fkg[ridx];
        sfv[i] = fvg[ridx];
    }
    for (int i = tid; i < KPn; i += 96)
        sbias[i] = (mask[(b * KPn + i) * KQn + q] < 0.5f) ? NEGV : 0.f;
    for (int i = tid; i < Tn; i += 96) sw4[i] = W_out[Rn + i];
    __syncthreads();

    const int p0 = tid, p1 = tid + 96;
    float4 f0[8], f1[8], a0[8], a1[8];
    {
        const float4* r0 = reinterpret_cast<const float4*>(g_fq + ((b * KPn + p0) * KQn + q) * Tn);
        const float4* r1 = reinterpret_cast<const float4*>(g_fq + ((b * KPn + p1) * KQn + q) * Tn);
        #pragma unroll
        for (int i = 0; i < 8; i++) {
            f0[i] = r0[i]; f1[i] = r1[i];
            a0[i] = make_float4(0.f, 0.f, 0.f, 0.f);
            a1[i] = make_float4(0.f, 0.f, 0.f, 0.f);
        }
    }
    float s0 = 0.f, s1 = 0.f;

    for (int k = 0; k < KPn; k++) {
        const float4* kk = &sfk[k * 8];
        const float d00 = dot4(f0[0], kk[0]) + dot4(f0[1], kk[1]);
        const float d01 = dot4(f0[2], kk[2]) + dot4(f0[3], kk[3]);
        const float d02 = dot4(f0[4], kk[4]) + dot4(f0[5], kk[5]);
        const float d03 = dot4(f0[6], kk[6]) + dot4(f0[7], kk[7]);
        const float d10 = dot4(f1[0], kk[0]) + dot4(f1[1], kk[1]);
        const float d11 = dot4(f1[2], kk[2]) + dot4(f1[3], kk[3]);
        const float d12 = dot4(f1[4], kk[4]) + dot4(f1[5], kk[5]);
        const float d13 = dot4(f1[6], kk[6]) + dot4(f1[7], kk[7]);
        const float l0 = sbias[k] + ((d00 + d01) + (d02 + d03));
        const float l1 = sbias[k] + ((d10 + d11) + (d12 + d13));
        const float e0 = __expf(l0), e1 = __expf(l1);
        s0 += e0; s1 += e1;
        const float4* vv = &sfv[k * 8];
        #pragma unroll
        for (int i = 0; i < 8; i++) {
            float4 v = vv[i];
            a0[i].x += e0 * v.x; a0[i].y += e0 * v.y; a0[i].z += e0 * v.z; a0[i].w += e0 * v.w;
            a1[i].x += e1 * v.x; a1[i].y += e1 * v.y; a1[i].z += e1 * v.z; a1[i].w += e1 * v.w;
        }
    }
    const float4* w44 = reinterpret_cast<const float4*>(sw4);
    float um0 = 0.f, um1 = 0.f;
    #pragma unroll
    for (int i = 0; i < 8; i++) {
        float4 w = w44[i];
        um0 += dot4(a0[i], w);
        um1 += dot4(a1[i], w);
    }
    const int idx0 = (b * KPn + p0) * KQn + q;
    const int idx1 = (b * KPn + p1) * KQn + q;
    g_Um[idx0] = g_Umh[idx0] + um0 / s0;
    g_Um[idx1] = g_Umh[idx1] + um1 / s1;
}

// ---------------- K4: U = Ep @ (Eq.w3)^T + u1 + u2 + Um, masked (tiled GEMM) ----------------
__global__ __launch_bounds__(256) void k4_U(
    const float* __restrict__ Eq, const float* __restrict__ Ep,
    const float* __restrict__ W_out, const float* __restrict__ mask)
{
    const int b = blockIdx.z;
    const int row0 = blockIdx.y * 64;   // p
    const int col0 = blockIdx.x * 64;   // q
    __shared__ float sA[64][17];
    __shared__ float sB[64][17];
    __shared__ float sw3[Hn];
    const int tid = threadIdx.x;
    const int tx = tid & 15, ty = tid >> 4;
    const int r = tid >> 2, k4i = (tid & 3) * 4;
    float c[4][4] = {};

    for (int i = tid; i < Hn; i += 256) sw3[i] = W_out[2 * Hn + i];
    __syncthreads();

    for (int kc = 0; kc < Hn; kc += 16) {
        float4 av = *reinterpret_cast<const float4*>(Ep + (b * KPn + row0 + r) * Hn + kc + k4i);
        float4 bv = *reinterpret_cast<const float4*>(Eq + (b * KQn + col0 + r) * Hn + kc + k4i);
        bv.x *= sw3[kc + k4i]; bv.y *= sw3[kc + k4i + 1];
        bv.z *= sw3[kc + k4i + 2]; bv.w *= sw3[kc + k4i + 3];
        __syncthreads();
        sA[r][k4i] = av.x; sA[r][k4i + 1] = av.y; sA[r][k4i + 2] = av.z; sA[r][k4i + 3] = av.w;
        sB[r][k4i] = bv.x; sB[r][k4i + 1] = bv.y; sB[r][k4i + 2] = bv.z; sB[r][k4i + 3] = bv.w;
        __syncthreads();
        #pragma unroll
        for (int kk = 0; kk < 16; kk++) {
            float a[4], bb[4];
            #pragma unroll
            for (int i = 0; i < 4; i++) a[i] = sA[ty + 16 * i][kk];
            #pragma unroll
            for (int j = 0; j < 4; j++) bb[j] = sB[tx + 16 * j][kk];
            #pragma unroll
            for (int i = 0; i < 4; i++)
                #pragma unroll
                for (int j = 0; j < 4; j++) c[i][j] += a[i] * bb[j];
        }
    }
    #pragma unroll
    for (int i = 0; i < 4; i++) {
        const int rr = row0 + ty + 16 * i;
        #pragma unroll
        for (int j = 0; j < 4; j++) {
            const int cc = col0 + tx + 16 * j;
            const int idx = (b * KPn + rr) * KQn + cc;
            float Uv = c[i][j] + g_u1[b * KQn + cc] + g_u2[b * KPn + rr] + g_Um[idx];
            if (mask[idx] < 0.5f) Uv = NEGV;
            g_U[idx] = Uv;
        }
    }
}

// ---------------- K5a: softmax over q -> A''_p, build G_left ----------------
__global__ __launch_bounds__(256) void k5_rowsoft(const float* __restrict__ Eq, const float* __restrict__ Ep)
{
    const int b = blockIdx.x, p = blockIdx.y;
    __shared__ float sw[KQn];
    __shared__ float red[256];
    const int tid = threadIdx.x;
    const int base = (b * KPn + p) * KQn;

    float v = (tid < KQn) ? g_U[base + tid] : -3.4e38f;
    red[tid] = v; __syncthreads();
    for (int o = 128; o; o >>= 1) { if (tid < o) red[tid] = fmaxf(red[tid], red[tid + o]); __syncthreads(); }
    const float m = red[0]; __syncthreads();
    const float e = (tid < KQn) ? __expf(v - m) : 0.f;
    red[tid] = e; __syncthreads();
    for (int o = 128; o; o >>= 1) { if (tid < o) red[tid] += red[tid + o]; __syncthreads(); }
    const float inv = 1.f / red[0];
    if (tid < KQn) sw[tid] = e * inv;
    __syncthreads();

    const int h = tid;
    float a0 = 0.f, a1 = 0.f;
    for (int k = 0; k < KQn; k += 2) {
        a0 += sw[k] * Eq[(b * KQn + k) * Hn + h];
        a1 += sw[k + 1] * Eq[(b * KQn + k + 1) * Hn + h];
    }
    const float a = a0 + a1;
    const float ep = Ep[(b * KPn + p) * Hn + h];
    float* G = g_Gl + (b * KPn + p) * Rn;
    G[h] = ep; G[Hn + h] = a; G[2 * Hn + h] = ep * a;
}

// ---------------- K5b: softmax over p -> B''_p, build G_right ----------------
__global__ __launch_bounds__(256) void k5_colsoft(const float* __restrict__ Eq, const float* __restrict__ Ep)
{
    const int b = blockIdx.x, q = blockIdx.y;
    __shared__ float sw[KPn];
    __shared__ float red[256];
    const int tid = threadIdx.x;

    float v = (tid < KPn) ? g_U[(b * KPn + tid) * KQn + q] : -3.4e38f;
    red[tid] = v; __syncthreads();
    for (int o = 128; o; o >>= 1) { if (tid < o) red[tid] = fmaxf(red[tid], red[tid + o]); __syncthreads(); }
    const float m = red[0]; __syncthreads();
    const float e = (tid < KPn) ? __expf(v - m) : 0.f;
    red[tid] = e; __syncthreads();
    for (int o = 128; o; o >>= 1) { if (tid < o) red[tid] += red[tid + o]; __syncthreads(); }
    const float inv = 1.f / red[0];
    if (tid < KPn) sw[tid] = e * inv;
    __syncthreads();

    const int h = tid;
    float a0 = 0.f, a1 = 0.f;
    for (int k = 0; k < KPn; k += 2) {
        a0 += sw[k] * Ep[(b * KPn + k) * Hn + h];
        a1 += sw[k + 1] * Ep[(b * KPn + k + 1) * Hn + h];
    }
    const float a = a0 + a1;
    const float eq = Eq[(b * KQn + q) * Hn + h];
    float* G = g_Gr + (b * KQn + q) * Rn;
    G[h] = eq; G[Hn + h] = a; G[2 * Hn + h] = eq * a;
}

// ---------------- K6: gates, 128x64 tile, 8x4 per thread ----------------
__global__ __launch_bounds__(256) void k6_gate(
    const float* __restrict__ Wl, const float* __restrict__ bl,
    const float* __restrict__ Wr, const float* __restrict__ br)
{
    const int side = blockIdx.z;
    const float* __restrict__ G = side ? g_Gr : g_Gl;
    const float* __restrict__ W = side ? Wr : Wl;
    const float* __restrict__ bias = side ? br : bl;
    float* __restrict__ outp = side ? g_right : g_left;
    const int row0 = blockIdx.y * 128;
    const int col0 = blockIdx.x * 64;
    __shared__ float sA[128][17];
    __shared__ float sB[64][17];
    const int tid = threadIdx.x;
    const int tx = tid & 15, ty = tid >> 4;
    float c[8][4] = {};

    const int ra = tid >> 1, ka = (tid & 1) * 8;
    const int rb = tid >> 2, kb = (tid & 3) * 4;

    for (int kc = 0; kc < Rn; kc += 16) {
        float4 av0 = *reinterpret_cast<const float4*>(G + (row0 + ra) * Rn + kc + ka);
        float4 av1 = *reinterpret_cast<const float4*>(G + (row0 + ra) * Rn + kc + ka + 4);
        float4 bv = *reinterpret_cast<const float4*>(W + (col0 + rb) * Rn + kc + kb);
        __syncthreads();
        sA[ra][ka] = av0.x; sA[ra][ka + 1] = av0.y; sA[ra][ka + 2] = av0.z; sA[ra][ka + 3] = av0.w;
        sA[ra][ka + 4] = av1.x; sA[ra][ka + 5] = av1.y; sA[ra][ka + 6] = av1.z; sA[ra][ka + 7] = av1.w;
        sB[rb][kb] = bv.x; sB[rb][kb + 1] = bv.y; sB[rb][kb + 2] = bv.z; sB[rb][kb + 3] = bv.w;
        __syncthreads();
        #pragma unroll
        for (int kk = 0; kk < 16; kk++) {
            float a[8], bb[4];
            #pragma unroll
            for (int i = 0; i < 8; i++) a[i] = sA[ty + 16 * i][kk];
            #pragma unroll
            for (int j = 0; j < 4; j++) bb[j] = sB[tx + 16 * j][kk];
            #pragma unroll
            for (int i = 0; i < 8; i++)
                #pragma unroll
                for (int j = 0; j < 4; j++) c[i][j] += a[i] * bb[j];
        }
    }
    #pragma unroll
    for (int i = 0; i < 8; i++) {
        const int r = row0 + ty + 16 * i;
        #pragma unroll
        for (int j = 0; j < 4; j++) {
            const int cc = col0 + tx + 16 * j;
            const float g = G[r * Rn + cc];
            const float s = 1.f / (1.f + __expf(-(c[i][j] + bias[cc])));
            outp[r * Rn + cc] = s * g;
        }
    }
}

// ---------------- K7: split-K partials of left @ right^T ----------------
__global__ __launch_bounds__(256) void k7_partial()
{
    const int z = blockIdx.z;
    const int b = z >> 2, ks = z & 3;
    const int kbase = ks * 192;
    const float* __restrict__ A = g_left + b * KPn * Rn;
    const float* __restrict__ Bm = g_right + b * KQn * Rn;
    const int row0 = blockIdx.y * 64;
    const int col0 = blockIdx.x * 64;
    __shared__ float sA[64][17];
    __shared__ float sB[64][17];
    const int tid = threadIdx.x;
    const int tx = tid & 15, ty = tid >> 4;
    float c[4][4] = {};

    for (int kc = kbase; kc < kbase + 192; kc += 16) {
        const int r = tid >> 2, k4 = (tid & 3) * 4;
        float4 av = *reinterpret_cast<const float4*>(A + (row0 + r) * Rn + kc + k4);
        float4 bv = *reinterpret_cast<const float4*>(Bm + (col0 + r) * Rn + kc + k4);
        __syncthreads();
        sA[r][k4] = av.x; sA[r][k4 + 1] = av.y; sA[r][k4 + 2] = av.z; sA[r][k4 + 3] = av.w;
        sB[r][k4] = bv.x; sB[r][k4 + 1] = bv.y; sB[r][k4 + 2] = bv.z; sB[r][k4 + 3] = bv.w;
        __syncthreads();
        #pragma unroll
        for (int kk = 0; kk < 16; kk++) {
            float a[4], bb[4];
            #pragma unroll
            for (int i = 0; i < 4; i++) a[i] = sA[ty + 16 * i][kk];
            #pragma unroll
            for (int j = 0; j < 4; j++) bb[j] = sB[tx + 16 * j][kk];
            #pragma unroll
            for (int i = 0; i < 4; i++)
                #pragma unroll
                for (int j = 0; j < 4; j++) c[i][j] += a[i] * bb[j];
        }
    }
    float* dst = g_part + ks * (BB * KPn * KQn) + b * (KPn * KQn);
    #pragma unroll
    for (int i = 0; i < 4; i++) {
        const int r = row0 + ty + 16 * i;
        #pragma unroll
        for (int j = 0; j < 4; j++) {
            const int cc = col0 + tx + 16 * j;
            dst[r * KQn + cc] = c[i][j];
        }
    }
}

// ---------------- K8: reduce split-K + relu ----------------
__global__ __launch_bounds__(256) void k8_reduce(float* __restrict__ outp)
{
    const int idx = blockIdx.x * 256 + threadIdx.x;
    const int n = BB * KPn * KQn;
    if (idx < n) {
        float s = (g_part[idx] + g_part[n + idx]) + (g_part[2 * n + idx] + g_part[3 * n + idx]);
        outp[idx] = fmaxf(s, 0.f);
    }
}

// ---------------- launch ----------------
extern "C" void kernel_launch(void* const* d_in, const int* in_sizes, int n_in,
                              void* d_out, int out_size)
{
    const float* Eq    = (const float*)d_in[0];
    const float* Ep    = (const float*)d_in[1];
    const float* mask  = (const float*)d_in[2];
    const float* W_in  = (const float*)d_in[3];
    const float* Wq    = (const float*)d_in[4];
    const float* bq    = (const float*)d_in[5];
    const float* Wk    = (const float*)d_in[6];
    const float* bk    = (const float*)d_in[7];
    const float* Wv    = (const float*)d_in[8];
    const float* bv    = (const float*)d_in[9];
    const float* Wo1   = (const float*)d_in[10];
    const float* bo1   = (const float*)d_in[11];
    const float* Wo2   = (const float*)d_in[12];
    const float* bo2   = (const float*)d_in[13];
    const float* W_out = (const float*)d_in[14];
    const float* Wl    = (const float*)d_in[15];
    const float* bl    = (const float*)d_in[16];
    const float* Wr    = (const float*)d_in[17];
    const float* br    = (const float*)d_in[18];
    float* outp = (float*)d_out;

    const int smemA = (KQn * 8 * 16) * 2 + KQn * 4 + Tn * 4;   // 50048
    cudaFuncSetAttribute(k2_attn_h, cudaFuncAttributeMaxDynamicSharedMemorySize, smemA);
    cudaFuncSetAttribute(k3_attn_v, cudaFuncAttributeMaxDynamicSharedMemorySize, smemA);

    k0_rowproj<<<dim3(BB, 2, 4), dim3(32, 8)>>>(Eq, Ep, W_in, W_out);
    k1_pair<<<dim3(BB, KPn), 192>>>(Eq, Ep, W_in, Wq, bq, Wk, bk, Wv, bv, Wo1, bo1, Wo2, bo2);
    k2_attn_h<<<dim3(BB, KPn), 96, smemA>>>(mask, W_out);
    k3_attn_v<<<dim3(BB, KQn), 96, smemA>>>(mask, W_out);
    k4_U<<<dim3(3, 3, BB), 256>>>(Eq, Ep, W_out, mask);
    k5_rowsoft<<<dim3(BB, KPn), 256>>>(Eq, Ep);
    k5_colsoft<<<dim3(BB, KQn), 256>>>(Eq, Ep);
    k6_gate<<<dim3(12, 6, 2), 256>>>(Wl, bl, Wr, br);
    k7_partial<<<dim3(3, 3, 16), 256>>>();
    k8_reduce<<<dim3(576), 256>>>(outp);
}

// round 6
// speedup vs baseline: 2.0408x; 1.2296x over previous
#include <cuda_runtime.h>
#include <math.h>

#define BB 4
#define KQn 192
#define KPn 192
#define Hn 256
#define Tn 32
#define Rn 768
#define NEGV (-1e9f)
#define SCALEV (0.17677669529663687f)   // 1/sqrt(32)

// ---------------- scratch ----------------
static __device__ float g_A1[BB * KQn * Tn];
static __device__ float g_A2[BB * KPn * Tn];
static __device__ float g_u1[BB * KQn];
static __device__ float g_u2[BB * KPn];
static __device__ float g_fq[BB * KPn * KQn * Tn];
static __device__ float g_fk[BB * KPn * KQn * Tn]; // pre-scaled by obv*SCALE
static __device__ float g_vw[BB * KPn * KQn];      // fv . w4 per pair
static __device__ float g_wv4[Tn];                 // Wv^T @ w4
static __device__ float g_c0[1];                   // bv . w4
static __device__ float g_Umh[BB * KPn * KQn];     // horizontal M . w4
static __device__ float g_Um[BB * KPn * KQn];      // total M . w4
static __device__ float g_U[BB * KPn * KQn];
static __device__ float g_Gl[BB * KPn * Rn];
static __device__ float g_Gr[BB * KQn * Rn];
static __device__ float g_left[BB * KPn * Rn];
static __device__ float g_right[BB * KQn * Rn];
static __device__ float g_part[4 * BB * KPn * KQn];

__device__ __forceinline__ float dot4(float4 a, float4 b) {
    return (a.x * b.x + a.y * b.y) + (a.z * b.z + a.w * b.w);
}

// ---------------- K0: per-row projections A1/A2 and u1/u2 ----------------
__global__ __launch_bounds__(256) void k0_rowproj(
    const float* __restrict__ Eq, const float* __restrict__ Ep,
    const float* __restrict__ W_in, const float* __restrict__ W_out)
{
    const int b = blockIdx.x;
    const int side = blockIdx.y;
    const float* src = side ? (Ep + b * KPn * Hn) : (Eq + b * KQn * Hn);
    const int woff = side ? Hn : 0;
    float* A = side ? (g_A2 + b * KPn * Tn) : (g_A1 + b * KQn * Tn);
    float* u = side ? (g_u2 + b * KPn) : (g_u1 + b * KQn);

    __shared__ float sW[Tn][Hn + 1];
    __shared__ float swv[Hn];
    const int tid = threadIdx.y * 32 + threadIdx.x;
    for (int i = tid; i < Tn * Hn; i += 256) {
        int t = i >> 8, h = i & 255;
        sW[t][h] = W_in[t * Rn + woff + h];
    }
    for (int i = tid; i < Hn; i += 256) swv[i] = W_out[woff + i];
    __syncthreads();

    const int t = threadIdx.x;
    const int y0 = blockIdx.z * 48;
    for (int y = y0 + threadIdx.y; y < y0 + 48; y += 8) {
        const float* row = src + y * Hn;
        float p0 = 0.f, p1 = 0.f, p2 = 0.f, p3 = 0.f, up = 0.f;
        for (int h = 0; h < Hn; h += 4) {
            p0 += row[h] * sW[t][h];
            p1 += row[h + 1] * sW[t][h + 1];
            p2 += row[h + 2] * sW[t][h + 2];
            p3 += row[h + 3] * sW[t][h + 3];
        }
        for (int h = t; h < Hn; h += 32) up += row[h] * swv[h];
        #pragma unroll
        for (int o = 16; o; o >>= 1) up += __shfl_down_sync(0xffffffffu, up, o);
        A[y * Tn + t] = (p0 + p1) + (p2 + p3);
        if (t == 0) u[y] = up;
    }
}

// ---------------- K0b: wv4 = Wv^T @ w4, c0 = bv . w4 ----------------
__global__ void k0b_wv4(const float* __restrict__ Wv, const float* __restrict__ bv,
                        const float* __restrict__ W_out)
{
    const int t = threadIdx.x;   // 32 threads
    float s = 0.f;
    for (int u = 0; u < Tn; u++) s += Wv[u * Tn + t] * W_out[Rn + u];
    g_wv4[t] = s;
    float c = bv[t] * W_out[Rn + t];
    #pragma unroll
    for (int o = 16; o; o >>= 1) c += __shfl_down_sync(0xffffffffu, c, o);
    if (t == 0) g_c0[0] = c;
}

// dst = (e1 @ W^T + bias) * scale, 2-way split accumulation
__device__ __forceinline__ void small_mm_store(const float* e1, const float* __restrict__ W,
                                               const float* __restrict__ bias, float scale,
                                               float* __restrict__ dst)
{
    float4* d = reinterpret_cast<float4*>(dst);
    #pragma unroll
    for (int u4 = 0; u4 < 8; u4++) {
        float r[4];
        #pragma unroll
        for (int uu = 0; uu < 4; uu++) {
            const int u = u4 * 4 + uu;
            float sa = bias[u], sb = 0.f;
            const float4* w4 = reinterpret_cast<const float4*>(W + u * Tn);
            #pragma unroll
            for (int t4 = 0; t4 < 4; t4++) {
                float4 w = w4[t4];
                sa += e1[t4 * 4 + 0] * w.x + e1[t4 * 4 + 1] * w.y
                    + e1[t4 * 4 + 2] * w.z + e1[t4 * 4 + 3] * w.w;
            }
            #pragma unroll
            for (int t4 = 4; t4 < 8; t4++) {
                float4 w = w4[t4];
                sb += e1[t4 * 4 + 0] * w.x + e1[t4 * 4 + 1] * w.y
                    + e1[t4 * 4 + 2] * w.z + e1[t4 * 4 + 3] * w.w;
            }
            r[uu] = (sa + sb) * scale;
        }
        d[u4] = make_float4(r[0], r[1], r[2], r[3]);
    }
}

// ---------------- K1: per (b,p): bilinear E1 + fq/fk(scaled) + vw; 1 query/thread ----------------
__global__ __launch_bounds__(192) void k1_pair(
    const float* __restrict__ Eq, const float* __restrict__ Ep,
    const float* __restrict__ W_in,
    const float* __restrict__ Wq, const float* __restrict__ bq,
    const float* __restrict__ Wk, const float* __restrict__ bk,
    const float* __restrict__ Wo1, const float* __restrict__ bo1,
    const float* __restrict__ Wo2, const float* __restrict__ bo2)
{
    const int b = blockIdx.x, p = blockIdx.y;
    __shared__ __align__(16) float sEp[Hn];
    __shared__ __align__(16) float sW3[Tn][Hn];
    __shared__ float sA2[Tn];
    __shared__ __align__(16) float swv4[Tn];
    const int tid = threadIdx.x;

    {
        const float4* eprow = reinterpret_cast<const float4*>(Ep + (b * KPn + p) * Hn);
        float4* sEp4w = reinterpret_cast<float4*>(sEp);
        for (int i = tid; i < Hn / 4; i += 192) sEp4w[i] = eprow[i];
        for (int i = tid; i < Tn; i += 192) { sA2[i] = g_A2[(b * KPn + p) * Tn + i]; swv4[i] = g_wv4[i]; }
        for (int i4 = tid; i4 < Tn * Hn / 4; i4 += 192) {
            int t = i4 >> 6, h4 = i4 & 63;
            reinterpret_cast<float4*>(&sW3[t][0])[h4] =
                reinterpret_cast<const float4*>(W_in + t * Rn + 2 * Hn)[h4];
        }
    }
    __syncthreads();

    const int q = tid;
    float acc[Tn];
    #pragma unroll
    for (int t = 0; t < Tn; t++) acc[t] = 0.f;

    const float4* eq4 = reinterpret_cast<const float4*>(Eq + (b * KQn + q) * Hn);
    const float4* sEp4 = reinterpret_cast<const float4*>(sEp);
    for (int h4 = 0; h4 < Hn / 4; h4++) {
        float4 e = eq4[h4];
        float4 pp = sEp4[h4];
        float4 ev = make_float4(e.x * pp.x, e.y * pp.y, e.z * pp.z, e.w * pp.w);
        #pragma unroll
        for (int t = 0; t < Tn; t++) {
            const float4 w = *reinterpret_cast<const float4*>(&sW3[t][h4 * 4]);
            acc[t] += ev.x * w.x + ev.y * w.y + ev.z * w.z + ev.w * w.w;
        }
    }
    {
        const float4* a1 = reinterpret_cast<const float4*>(g_A1 + (b * KQn + q) * Tn);
        #pragma unroll
        for (int t4 = 0; t4 < 8; t4++) {
            float4 a = a1[t4];
            acc[t4 * 4 + 0] += a.x + sA2[t4 * 4 + 0];
            acc[t4 * 4 + 1] += a.y + sA2[t4 * 4 + 1];
            acc[t4 * 4 + 2] += a.z + sA2[t4 * 4 + 2];
            acc[t4 * 4 + 3] += a.w + sA2[t4 * 4 + 3];
        }
    }

    // obv, folded into fk scale
    float ob = bo2[0];
    #pragma unroll 4
    for (int u = 0; u < Tn; u++) {
        float sa = bo1[u], sb = 0.f;
        const float4* w4 = reinterpret_cast<const float4*>(Wo1 + u * Tn);
        #pragma unroll
        for (int t4 = 0; t4 < 4; t4++) {
            float4 w = w4[t4];
            sa += acc[t4 * 4 + 0] * w.x + acc[t4 * 4 + 1] * w.y
                + acc[t4 * 4 + 2] * w.z + acc[t4 * 4 + 3] * w.w;
        }
        #pragma unroll
        for (int t4 = 4; t4 < 8; t4++) {
            float4 w = w4[t4];
            sb += acc[t4 * 4 + 0] * w.x + acc[t4 * 4 + 1] * w.y
                + acc[t4 * 4 + 2] * w.z + acc[t4 * 4 + 3] * w.w;
        }
        ob += fmaxf(sa + sb, 0.f) * Wo2[u];
    }
    const float sc = SCALEV / (1.f + __expf(-ob));

    // vw = acc . wv4 + c0   (== (E1@Wv^T+bv) . w4)
    float va = 0.f, vb = 0.f;
    const float4* wv44 = reinterpret_cast<const float4*>(swv4);
    const float4* acc4 = reinterpret_cast<const float4*>(acc);
    #pragma unroll
    for (int t4 = 0; t4 < 4; t4++) va += dot4(acc4[t4], wv44[t4]);
    #pragma unroll
    for (int t4 = 4; t4 < 8; t4++) vb += dot4(acc4[t4], wv44[t4]);

    const int pairbase = (b * KPn + p) * KQn + q;
    g_vw[pairbase] = (va + vb) + g_c0[0];
    small_mm_store(acc, Wq, bq, 1.f, g_fq + pairbase * Tn);
    small_mm_store(acc, Wk, bk, sc,  g_fk + pairbase * Tn);
}

// ---------------- K2: horizontal attention -> Umh (no V GEMM) ----------------
__global__ __launch_bounds__(96) void k2_attn_h(const float* __restrict__ mask)
{
    __shared__ __align__(16) float4 sfk[KQn * 8];   // 24576 B
    __shared__ __align__(8) float2 sbv[KQn];        // {bias, vw}

    const int b = blockIdx.x, p = blockIdx.y;
    const int tid = threadIdx.x;
    const int base = (b * KPn + p) * KQn;

    const float4* fk4 = reinterpret_cast<const float4*>(g_fk + base * Tn);
    for (int i = tid; i < KQn * 8; i += 96) sfk[i] = fk4[i];
    for (int i = tid; i < KQn; i += 96)
        sbv[i] = make_float2((mask[base + i] < 0.5f) ? NEGV : 0.f, g_vw[base + i]);
    __syncthreads();

    const int q0 = tid, q1 = tid + 96;
    float4 f0[8], f1[8];
    {
        const float4* r0 = reinterpret_cast<const float4*>(g_fq + (base + q0) * Tn);
        const float4* r1 = reinterpret_cast<const float4*>(g_fq + (base + q1) * Tn);
        #pragma unroll
        for (int i = 0; i < 8; i++) { f0[i] = r0[i]; f1[i] = r1[i]; }
    }
    float s0 = 0.f, s1 = 0.f, t0 = 0.f, t1 = 0.f;

    #pragma unroll 2
    for (int k = 0; k < KQn; k++) {
        const float4* kk = &sfk[k * 8];
        const float d00 = dot4(f0[0], kk[0]) + dot4(f0[1], kk[1]);
        const float d01 = dot4(f0[2], kk[2]) + dot4(f0[3], kk[3]);
        const float d02 = dot4(f0[4], kk[4]) + dot4(f0[5], kk[5]);
        const float d03 = dot4(f0[6], kk[6]) + dot4(f0[7], kk[7]);
        const float d10 = dot4(f1[0], kk[0]) + dot4(f1[1], kk[1]);
        const float d11 = dot4(f1[2], kk[2]) + dot4(f1[3], kk[3]);
        const float d12 = dot4(f1[4], kk[4]) + dot4(f1[5], kk[5]);
        const float d13 = dot4(f1[6], kk[6]) + dot4(f1[7], kk[7]);
        const float2 bv2 = sbv[k];
        const float e0 = __expf(bv2.x + ((d00 + d01) + (d02 + d03)));
        const float e1 = __expf(bv2.x + ((d10 + d11) + (d12 + d13)));
        s0 += e0; t0 += e0 * bv2.y;
        s1 += e1; t1 += e1 * bv2.y;
    }
    g_Umh[base + q0] = t0 / s0;
    g_Umh[base + q1] = t1 / s1;
}

// ---------------- K3: vertical attention -> Um = Umh + t/s ----------------
__global__ __launch_bounds__(96) void k3_attn_v(const float* __restrict__ mask)
{
    __shared__ __align__(16) float4 sfk[KPn * 8];
    __shared__ __align__(8) float2 sbv[KPn];

    const int b = blockIdx.x, q = blockIdx.y;
    const int tid = threadIdx.x;

    const float4* fkg = reinterpret_cast<const float4*>(g_fk);
    for (int i = tid; i < KPn * 8; i += 96) {
        const int k = i >> 3, t4 = i & 7;
        sfk[i] = fkg[((b * KPn + k) * KQn + q) * 8 + t4];
    }
    for (int i = tid; i < KPn; i += 96) {
        const int idx = (b * KPn + i) * KQn + q;
        sbv[i] = make_float2((mask[idx] < 0.5f) ? NEGV : 0.f, g_vw[idx]);
    }
    __syncthreads();

    const int p0 = tid, p1 = tid + 96;
    float4 f0[8], f1[8];
    {
        const float4* r0 = reinterpret_cast<const float4*>(g_fq + ((b * KPn + p0) * KQn + q) * Tn);
        const float4* r1 = reinterpret_cast<const float4*>(g_fq + ((b * KPn + p1) * KQn + q) * Tn);
        #pragma unroll
        for (int i = 0; i < 8; i++) { f0[i] = r0[i]; f1[i] = r1[i]; }
    }
    float s0 = 0.f, s1 = 0.f, t0 = 0.f, t1 = 0.f;

    #pragma unroll 2
    for (int k = 0; k < KPn; k++) {
        const float4* kk = &sfk[k * 8];
        const float d00 = dot4(f0[0], kk[0]) + dot4(f0[1], kk[1]);
        const float d01 = dot4(f0[2], kk[2]) + dot4(f0[3], kk[3]);
        const float d02 = dot4(f0[4], kk[4]) + dot4(f0[5], kk[5]);
        const float d03 = dot4(f0[6], kk[6]) + dot4(f0[7], kk[7]);
        const float d10 = dot4(f1[0], kk[0]) + dot4(f1[1], kk[1]);
        const float d11 = dot4(f1[2], kk[2]) + dot4(f1[3], kk[3]);
        const float d12 = dot4(f1[4], kk[4]) + dot4(f1[5], kk[5]);
        const float d13 = dot4(f1[6], kk[6]) + dot4(f1[7], kk[7]);
        const float2 bv2 = sbv[k];
        const float e0 = __expf(bv2.x + ((d00 + d01) + (d02 + d03)));
        const float e1 = __expf(bv2.x + ((d10 + d11) + (d12 + d13)));
        s0 += e0; t0 += e0 * bv2.y;
        s1 += e1; t1 += e1 * bv2.y;
    }
    const int idx0 = (b * KPn + p0) * KQn + q;
    const int idx1 = (b * KPn + p1) * KQn + q;
    g_Um[idx0] = g_Umh[idx0] + t0 / s0;
    g_Um[idx1] = g_Umh[idx1] + t1 / s1;
}

// ---------------- K4: U = Ep @ (Eq.w3)^T + u1 + u2 + Um, masked ----------------
__global__ __launch_bounds__(256) void k4_U(
    const float* __restrict__ Eq, const float* __restrict__ Ep,
    const float* __restrict__ W_out, const float* __restrict__ mask)
{
    const int b = blockIdx.z;
    const int row0 = blockIdx.y * 64;
    const int col0 = blockIdx.x * 64;
    __shared__ float sA[64][17];
    __shared__ float sB[64][17];
    __shared__ float sw3[Hn];
    const int tid = threadIdx.x;
    const int tx = tid & 15, ty = tid >> 4;
    const int r = tid >> 2, k4i = (tid & 3) * 4;
    float c[4][4] = {};

    for (int i = tid; i < Hn; i += 256) sw3[i] = W_out[2 * Hn + i];
    __syncthreads();

    for (int kc = 0; kc < Hn; kc += 16) {
        float4 av = *reinterpret_cast<const float4*>(Ep + (b * KPn + row0 + r) * Hn + kc + k4i);
        float4 bv = *reinterpret_cast<const float4*>(Eq + (b * KQn + col0 + r) * Hn + kc + k4i);
        bv.x *= sw3[kc + k4i]; bv.y *= sw3[kc + k4i + 1];
        bv.z *= sw3[kc + k4i + 2]; bv.w *= sw3[kc + k4i + 3];
        __syncthreads();
        sA[r][k4i] = av.x; sA[r][k4i + 1] = av.y; sA[r][k4i + 2] = av.z; sA[r][k4i + 3] = av.w;
        sB[r][k4i] = bv.x; sB[r][k4i + 1] = bv.y; sB[r][k4i + 2] = bv.z; sB[r][k4i + 3] = bv.w;
        __syncthreads();
        #pragma unroll
        for (int kk = 0; kk < 16; kk++) {
            float a[4], bb[4];
            #pragma unroll
            for (int i = 0; i < 4; i++) a[i] = sA[ty + 16 * i][kk];
            #pragma unroll
            for (int j = 0; j < 4; j++) bb[j] = sB[tx + 16 * j][kk];
            #pragma unroll
            for (int i = 0; i < 4; i++)
                #pragma unroll
                for (int j = 0; j < 4; j++) c[i][j] += a[i] * bb[j];
        }
    }
    #pragma unroll
    for (int i = 0; i < 4; i++) {
        const int rr = row0 + ty + 16 * i;
        #pragma unroll
        for (int j = 0; j < 4; j++) {
            const int cc = col0 + tx + 16 * j;
            const int idx = (b * KPn + rr) * KQn + cc;
            float Uv = c[i][j] + g_u1[b * KQn + cc] + g_u2[b * KPn + rr] + g_Um[idx];
            if (mask[idx] < 0.5f) Uv = NEGV;
            g_U[idx] = Uv;
        }
    }
}

// ---------------- K5a: softmax over q -> A''_p, build G_left ----------------
__global__ __launch_bounds__(256) void k5_rowsoft(const float* __restrict__ Eq, const float* __restrict__ Ep)
{
    const int b = blockIdx.x, p = blockIdx.y;
    __shared__ float sw[KQn];
    __shared__ float red[256];
    const int tid = threadIdx.x;
    const int base = (b * KPn + p) * KQn;

    float v = (tid < KQn) ? g_U[base + tid] : -3.4e38f;
    red[tid] = v; __syncthreads();
    for (int o = 128; o; o >>= 1) { if (tid < o) red[tid] = fmaxf(red[tid], red[tid + o]); __syncthreads(); }
    const float m = red[0]; __syncthreads();
    const float e = (tid < KQn) ? __expf(v - m) : 0.f;
    red[tid] = e; __syncthreads();
    for (int o = 128; o; o >>= 1) { if (tid < o) red[tid] += red[tid + o]; __syncthreads(); }
    const float inv = 1.f / red[0];
    if (tid < KQn) sw[tid] = e * inv;
    __syncthreads();

    const int h = tid;
    float a0 = 0.f, a1 = 0.f;
    for (int k = 0; k < KQn; k += 2) {
        a0 += sw[k] * Eq[(b * KQn + k) * Hn + h];
        a1 += sw[k + 1] * Eq[(b * KQn + k + 1) * Hn + h];
    }
    const float a = a0 + a1;
    const float ep = Ep[(b * KPn + p) * Hn + h];
    float* G = g_Gl + (b * KPn + p) * Rn;
    G[h] = ep; G[Hn + h] = a; G[2 * Hn + h] = ep * a;
}

// ---------------- K5b: softmax over p -> B''_p, build G_right ----------------
__global__ __launch_bounds__(256) void k5_colsoft(const float* __restrict__ Eq, const float* __restrict__ Ep)
{
    const int b = blockIdx.x, q = blockIdx.y;
    __shared__ float sw[KPn];
    __shared__ float red[256];
    const int tid = threadIdx.x;

    float v = (tid < KPn) ? g_U[(b * KPn + tid) * KQn + q] : -3.4e38f;
    red[tid] = v; __syncthreads();
    for (int o = 128; o; o >>= 1) { if (tid < o) red[tid] = fmaxf(red[tid], red[tid + o]); __syncthreads(); }
    const float m = red[0]; __syncthreads();
    const float e = (tid < KPn) ? __expf(v - m) : 0.f;
    red[tid] = e; __syncthreads();
    for (int o = 128; o; o >>= 1) { if (tid < o) red[tid] += red[tid + o]; __syncthreads(); }
    const float inv = 1.f / red[0];
    if (tid < KPn) sw[tid] = e * inv;
    __syncthreads();

    const int h = tid;
    float a0 = 0.f, a1 = 0.f;
    for (int k = 0; k < KPn; k += 2) {
        a0 += sw[k] * Ep[(b * KPn + k) * Hn + h];
        a1 += sw[k + 1] * Ep[(b * KPn + k + 1) * Hn + h];
    }
    const float a = a0 + a1;
    const float eq = Eq[(b * KQn + q) * Hn + h];
    float* G = g_Gr + (b * KQn + q) * Rn;
    G[h] = eq; G[Hn + h] = a; G[2 * Hn + h] = eq * a;
}

// ---------------- K6: gates, 128x64 tile, 8x4 per thread ----------------
__global__ __launch_bounds__(256) void k6_gate(
    const float* __restrict__ Wl, const float* __restrict__ bl,
    const float* __restrict__ Wr, const float* __restrict__ br)
{
    const int side = blockIdx.z;
    const float* __restrict__ G = side ? g_Gr : g_Gl;
    const float* __restrict__ W = side ? Wr : Wl;
    const float* __restrict__ bias = side ? br : bl;
    float* __restrict__ outp = side ? g_right : g_left;
    const int row0 = blockIdx.y * 128;
    const int col0 = blockIdx.x * 64;
    __shared__ float sA[128][17];
    __shared__ float sB[64][17];
    const int tid = threadIdx.x;
    const int tx = tid & 15, ty = tid >> 4;
    float c[8][4] = {};

    const int ra = tid >> 1, ka = (tid & 1) * 8;
    const int rb = tid >> 2, kb = (tid & 3) * 4;

    for (int kc = 0; kc < Rn; kc += 16) {
        float4 av0 = *reinterpret_cast<const float4*>(G + (row0 + ra) * Rn + kc + ka);
        float4 av1 = *reinterpret_cast<const float4*>(G + (row0 + ra) * Rn + kc + ka + 4);
        float4 bv = *reinterpret_cast<const float4*>(W + (col0 + rb) * Rn + kc + kb);
        __syncthreads();
        sA[ra][ka] = av0.x; sA[ra][ka + 1] = av0.y; sA[ra][ka + 2] = av0.z; sA[ra][ka + 3] = av0.w;
        sA[ra][ka + 4] = av1.x; sA[ra][ka + 5] = av1.y; sA[ra][ka + 6] = av1.z; sA[ra][ka + 7] = av1.w;
        sB[rb][kb] = bv.x; sB[rb][kb + 1] = bv.y; sB[rb][kb + 2] = bv.z; sB[rb][kb + 3] = bv.w;
        __syncthreads();
        #pragma unroll
        for (int kk = 0; kk < 16; kk++) {
            float a[8], bb[4];
            #pragma unroll
            for (int i = 0; i < 8; i++) a[i] = sA[ty + 16 * i][kk];
            #pragma unroll
            for (int j = 0; j < 4; j++) bb[j] = sB[tx + 16 * j][kk];
            #pragma unroll
            for (int i = 0; i < 8; i++)
                #pragma unroll
                for (int j = 0; j < 4; j++) c[i][j] += a[i] * bb[j];
        }
    }
    #pragma unroll
    for (int i = 0; i < 8; i++) {
        const int r = row0 + ty + 16 * i;
        #pragma unroll
        for (int j = 0; j < 4; j++) {
            const int cc = col0 + tx + 16 * j;
            const float g = G[r * Rn + cc];
            const float s = 1.f / (1.f + __expf(-(c[i][j] + bias[cc])));
            outp[r * Rn + cc] = s * g;
        }
    }
}

// ---------------- K7: split-K partials of left @ right^T ----------------
__global__ __launch_bounds__(256) void k7_partial()
{
    const int z = blockIdx.z;
    const int b = z >> 2, ks = z & 3;
    const int kbase = ks * 192;
    const float* __restrict__ A = g_left + b * KPn * Rn;
    const float* __restrict__ Bm = g_right + b * KQn * Rn;
    const int row0 = blockIdx.y * 64;
    const int col0 = blockIdx.x * 64;
    __shared__ float sA[64][17];
    __shared__ float sB[64][17];
    const int tid = threadIdx.x;
    const int tx = tid & 15, ty = tid >> 4;
    float c[4][4] = {};

    for (int kc = kbase; kc < kbase + 192; kc += 16) {
        const int r = tid >> 2, k4 = (tid & 3) * 4;
        float4 av = *reinterpret_cast<const float4*>(A + (row0 + r) * Rn + kc + k4);
        float4 bv = *reinterpret_cast<const float4*>(Bm + (col0 + r) * Rn + kc + k4);
        __syncthreads();
        sA[r][k4] = av.x; sA[r][k4 + 1] = av.y; sA[r][k4 + 2] = av.z; sA[r][k4 + 3] = av.w;
        sB[r][k4] = bv.x; sB[r][k4 + 1] = bv.y; sB[r][k4 + 2] = bv.z; sB[r][k4 + 3] = bv.w;
        __syncthreads();
        #pragma unroll
        for (int kk = 0; kk < 16; kk++) {
            float a[4], bb[4];
            #pragma unroll
            for (int i = 0; i < 4; i++) a[i] = sA[ty + 16 * i][kk];
            #pragma unroll
            for (int j = 0; j < 4; j++) bb[j] = sB[tx + 16 * j][kk];
            #pragma unroll
            for (int i = 0; i < 4; i++)
                #pragma unroll
                for (int j = 0; j < 4; j++) c[i][j] += a[i] * bb[j];
        }
    }
    float* dst = g_part + ks * (BB * KPn * KQn) + b * (KPn * KQn);
    #pragma unroll
    for (int i = 0; i < 4; i++) {
        const int r = row0 + ty + 16 * i;
        #pragma unroll
        for (int j = 0; j < 4; j++) {
            const int cc = col0 + tx + 16 * j;
            dst[r * KQn + cc] = c[i][j];
        }
    }
}

// ---------------- K8: reduce split-K + relu ----------------
__global__ __launch_bounds__(256) void k8_reduce(float* __restrict__ outp)
{
    const int idx = blockIdx.x * 256 + threadIdx.x;
    const int n = BB * KPn * KQn;
    if (idx < n) {
        float s = (g_part[idx] + g_part[n + idx]) + (g_part[2 * n + idx] + g_part[3 * n + idx]);
        outp[idx] = fmaxf(s, 0.f);
    }
}

// ---------------- launch ----------------
extern "C" void kernel_launch(void* const* d_in, const int* in_sizes, int n_in,
                              void* d_out, int out_size)
{
    const float* Eq    = (const float*)d_in[0];
    const float* Ep    = (const float*)d_in[1];
    const float* mask  = (const float*)d_in[2];
    const float* W_in  = (const float*)d_in[3];
    const float* Wq    = (const float*)d_in[4];
    const float* bq    = (const float*)d_in[5];
    const float* Wk    = (const float*)d_in[6];
    const float* bk    = (const float*)d_in[7];
    const float* Wv    = (const float*)d_in[8];
    const float* bv    = (const float*)d_in[9];
    const float* Wo1   = (const float*)d_in[10];
    const float* bo1   = (const float*)d_in[11];
    const float* Wo2   = (const float*)d_in[12];
    const float* bo2   = (const float*)d_in[13];
    const float* W_out = (const float*)d_in[14];
    const float* Wl    = (const float*)d_in[15];
    const float* bl    = (const float*)d_in[16];
    const float* Wr    = (const float*)d_in[17];
    const float* br    = (const float*)d_in[18];
    float* outp = (float*)d_out;

    k0_rowproj<<<dim3(BB, 2, 4), dim3(32, 8)>>>(Eq, Ep, W_in, W_out);
    k0b_wv4<<<1, 32>>>(Wv, bv, W_out);
    k1_pair<<<dim3(BB, KPn), 192>>>(Eq, Ep, W_in, Wq, bq, Wk, bk, Wo1, bo1, Wo2, bo2);
    k2_attn_h<<<dim3(BB, KPn), 96>>>(mask);
    k3_attn_v<<<dim3(BB, KQn), 96>>>(mask);
    k4_U<<<dim3(3, 3, BB), 256>>>(Eq, Ep, W_out, mask);
    k5_rowsoft<<<dim3(BB, KPn), 256>>>(Eq, Ep);
    k5_colsoft<<<dim3(BB, KQn), 256>>>(Eq, Ep);
    k6_gate<<<dim3(12, 6, 2), 256>>>(Wl, bl, Wr, br);
    k7_partial<<<dim3(3, 3, 16), 256>>>();
    k8_reduce<<<dim3(576), 256>>>(outp);
}

// round 7
// speedup vs baseline: 2.5059x; 1.2279x over previous
#include <cuda_runtime.h>
#include <math.h>
#include <stdint.h>

#define BB 4
#define KQn 192
#define KPn 192
#define Hn 256
#define Tn 32
#define Rn 768
#define NEGV (-1e9f)
#define SCALEV (0.17677669529663687f)   // 1/sqrt(32)
#define SPAD 36                          // smem row stride (conflict-free frag loads)

// ---------------- scratch ----------------
static __device__ float g_A1[BB * KQn * Tn];
static __device__ float g_A2[BB * KPn * Tn];
static __device__ float g_u1[BB * KQn];
static __device__ float g_u2[BB * KPn];
static __device__ float g_fq[BB * KPn * KQn * Tn];
static __device__ float g_fk[BB * KPn * KQn * Tn]; // pre-scaled by obv*SCALE
static __device__ float g_vw[BB * KPn * KQn];      // fv . w4 per pair
static __device__ float g_wv4[Tn];                 // Wv^T @ w4
static __device__ float g_c0[1];                   // bv . w4
static __device__ float g_Umh[BB * KPn * KQn];
static __device__ float g_Um[BB * KPn * KQn];
static __device__ float g_U[BB * KPn * KQn];
static __device__ float g_Gl[BB * KPn * Rn];
static __device__ float g_Gr[BB * KQn * Rn];
static __device__ float g_left[BB * KPn * Rn];
static __device__ float g_right[BB * KQn * Rn];
static __device__ float g_part[4 * BB * KPn * KQn];

__device__ __forceinline__ float dot4(float4 a, float4 b) {
    return (a.x * b.x + a.y * b.y) + (a.z * b.z + a.w * b.w);
}

__device__ __forceinline__ uint32_t tf32cvt(float x) {
    uint32_t u;
    asm("cvt.rna.tf32.f32 %0, %1;" : "=r"(u) : "f"(x));
    return u;
}

__device__ __forceinline__ void mma_tf32(float c[4], const uint32_t a[4], uint32_t b0, uint32_t b1) {
    asm volatile("mma.sync.aligned.m16n8k8.row.col.f32.tf32.tf32.f32 "
        "{%0,%1,%2,%3}, {%4,%5,%6,%7}, {%8,%9}, {%0,%1,%2,%3};"
        : "+f"(c[0]), "+f"(c[1]), "+f"(c[2]), "+f"(c[3])
        : "r"(a[0]), "r"(a[1]), "r"(a[2]), "r"(a[3]), "r"(b0), "r"(b1));
}

// ---------------- K0: per-row projections A1/A2 and u1/u2 ----------------
__global__ __launch_bounds__(256) void k0_rowproj(
    const float* __restrict__ Eq, const float* __restrict__ Ep,
    const float* __restrict__ W_in, const float* __restrict__ W_out)
{
    const int b = blockIdx.x;
    const int side = blockIdx.y;
    const float* src = side ? (Ep + b * KPn * Hn) : (Eq + b * KQn * Hn);
    const int woff = side ? Hn : 0;
    float* A = side ? (g_A2 + b * KPn * Tn) : (g_A1 + b * KQn * Tn);
    float* u = side ? (g_u2 + b * KPn) : (g_u1 + b * KQn);

    __shared__ float sW[Tn][Hn + 1];
    __shared__ float swv[Hn];
    const int tid = threadIdx.y * 32 + threadIdx.x;
    for (int i = tid; i < Tn * Hn; i += 256) {
        int t = i >> 8, h = i & 255;
        sW[t][h] = W_in[t * Rn + woff + h];
    }
    for (int i = tid; i < Hn; i += 256) swv[i] = W_out[woff + i];
    __syncthreads();

    const int t = threadIdx.x;
    const int y0 = blockIdx.z * 48;
    for (int y = y0 + threadIdx.y; y < y0 + 48; y += 8) {
        const float* row = src + y * Hn;
        float p0 = 0.f, p1 = 0.f, p2 = 0.f, p3 = 0.f, up = 0.f;
        for (int h = 0; h < Hn; h += 4) {
            p0 += row[h] * sW[t][h];
            p1 += row[h + 1] * sW[t][h + 1];
            p2 += row[h + 2] * sW[t][h + 2];
            p3 += row[h + 3] * sW[t][h + 3];
        }
        for (int h = t; h < Hn; h += 32) up += row[h] * swv[h];
        #pragma unroll
        for (int o = 16; o; o >>= 1) up += __shfl_down_sync(0xffffffffu, up, o);
        A[y * Tn + t] = (p0 + p1) + (p2 + p3);
        if (t == 0) u[y] = up;
    }
}

// ---------------- K0b: wv4 = Wv^T @ w4, c0 = bv . w4 ----------------
__global__ void k0b_wv4(const float* __restrict__ Wv, const float* __restrict__ bv,
                        const float* __restrict__ W_out)
{
    const int t = threadIdx.x;
    float s = 0.f;
    for (int u = 0; u < Tn; u++) s += Wv[u * Tn + t] * W_out[Rn + u];
    g_wv4[t] = s;
    float c = bv[t] * W_out[Rn + t];
    #pragma unroll
    for (int o = 16; o; o >>= 1) c += __shfl_down_sync(0xffffffffu, c, o);
    if (t == 0) g_c0[0] = c;
}

// dst = (e1 @ W^T + bias) * scale
__device__ __forceinline__ void small_mm_store(const float* e1, const float* __restrict__ W,
                                               const float* __restrict__ bias, float scale,
                                               float* __restrict__ dst)
{
    float4* d = reinterpret_cast<float4*>(dst);
    #pragma unroll
    for (int u4 = 0; u4 < 8; u4++) {
        float r[4];
        #pragma unroll
        for (int uu = 0; uu < 4; uu++) {
            const int u = u4 * 4 + uu;
            float sa = bias[u], sb = 0.f;
            const float4* w4 = reinterpret_cast<const float4*>(W + u * Tn);
            #pragma unroll
            for (int t4 = 0; t4 < 4; t4++) {
                float4 w = w4[t4];
                sa += e1[t4 * 4 + 0] * w.x + e1[t4 * 4 + 1] * w.y
                    + e1[t4 * 4 + 2] * w.z + e1[t4 * 4 + 3] * w.w;
            }
            #pragma unroll
            for (int t4 = 4; t4 < 8; t4++) {
                float4 w = w4[t4];
                sb += e1[t4 * 4 + 0] * w.x + e1[t4 * 4 + 1] * w.y
                    + e1[t4 * 4 + 2] * w.z + e1[t4 * 4 + 3] * w.w;
            }
            r[uu] = (sa + sb) * scale;
        }
        d[u4] = make_float4(r[0], r[1], r[2], r[3]);
    }
}

// ---------------- K1: per (b,p): bilinear E1 + fq/fk(scaled) + vw ----------------
__global__ __launch_bounds__(192) void k1_pair(
    const float* __restrict__ Eq, const float* __restrict__ Ep,
    const float* __restrict__ W_in,
    const float* __restrict__ Wq, const float* __restrict__ bq,
    const float* __restrict__ Wk, const float* __restrict__ bk,
    const float* __restrict__ Wo1, const float* __restrict__ bo1,
    const float* __restrict__ Wo2, const float* __restrict__ bo2)
{
    const int b = blockIdx.x, p = blockIdx.y;
    __shared__ __align__(16) float sEp[Hn];
    __shared__ __align__(16) float sW3[Tn][Hn];
    __shared__ float sA2[Tn];
    __shared__ __align__(16) float swv4[Tn];
    const int tid = threadIdx.x;

    {
        const float4* eprow = reinterpret_cast<const float4*>(Ep + (b * KPn + p) * Hn);
        float4* sEp4w = reinterpret_cast<float4*>(sEp);
        for (int i = tid; i < Hn / 4; i += 192) sEp4w[i] = eprow[i];
        for (int i = tid; i < Tn; i += 192) { sA2[i] = g_A2[(b * KPn + p) * Tn + i]; swv4[i] = g_wv4[i]; }
        for (int i4 = tid; i4 < Tn * Hn / 4; i4 += 192) {
            int t = i4 >> 6, h4 = i4 & 63;
            reinterpret_cast<float4*>(&sW3[t][0])[h4] =
                reinterpret_cast<const float4*>(W_in + t * Rn + 2 * Hn)[h4];
        }
    }
    __syncthreads();

    const int q = tid;
    float acc[Tn];
    #pragma unroll
    for (int t = 0; t < Tn; t++) acc[t] = 0.f;

    const float4* eq4 = reinterpret_cast<const float4*>(Eq + (b * KQn + q) * Hn);
    const float4* sEp4 = reinterpret_cast<const float4*>(sEp);
    for (int h4 = 0; h4 < Hn / 4; h4++) {
        float4 e = eq4[h4];
        float4 pp = sEp4[h4];
        float4 ev = make_float4(e.x * pp.x, e.y * pp.y, e.z * pp.z, e.w * pp.w);
        #pragma unroll
        for (int t = 0; t < Tn; t++) {
            const float4 w = *reinterpret_cast<const float4*>(&sW3[t][h4 * 4]);
            acc[t] += ev.x * w.x + ev.y * w.y + ev.z * w.z + ev.w * w.w;
        }
    }
    {
        const float4* a1 = reinterpret_cast<const float4*>(g_A1 + (b * KQn + q) * Tn);
        #pragma unroll
        for (int t4 = 0; t4 < 8; t4++) {
            float4 a = a1[t4];
            acc[t4 * 4 + 0] += a.x + sA2[t4 * 4 + 0];
            acc[t4 * 4 + 1] += a.y + sA2[t4 * 4 + 1];
            acc[t4 * 4 + 2] += a.z + sA2[t4 * 4 + 2];
            acc[t4 * 4 + 3] += a.w + sA2[t4 * 4 + 3];
        }
    }

    float ob = bo2[0];
    #pragma unroll 4
    for (int u = 0; u < Tn; u++) {
        float sa = bo1[u], sb = 0.f;
        const float4* w4 = reinterpret_cast<const float4*>(Wo1 + u * Tn);
        #pragma unroll
        for (int t4 = 0; t4 < 4; t4++) {
            float4 w = w4[t4];
            sa += acc[t4 * 4 + 0] * w.x + acc[t4 * 4 + 1] * w.y
                + acc[t4 * 4 + 2] * w.z + acc[t4 * 4 + 3] * w.w;
        }
        #pragma unroll
        for (int t4 = 4; t4 < 8; t4++) {
            float4 w = w4[t4];
            sb += acc[t4 * 4 + 0] * w.x + acc[t4 * 4 + 1] * w.y
                + acc[t4 * 4 + 2] * w.z + acc[t4 * 4 + 3] * w.w;
        }
        ob += fmaxf(sa + sb, 0.f) * Wo2[u];
    }
    const float sc = SCALEV / (1.f + __expf(-ob));

    float va = 0.f, vb = 0.f;
    const float4* wv44 = reinterpret_cast<const float4*>(swv4);
    const float4* acc4 = reinterpret_cast<const float4*>(acc);
    #pragma unroll
    for (int t4 = 0; t4 < 4; t4++) va += dot4(acc4[t4], wv44[t4]);
    #pragma unroll
    for (int t4 = 4; t4 < 8; t4++) vb += dot4(acc4[t4], wv44[t4]);

    const int pairbase = (b * KPn + p) * KQn + q;
    g_vw[pairbase] = (va + vb) + g_c0[0];
    small_mm_store(acc, Wq, bq, 1.f, g_fq + pairbase * Tn);
    small_mm_store(acc, Wk, bk, sc,  g_fk + pairbase * Tn);
}

// ================= tensor-core attention core (shared by k2/k3) =================
// smem: sfq[192][SPAD] (tf32 bits), sfk[192][SPAD], sbv[192] float2{bias, vw}
// Each of 6 warps owns rows [wid*32, wid*32+32). Outputs s,t sums per row.
__device__ __forceinline__ void attn_mma_core(
    const uint32_t* __restrict__ sfq, const uint32_t* __restrict__ sfk,
    const float2* __restrict__ sbv, int tid, float sOut[4], float tOut[4], int rows[4])
{
    const int wid = tid >> 5, lane = tid & 31;
    const int g = lane >> 2, t4 = lane & 3;
    const int m0 = wid * 32;

    float s[4] = {0.f, 0.f, 0.f, 0.f}, tt[4] = {0.f, 0.f, 0.f, 0.f};

    for (int nc = 0; nc < 192; nc += 32) {
        float c[2][4][4];
        #pragma unroll
        for (int mt = 0; mt < 2; mt++)
            #pragma unroll
            for (int nt = 0; nt < 4; nt++)
                #pragma unroll
                for (int r = 0; r < 4; r++) c[mt][nt][r] = 0.f;

        #pragma unroll
        for (int ks = 0; ks < 4; ks++) {
            uint32_t a[2][4];
            #pragma unroll
            for (int mt = 0; mt < 2; mt++) {
                const int r = m0 + mt * 16;
                a[mt][0] = sfq[(r + g) * SPAD + ks * 8 + t4];
                a[mt][1] = sfq[(r + g + 8) * SPAD + ks * 8 + t4];
                a[mt][2] = sfq[(r + g) * SPAD + ks * 8 + t4 + 4];
                a[mt][3] = sfq[(r + g + 8) * SPAD + ks * 8 + t4 + 4];
            }
            #pragma unroll
            for (int nt = 0; nt < 4; nt++) {
                const uint32_t b0 = sfk[(nc + nt * 8 + g) * SPAD + ks * 8 + t4];
                const uint32_t b1 = sfk[(nc + nt * 8 + g) * SPAD + ks * 8 + t4 + 4];
                mma_tf32(c[0][nt], a[0], b0, b1);
                mma_tf32(c[1][nt], a[1], b0, b1);
            }
        }

        #pragma unroll
        for (int nt = 0; nt < 4; nt++) {
            const int col0 = nc + nt * 8 + 2 * t4;
            const float2 bv0 = sbv[col0];
            const float2 bv1 = sbv[col0 + 1];
            #pragma unroll
            for (int mt = 0; mt < 2; mt++) {
                const float e0 = __expf(c[mt][nt][0] + bv0.x);
                const float e1 = __expf(c[mt][nt][1] + bv1.x);
                const float e2 = __expf(c[mt][nt][2] + bv0.x);
                const float e3 = __expf(c[mt][nt][3] + bv1.x);
                s[mt * 2 + 0] += e0 + e1;
                tt[mt * 2 + 0] += e0 * bv0.y + e1 * bv1.y;
                s[mt * 2 + 1] += e2 + e3;
                tt[mt * 2 + 1] += e2 * bv0.y + e3 * bv1.y;
            }
        }
    }

    #pragma unroll
    for (int i = 0; i < 4; i++) {
        s[i] += __shfl_xor_sync(0xffffffffu, s[i], 1);
        s[i] += __shfl_xor_sync(0xffffffffu, s[i], 2);
        tt[i] += __shfl_xor_sync(0xffffffffu, tt[i], 1);
        tt[i] += __shfl_xor_sync(0xffffffffu, tt[i], 2);
        sOut[i] = s[i]; tOut[i] = tt[i];
    }
    rows[0] = m0 + g;
    rows[1] = m0 + g + 8;
    rows[2] = m0 + 16 + g;
    rows[3] = m0 + 24 + g;
}

// ---------------- K2: horizontal attention (tf32 mma) -> Umh ----------------
__global__ __launch_bounds__(192) void k2_attn_h(const float* __restrict__ mask)
{
    extern __shared__ uint32_t smem[];
    uint32_t* sfq = smem;
    uint32_t* sfk = sfq + 192 * SPAD;
    float2* sbv = reinterpret_cast<float2*>(sfk + 192 * SPAD);

    const int b = blockIdx.x, p = blockIdx.y;
    const int tid = threadIdx.x;
    const int base = (b * KPn + p) * KQn;

    const float4* fq4 = reinterpret_cast<const float4*>(g_fq + base * Tn);
    const float4* fk4 = reinterpret_cast<const float4*>(g_fk + base * Tn);
    for (int i = tid; i < 192 * 8; i += 192) {
        const int row = i >> 3, f4 = i & 7;
        float4 v = fq4[i];
        uint32_t* dq = sfq + row * SPAD + f4 * 4;
        dq[0] = tf32cvt(v.x); dq[1] = tf32cvt(v.y); dq[2] = tf32cvt(v.z); dq[3] = tf32cvt(v.w);
        float4 w = fk4[i];
        uint32_t* dk = sfk + row * SPAD + f4 * 4;
        dk[0] = tf32cvt(w.x); dk[1] = tf32cvt(w.y); dk[2] = tf32cvt(w.z); dk[3] = tf32cvt(w.w);
    }
    {
        const int i = tid;  // 192 threads, 192 cols
        sbv[i] = make_float2((mask[base + i] < 0.5f) ? NEGV : 0.f, g_vw[base + i]);
    }
    __syncthreads();

    float s[4], t[4]; int rows[4];
    attn_mma_core(sfq, sfk, sbv, tid, s, t, rows);

    if ((tid & 3) == 0) {
        #pragma unroll
        for (int i = 0; i < 4; i++) g_Umh[base + rows[i]] = t[i] / s[i];
    }
}

// ---------------- K3: vertical attention (tf32 mma) -> Um ----------------
__global__ __launch_bounds__(192) void k3_attn_v(const float* __restrict__ mask)
{
    extern __shared__ uint32_t smem[];
    uint32_t* sfq = smem;
    uint32_t* sfk = sfq + 192 * SPAD;
    float2* sbv = reinterpret_cast<float2*>(sfk + 192 * SPAD);

    const int b = blockIdx.x, q = blockIdx.y;
    const int tid = threadIdx.x;

    const float4* fqg = reinterpret_cast<const float4*>(g_fq);
    const float4* fkg = reinterpret_cast<const float4*>(g_fk);
    for (int i = tid; i < 192 * 8; i += 192) {
        const int row = i >> 3, f4 = i & 7;
        const int gidx = ((b * KPn + row) * KQn + q) * 8 + f4;
        float4 v = fqg[gidx];
        uint32_t* dq = sfq + row * SPAD + f4 * 4;
        dq[0] = tf32cvt(v.x); dq[1] = tf32cvt(v.y); dq[2] = tf32cvt(v.z); dq[3] = tf32cvt(v.w);
        float4 w = fkg[gidx];
        uint32_t* dk = sfk + row * SPAD + f4 * 4;
        dk[0] = tf32cvt(w.x); dk[1] = tf32cvt(w.y); dk[2] = tf32cvt(w.z); dk[3] = tf32cvt(w.w);
    }
    {
        const int i = tid;
        const int idx = (b * KPn + i) * KQn + q;
        sbv[i] = make_float2((mask[idx] < 0.5f) ? NEGV : 0.f, g_vw[idx]);
    }
    __syncthreads();

    float s[4], t[4]; int rows[4];
    attn_mma_core(sfq, sfk, sbv, tid, s, t, rows);

    if ((tid & 3) == 0) {
        #pragma unroll
        for (int i = 0; i < 4; i++) {
            const int idx = (b * KPn + rows[i]) * KQn + q;
            g_Um[idx] = g_Umh[idx] + t[i] / s[i];
        }
    }
}

// ---------------- K4: U = Ep @ (Eq.w3)^T + u1 + u2 + Um, masked ----------------
__global__ __launch_bounds__(256) void k4_U(
    const float* __restrict__ Eq, const float* __restrict__ Ep,
    const float* __restrict__ W_out, const float* __restrict__ mask)
{
    const int b = blockIdx.z;
    const int row0 = blockIdx.y * 64;
    const int col0 = blockIdx.x * 64;
    __shared__ float sA[64][17];
    __shared__ float sB[64][17];
    __shared__ float sw3[Hn];
    const int tid = threadIdx.x;
    const int tx = tid & 15, ty = tid >> 4;
    const int r = tid >> 2, k4i = (tid & 3) * 4;
    float c[4][4] = {};

    for (int i = tid; i < Hn; i += 256) sw3[i] = W_out[2 * Hn + i];
    __syncthreads();

    for (int kc = 0; kc < Hn; kc += 16) {
        float4 av = *reinterpret_cast<const float4*>(Ep + (b * KPn + row0 + r) * Hn + kc + k4i);
        float4 bv = *reinterpret_cast<const float4*>(Eq + (b * KQn + col0 + r) * Hn + kc + k4i);
        bv.x *= sw3[kc + k4i]; bv.y *= sw3[kc + k4i + 1];
        bv.z *= sw3[kc + k4i + 2]; bv.w *= sw3[kc + k4i + 3];
        __syncthreads();
        sA[r][k4i] = av.x; sA[r][k4i + 1] = av.y; sA[r][k4i + 2] = av.z; sA[r][k4i + 3] = av.w;
        sB[r][k4i] = bv.x; sB[r][k4i + 1] = bv.y; sB[r][k4i + 2] = bv.z; sB[r][k4i + 3] = bv.w;
        __syncthreads();
        #pragma unroll
        for (int kk = 0; kk < 16; kk++) {
            float a[4], bb[4];
            #pragma unroll
            for (int i = 0; i < 4; i++) a[i] = sA[ty + 16 * i][kk];
            #pragma unroll
            for (int j = 0; j < 4; j++) bb[j] = sB[tx + 16 * j][kk];
            #pragma unroll
            for (int i = 0; i < 4; i++)
                #pragma unroll
                for (int j = 0; j < 4; j++) c[i][j] += a[i] * bb[j];
        }
    }
    #pragma unroll
    for (int i = 0; i < 4; i++) {
        const int rr = row0 + ty + 16 * i;
        #pragma unroll
        for (int j = 0; j < 4; j++) {
            const int cc = col0 + tx + 16 * j;
            const int idx = (b * KPn + rr) * KQn + cc;
            float Uv = c[i][j] + g_u1[b * KQn + cc] + g_u2[b * KPn + rr] + g_Um[idx];
            if (mask[idx] < 0.5f) Uv = NEGV;
            g_U[idx] = Uv;
        }
    }
}

// ---------------- K5a: softmax over q -> A''_p, build G_left ----------------
__global__ __launch_bounds__(256) void k5_rowsoft(const float* __restrict__ Eq, const float* __restrict__ Ep)
{
    const int b = blockIdx.x, p = blockIdx.y;
    __shared__ float sw[KQn];
    __shared__ float red[256];
    const int tid = threadIdx.x;
    const int base = (b * KPn + p) * KQn;

    float v = (tid < KQn) ? g_U[base + tid] : -3.4e38f;
    red[tid] = v; __syncthreads();
    for (int o = 128; o; o >>= 1) { if (tid < o) red[tid] = fmaxf(red[tid], red[tid + o]); __syncthreads(); }
    const float m = red[0]; __syncthreads();
    const float e = (tid < KQn) ? __expf(v - m) : 0.f;
    red[tid] = e; __syncthreads();
    for (int o = 128; o; o >>= 1) { if (tid < o) red[tid] += red[tid + o]; __syncthreads(); }
    const float inv = 1.f / red[0];
    if (tid < KQn) sw[tid] = e * inv;
    __syncthreads();

    const int h = tid;
    float a0 = 0.f, a1 = 0.f;
    for (int k = 0; k < KQn; k += 2) {
        a0 += sw[k] * Eq[(b * KQn + k) * Hn + h];
        a1 += sw[k + 1] * Eq[(b * KQn + k + 1) * Hn + h];
    }
    const float a = a0 + a1;
    const float ep = Ep[(b * KPn + p) * Hn + h];
    float* G = g_Gl + (b * KPn + p) * Rn;
    G[h] = ep; G[Hn + h] = a; G[2 * Hn + h] = ep * a;
}

// ---------------- K5b: softmax over p -> B''_p, build G_right ----------------
__global__ __launch_bounds__(256) void k5_colsoft(const float* __restrict__ Eq, const float* __restrict__ Ep)
{
    const int b = blockIdx.x, q = blockIdx.y;
    __shared__ float sw[KPn];
    __shared__ float red[256];
    const int tid = threadIdx.x;

    float v = (tid < KPn) ? g_U[(b * KPn + tid) * KQn + q] : -3.4e38f;
    red[tid] = v; __syncthreads();
    for (int o = 128; o; o >>= 1) { if (tid < o) red[tid] = fmaxf(red[tid], red[tid + o]); __syncthreads(); }
    const float m = red[0]; __syncthreads();
    const float e = (tid < KPn) ? __expf(v - m) : 0.f;
    red[tid] = e; __syncthreads();
    for (int o = 128; o; o >>= 1) { if (tid < o) red[tid] += red[tid + o]; __syncthreads(); }
    const float inv = 1.f / red[0];
    if (tid < KPn) sw[tid] = e * inv;
    __syncthreads();

    const int h = tid;
    float a0 = 0.f, a1 = 0.f;
    for (int k = 0; k < KPn; k += 2) {
        a0 += sw[k] * Ep[(b * KPn + k) * Hn + h];
        a1 += sw[k + 1] * Ep[(b * KPn + k + 1) * Hn + h];
    }
    const float a = a0 + a1;
    const float eq = Eq[(b * KQn + q) * Hn + h];
    float* G = g_Gr + (b * KQn + q) * Rn;
    G[h] = eq; G[Hn + h] = a; G[2 * Hn + h] = eq * a;
}

// ---------------- K6: gates, 128x64 tile, 8x4 per thread ----------------
__global__ __launch_bounds__(256) void k6_gate(
    const float* __restrict__ Wl, const float* __restrict__ bl,
    const float* __restrict__ Wr, const float* __restrict__ br)
{
    const int side = blockIdx.z;
    const float* __restrict__ G = side ? g_Gr : g_Gl;
    const float* __restrict__ W = side ? Wr : Wl;
    const float* __restrict__ bias = side ? br : bl;
    float* __restrict__ outp = side ? g_right : g_left;
    const int row0 = blockIdx.y * 128;
    const int col0 = blockIdx.x * 64;
    __shared__ float sA[128][17];
    __shared__ float sB[64][17];
    const int tid = threadIdx.x;
    const int tx = tid & 15, ty = tid >> 4;
    float c[8][4] = {};

    const int ra = tid >> 1, ka = (tid & 1) * 8;
    const int rb = tid >> 2, kb = (tid & 3) * 4;

    for (int kc = 0; kc < Rn; kc += 16) {
        float4 av0 = *reinterpret_cast<const float4*>(G + (row0 + ra) * Rn + kc + ka);
        float4 av1 = *reinterpret_cast<const float4*>(G + (row0 + ra) * Rn + kc + ka + 4);
        float4 bv = *reinterpret_cast<const float4*>(W + (col0 + rb) * Rn + kc + kb);
        __syncthreads();
        sA[ra][ka] = av0.x; sA[ra][ka + 1] = av0.y; sA[ra][ka + 2] = av0.z; sA[ra][ka + 3] = av0.w;
        sA[ra][ka + 4] = av1.x; sA[ra][ka + 5] = av1.y; sA[ra][ka + 6] = av1.z; sA[ra][ka + 7] = av1.w;
        sB[rb][kb] = bv.x; sB[rb][kb + 1] = bv.y; sB[rb][kb + 2] = bv.z; sB[rb][kb + 3] = bv.w;
        __syncthreads();
        #pragma unroll
        for (int kk = 0; kk < 16; kk++) {
            float a[8], bb[4];
            #pragma unroll
            for (int i = 0; i < 8; i++) a[i] = sA[ty + 16 * i][kk];
            #pragma unroll
            for (int j = 0; j < 4; j++) bb[j] = sB[tx + 16 * j][kk];
            #pragma unroll
            for (int i = 0; i < 8; i++)
                #pragma unroll
                for (int j = 0; j < 4; j++) c[i][j] += a[i] * bb[j];
        }
    }
    #pragma unroll
    for (int i = 0; i < 8; i++) {
        const int r = row0 + ty + 16 * i;
        #pragma unroll
        for (int j = 0; j < 4; j++) {
            const int cc = col0 + tx + 16 * j;
            const float g = G[r * Rn + cc];
            const float s = 1.f / (1.f + __expf(-(c[i][j] + bias[cc])));
            outp[r * Rn + cc] = s * g;
        }
    }
}

// ---------------- K7: split-K partials of left @ right^T ----------------
__global__ __launch_bounds__(256) void k7_partial()
{
    const int z = blockIdx.z;
    const int b = z >> 2, ks = z & 3;
    const int kbase = ks * 192;
    const float* __restrict__ A = g_left + b * KPn * Rn;
    const float* __restrict__ Bm = g_right + b * KQn * Rn;
    const int row0 = blockIdx.y * 64;
    const int col0 = blockIdx.x * 64;
    __shared__ float sA[64][17];
    __shared__ float sB[64][17];
    const int tid = threadIdx.x;
    const int tx = tid & 15, ty = tid >> 4;
    float c[4][4] = {};

    for (int kc = kbase; kc < kbase + 192; kc += 16) {
        const int r = tid >> 2, k4 = (tid & 3) * 4;
        float4 av = *reinterpret_cast<const float4*>(A + (row0 + r) * Rn + kc + k4);
        float4 bv = *reinterpret_cast<const float4*>(Bm + (col0 + r) * Rn + kc + k4);
        __syncthreads();
        sA[r][k4] = av.x; sA[r][k4 + 1] = av.y; sA[r][k4 + 2] = av.z; sA[r][k4 + 3] = av.w;
        sB[r][k4] = bv.x; sB[r][k4 + 1] = bv.y; sB[r][k4 + 2] = bv.z; sB[r][k4 + 3] = bv.w;
        __syncthreads();
        #pragma unroll
        for (int kk = 0; kk < 16; kk++) {
            float a[4], bb[4];
            #pragma unroll
            for (int i = 0; i < 4; i++) a[i] = sA[ty + 16 * i][kk];
            #pragma unroll
            for (int j = 0; j < 4; j++) bb[j] = sB[tx + 16 * j][kk];
            #pragma unroll
            for (int i = 0; i < 4; i++)
                #pragma unroll
                for (int j = 0; j < 4; j++) c[i][j] += a[i] * bb[j];
        }
    }
    float* dst = g_part + ks * (BB * KPn * KQn) + b * (KPn * KQn);
    #pragma unroll
    for (int i = 0; i < 4; i++) {
        const int r = row0 + ty + 16 * i;
        #pragma unroll
        for (int j = 0; j < 4; j++) {
            const int cc = col0 + tx + 16 * j;
            dst[r * KQn + cc] = c[i][j];
        }
    }
}

// ---------------- K8: reduce split-K + relu ----------------
__global__ __launch_bounds__(256) void k8_reduce(float* __restrict__ outp)
{
    const int idx = blockIdx.x * 256 + threadIdx.x;
    const int n = BB * KPn * KQn;
    if (idx < n) {
        float s = (g_part[idx] + g_part[n + idx]) + (g_part[2 * n + idx] + g_part[3 * n + idx]);
        outp[idx] = fmaxf(s, 0.f);
    }
}

// ---------------- launch ----------------
extern "C" void kernel_launch(void* const* d_in, const int* in_sizes, int n_in,
                              void* d_out, int out_size)
{
    const float* Eq    = (const float*)d_in[0];
    const float* Ep    = (const float*)d_in[1];
    const float* mask  = (const float*)d_in[2];
    const float* W_in  = (const float*)d_in[3];
    const float* Wq    = (const float*)d_in[4];
    const float* bq    = (const float*)d_in[5];
    const float* Wk    = (const float*)d_in[6];
    const float* bk    = (const float*)d_in[7];
    const float* Wv    = (const float*)d_in[8];
    const float* bv    = (const float*)d_in[9];
    const float* Wo1   = (const float*)d_in[10];
    const float* bo1   = (const float*)d_in[11];
    const float* Wo2   = (const float*)d_in[12];
    const float* bo2   = (const float*)d_in[13];
    const float* W_out = (const float*)d_in[14];
    const float* Wl    = (const float*)d_in[15];
    const float* bl    = (const float*)d_in[16];
    const float* Wr    = (const float*)d_in[17];
    const float* br    = (const float*)d_in[18];
    float* outp = (float*)d_out;

    const int smemAttn = 2 * 192 * SPAD * 4 + 192 * 8;   // 56832 B
    cudaFuncSetAttribute(k2_attn_h, cudaFuncAttributeMaxDynamicSharedMemorySize, smemAttn);
    cudaFuncSetAttribute(k3_attn_v, cudaFuncAttributeMaxDynamicSharedMemorySize, smemAttn);

    k0_rowproj<<<dim3(BB, 2, 4), dim3(32, 8)>>>(Eq, Ep, W_in, W_out);
    k0b_wv4<<<1, 32>>>(Wv, bv, W_out);
    k1_pair<<<dim3(BB, KPn), 192>>>(Eq, Ep, W_in, Wq, bq, Wk, bk, Wo1, bo1, Wo2, bo2);
    k2_attn_h<<<dim3(BB, KPn), 192, smemAttn>>>(mask);
    k3_attn_v<<<dim3(BB, KQn), 192, smemAttn>>>(mask);
    k4_U<<<dim3(3, 3, BB), 256>>>(Eq, Ep, W_out, mask);
    k5_rowsoft<<<dim3(BB, KPn), 256>>>(Eq, Ep);
    k5_colsoft<<<dim3(BB, KQn), 256>>>(Eq, Ep);
    k6_gate<<<dim3(12, 6, 2), 256>>>(Wl, bl, Wr, br);
    k7_partial<<<dim3(3, 3, 16), 256>>>();
    k8_reduce<<<dim3(576), 256>>>(outp);
}

// round 8
// speedup vs baseline: 3.5108x; 1.4010x over previous
#include <cuda_runtime.h>
#include <math.h>
#include <stdint.h>

#define BB 4
#define KQn 192
#define KPn 192
#define Hn 256
#define Tn 32
#define Rn 768
#define NEGV (-1e9f)
#define SCALEV (0.17677669529663687f)   // 1/sqrt(32)
#define SPAD 36                          // smem row stride (conflict-free frag loads)

// ---------------- scratch ----------------
static __device__ float g_A1[BB * KQn * Tn];
static __device__ float g_A2[BB * KPn * Tn];
static __device__ float g_u1[BB * KQn];
static __device__ float g_u2[BB * KPn];
static __device__ float g_fq[BB * KPn * KQn * Tn];
static __device__ float g_fk[BB * KPn * KQn * Tn]; // pre-scaled by obv*SCALE
static __device__ float g_vw[BB * KPn * KQn];      // fv . w4 per pair
static __device__ float g_wv4[Tn];                 // Wv^T @ w4
static __device__ float g_c0[1];                   // bv . w4
static __device__ float g_Umh[BB * KPn * KQn];
static __device__ float g_Um[BB * KPn * KQn];
static __device__ float g_U[BB * KPn * KQn];
static __device__ float g_Gl[BB * KPn * Rn];
static __device__ float g_Gr[BB * KQn * Rn];
static __device__ float g_left[BB * KPn * Rn];
static __device__ float g_right[BB * KQn * Rn];
static __device__ float g_part[4 * BB * KPn * KQn];

__device__ __forceinline__ float dot4(float4 a, float4 b) {
    return (a.x * b.x + a.y * b.y) + (a.z * b.z + a.w * b.w);
}

__device__ __forceinline__ uint32_t tf32cvt(float x) {
    uint32_t u;
    asm("cvt.rna.tf32.f32 %0, %1;" : "=r"(u) : "f"(x));
    return u;
}

__device__ __forceinline__ void mma_tf32(float c[4], const uint32_t a[4], uint32_t b0, uint32_t b1) {
    asm volatile("mma.sync.aligned.m16n8k8.row.col.f32.tf32.tf32.f32 "
        "{%0,%1,%2,%3}, {%4,%5,%6,%7}, {%8,%9}, {%0,%1,%2,%3};"
        : "+f"(c[0]), "+f"(c[1]), "+f"(c[2]), "+f"(c[3])
        : "r"(a[0]), "r"(a[1]), "r"(a[2]), "r"(a[3]), "r"(b0), "r"(b1));
}

// ---------------- K0: per-row projections A1/A2 and u1/u2 ----------------
__global__ __launch_bounds__(256) void k0_rowproj(
    const float* __restrict__ Eq, const float* __restrict__ Ep,
    const float* __restrict__ W_in, const float* __restrict__ W_out)
{
    const int b = blockIdx.x;
    const int side = blockIdx.y;
    const float* src = side ? (Ep + b * KPn * Hn) : (Eq + b * KQn * Hn);
    const int woff = side ? Hn : 0;
    float* A = side ? (g_A2 + b * KPn * Tn) : (g_A1 + b * KQn * Tn);
    float* u = side ? (g_u2 + b * KPn) : (g_u1 + b * KQn);

    __shared__ float sW[Tn][Hn + 1];
    __shared__ float swv[Hn];
    const int tid = threadIdx.y * 32 + threadIdx.x;
    for (int i = tid; i < Tn * Hn; i += 256) {
        int t = i >> 8, h = i & 255;
        sW[t][h] = W_in[t * Rn + woff + h];
    }
    for (int i = tid; i < Hn; i += 256) swv[i] = W_out[woff + i];
    __syncthreads();

    const int t = threadIdx.x;
    const int y0 = blockIdx.z * 48;
    for (int y = y0 + threadIdx.y; y < y0 + 48; y += 8) {
        const float* row = src + y * Hn;
        float p0 = 0.f, p1 = 0.f, p2 = 0.f, p3 = 0.f, up = 0.f;
        for (int h = 0; h < Hn; h += 4) {
            p0 += row[h] * sW[t][h];
            p1 += row[h + 1] * sW[t][h + 1];
            p2 += row[h + 2] * sW[t][h + 2];
            p3 += row[h + 3] * sW[t][h + 3];
        }
        for (int h = t; h < Hn; h += 32) up += row[h] * swv[h];
        #pragma unroll
        for (int o = 16; o; o >>= 1) up += __shfl_down_sync(0xffffffffu, up, o);
        A[y * Tn + t] = (p0 + p1) + (p2 + p3);
        if (t == 0) u[y] = up;
    }
}

// ---------------- K0b: wv4 = Wv^T @ w4, c0 = bv . w4 ----------------
__global__ void k0b_wv4(const float* __restrict__ Wv, const float* __restrict__ bv,
                        const float* __restrict__ W_out)
{
    const int t = threadIdx.x;
    float s = 0.f;
    for (int u = 0; u < Tn; u++) s += Wv[u * Tn + t] * W_out[Rn + u];
    g_wv4[t] = s;
    float c = bv[t] * W_out[Rn + t];
    #pragma unroll
    for (int o = 16; o; o >>= 1) c += __shfl_down_sync(0xffffffffu, c, o);
    if (t == 0) g_c0[0] = c;
}

// dst = (e1 @ W^T + bias) * scale
__device__ __forceinline__ void small_mm_store(const float* e1, const float* __restrict__ W,
                                               const float* __restrict__ bias, float scale,
                                               float* __restrict__ dst)
{
    float4* d = reinterpret_cast<float4*>(dst);
    #pragma unroll
    for (int u4 = 0; u4 < 8; u4++) {
        float r[4];
        #pragma unroll
        for (int uu = 0; uu < 4; uu++) {
            const int u = u4 * 4 + uu;
            float sa = bias[u], sb = 0.f;
            const float4* w4 = reinterpret_cast<const float4*>(W + u * Tn);
            #pragma unroll
            for (int t4 = 0; t4 < 4; t4++) {
                float4 w = w4[t4];
                sa += e1[t4 * 4 + 0] * w.x + e1[t4 * 4 + 1] * w.y
                    + e1[t4 * 4 + 2] * w.z + e1[t4 * 4 + 3] * w.w;
            }
            #pragma unroll
            for (int t4 = 4; t4 < 8; t4++) {
                float4 w = w4[t4];
                sb += e1[t4 * 4 + 0] * w.x + e1[t4 * 4 + 1] * w.y
                    + e1[t4 * 4 + 2] * w.z + e1[t4 * 4 + 3] * w.w;
            }
            r[uu] = (sa + sb) * scale;
        }
        d[u4] = make_float4(r[0], r[1], r[2], r[3]);
    }
}

// ---------------- K1: per (b,p): bilinear via tf32 MMA + scalar epilogue ----------------
// smem: sW3[32][260] tf32, sA[192][36] tf32 (reused as fp32 sE1), sEpRow[256], sA2[32], swv4[32]
__global__ __launch_bounds__(192) void k1_pair(
    const float* __restrict__ Eq, const float* __restrict__ Ep,
    const float* __restrict__ W_in,
    const float* __restrict__ Wq, const float* __restrict__ bq,
    const float* __restrict__ Wk, const float* __restrict__ bk,
    const float* __restrict__ Wo1, const float* __restrict__ bo1,
    const float* __restrict__ Wo2, const float* __restrict__ bo2)
{
    extern __shared__ uint32_t smem[];
    uint32_t* sW3 = smem;                                   // 32*260
    uint32_t* sA = sW3 + 32 * 260;                          // 192*36
    float* sE1 = reinterpret_cast<float*>(sA);              // reuse after MMA
    float* sEpRow = reinterpret_cast<float*>(sA + 192 * 36);
    float* sA2 = sEpRow + Hn;
    float* swv4 = sA2 + Tn;

    const int b = blockIdx.x, p = blockIdx.y;
    const int tid = threadIdx.x;
    const int wid = tid >> 5, lane = tid & 31, g = lane >> 2, t4 = lane & 3;

    // stage W3 (tf32), Ep row, A2, wv4
    for (int i = tid; i < 32 * 64; i += 192) {   // float4 units of W3
        const int t = i >> 6, h4 = i & 63;
        float4 w = reinterpret_cast<const float4*>(W_in + t * Rn + 2 * Hn)[h4];
        uint32_t* d = sW3 + t * 260 + h4 * 4;
        d[0] = tf32cvt(w.x); d[1] = tf32cvt(w.y); d[2] = tf32cvt(w.z); d[3] = tf32cvt(w.w);
    }
    for (int i = tid; i < Hn / 4; i += 192)
        reinterpret_cast<float4*>(sEpRow)[i] =
            reinterpret_cast<const float4*>(Ep + (b * KPn + p) * Hn)[i];
    if (tid < Tn) { sA2[tid] = g_A2[(b * KPn + p) * Tn + tid]; swv4[tid] = g_wv4[tid]; }
    __syncthreads();

    float c[2][4][4] = {};
    const int m0 = wid * 32;
    const float4* eqrow = reinterpret_cast<const float4*>(Eq + (b * KQn + tid) * Hn);
    const float4* sEpRow4 = reinterpret_cast<const float4*>(sEpRow);

    for (int kc = 0; kc < 8; kc++) {
        // build A chunk: (Eq[q,:] * Ep[p,:]) tf32 for h in [kc*32, kc*32+32)
        #pragma unroll
        for (int j = 0; j < 8; j++) {
            float4 e = eqrow[kc * 8 + j];
            float4 pp = sEpRow4[kc * 8 + j];
            uint32_t* d = sA + tid * 36 + j * 4;
            d[0] = tf32cvt(e.x * pp.x); d[1] = tf32cvt(e.y * pp.y);
            d[2] = tf32cvt(e.z * pp.z); d[3] = tf32cvt(e.w * pp.w);
        }
        __syncthreads();
        #pragma unroll
        for (int ks = 0; ks < 4; ks++) {
            uint32_t a[2][4];
            #pragma unroll
            for (int mt = 0; mt < 2; mt++) {
                const int r = m0 + mt * 16;
                a[mt][0] = sA[(r + g) * 36 + ks * 8 + t4];
                a[mt][1] = sA[(r + g + 8) * 36 + ks * 8 + t4];
                a[mt][2] = sA[(r + g) * 36 + ks * 8 + t4 + 4];
                a[mt][3] = sA[(r + g + 8) * 36 + ks * 8 + t4 + 4];
            }
            #pragma unroll
            for (int nt = 0; nt < 4; nt++) {
                const uint32_t b0 = sW3[(nt * 8 + g) * 260 + kc * 32 + ks * 8 + t4];
                const uint32_t b1 = sW3[(nt * 8 + g) * 260 + kc * 32 + ks * 8 + t4 + 4];
                mma_tf32(c[0][nt], a[0], b0, b1);
                mma_tf32(c[1][nt], a[1], b0, b1);
            }
        }
        __syncthreads();
    }

    // spill C (bilinear part of E1) to smem as fp32
    #pragma unroll
    for (int mt = 0; mt < 2; mt++)
        #pragma unroll
        for (int nt = 0; nt < 4; nt++) {
            const int r0 = m0 + mt * 16 + g;
            const int col = nt * 8 + 2 * t4;
            sE1[r0 * 36 + col] = c[mt][nt][0];
            sE1[r0 * 36 + col + 1] = c[mt][nt][1];
            sE1[(r0 + 8) * 36 + col] = c[mt][nt][2];
            sE1[(r0 + 8) * 36 + col + 1] = c[mt][nt][3];
        }
    __syncthreads();

    // scalar epilogue: q = tid
    const int q = tid;
    float acc[Tn];
    {
        const float4* a1 = reinterpret_cast<const float4*>(g_A1 + (b * KQn + q) * Tn);
        #pragma unroll
        for (int i4 = 0; i4 < 8; i4++) {
            float4 ev = *reinterpret_cast<const float4*>(&sE1[q * 36 + i4 * 4]);
            float4 a = a1[i4];
            acc[i4 * 4 + 0] = ev.x + a.x + sA2[i4 * 4 + 0];
            acc[i4 * 4 + 1] = ev.y + a.y + sA2[i4 * 4 + 1];
            acc[i4 * 4 + 2] = ev.z + a.z + sA2[i4 * 4 + 2];
            acc[i4 * 4 + 3] = ev.w + a.w + sA2[i4 * 4 + 3];
        }
    }

    float ob = bo2[0];
    #pragma unroll 4
    for (int u = 0; u < Tn; u++) {
        float sa = bo1[u], sb = 0.f;
        const float4* w4 = reinterpret_cast<const float4*>(Wo1 + u * Tn);
        #pragma unroll
        for (int t4i = 0; t4i < 4; t4i++) {
            float4 w = w4[t4i];
            sa += acc[t4i * 4 + 0] * w.x + acc[t4i * 4 + 1] * w.y
                + acc[t4i * 4 + 2] * w.z + acc[t4i * 4 + 3] * w.w;
        }
        #pragma unroll
        for (int t4i = 4; t4i < 8; t4i++) {
            float4 w = w4[t4i];
            sb += acc[t4i * 4 + 0] * w.x + acc[t4i * 4 + 1] * w.y
                + acc[t4i * 4 + 2] * w.z + acc[t4i * 4 + 3] * w.w;
        }
        ob += fmaxf(sa + sb, 0.f) * Wo2[u];
    }
    const float sc = SCALEV / (1.f + __expf(-ob));

    float va = 0.f, vb = 0.f;
    const float4* wv44 = reinterpret_cast<const float4*>(swv4);
    const float4* acc4 = reinterpret_cast<const float4*>(acc);
    #pragma unroll
    for (int t4i = 0; t4i < 4; t4i++) va += dot4(acc4[t4i], wv44[t4i]);
    #pragma unroll
    for (int t4i = 4; t4i < 8; t4i++) vb += dot4(acc4[t4i], wv44[t4i]);

    const int pairbase = (b * KPn + p) * KQn + q;
    g_vw[pairbase] = (va + vb) + g_c0[0];
    small_mm_store(acc, Wq, bq, 1.f, g_fq + pairbase * Tn);
    small_mm_store(acc, Wk, bk, sc,  g_fk + pairbase * Tn);
}

// ================= tensor-core attention core (shared by k2/k3) =================
__device__ __forceinline__ void attn_mma_core(
    const uint32_t* __restrict__ sfq, const uint32_t* __restrict__ sfk,
    const float2* __restrict__ sbv, int tid, float sOut[4], float tOut[4], int rows[4])
{
    const int wid = tid >> 5, lane = tid & 31;
    const int g = lane >> 2, t4 = lane & 3;
    const int m0 = wid * 32;

    float s[4] = {0.f, 0.f, 0.f, 0.f}, tt[4] = {0.f, 0.f, 0.f, 0.f};

    for (int nc = 0; nc < 192; nc += 32) {
        float c[2][4][4];
        #pragma unroll
        for (int mt = 0; mt < 2; mt++)
            #pragma unroll
            for (int nt = 0; nt < 4; nt++)
                #pragma unroll
                for (int r = 0; r < 4; r++) c[mt][nt][r] = 0.f;

        #pragma unroll
        for (int ks = 0; ks < 4; ks++) {
            uint32_t a[2][4];
            #pragma unroll
            for (int mt = 0; mt < 2; mt++) {
                const int r = m0 + mt * 16;
                a[mt][0] = sfq[(r + g) * SPAD + ks * 8 + t4];
                a[mt][1] = sfq[(r + g + 8) * SPAD + ks * 8 + t4];
                a[mt][2] = sfq[(r + g) * SPAD + ks * 8 + t4 + 4];
                a[mt][3] = sfq[(r + g + 8) * SPAD + ks * 8 + t4 + 4];
            }
            #pragma unroll
            for (int nt = 0; nt < 4; nt++) {
                const uint32_t b0 = sfk[(nc + nt * 8 + g) * SPAD + ks * 8 + t4];
                const uint32_t b1 = sfk[(nc + nt * 8 + g) * SPAD + ks * 8 + t4 + 4];
                mma_tf32(c[0][nt], a[0], b0, b1);
                mma_tf32(c[1][nt], a[1], b0, b1);
            }
        }

        #pragma unroll
        for (int nt = 0; nt < 4; nt++) {
            const int col0 = nc + nt * 8 + 2 * t4;
            const float2 bv0 = sbv[col0];
            const float2 bv1 = sbv[col0 + 1];
            #pragma unroll
            for (int mt = 0; mt < 2; mt++) {
                const float e0 = __expf(c[mt][nt][0] + bv0.x);
                const float e1 = __expf(c[mt][nt][1] + bv1.x);
                const float e2 = __expf(c[mt][nt][2] + bv0.x);
                const float e3 = __expf(c[mt][nt][3] + bv1.x);
                s[mt * 2 + 0] += e0 + e1;
                tt[mt * 2 + 0] += e0 * bv0.y + e1 * bv1.y;
                s[mt * 2 + 1] += e2 + e3;
                tt[mt * 2 + 1] += e2 * bv0.y + e3 * bv1.y;
            }
        }
    }

    #pragma unroll
    for (int i = 0; i < 4; i++) {
        s[i] += __shfl_xor_sync(0xffffffffu, s[i], 1);
        s[i] += __shfl_xor_sync(0xffffffffu, s[i], 2);
        tt[i] += __shfl_xor_sync(0xffffffffu, tt[i], 1);
        tt[i] += __shfl_xor_sync(0xffffffffu, tt[i], 2);
        sOut[i] = s[i]; tOut[i] = tt[i];
    }
    rows[0] = m0 + g;
    rows[1] = m0 + g + 8;
    rows[2] = m0 + 16 + g;
    rows[3] = m0 + 24 + g;
}

// ---------------- K2: horizontal attention (tf32 mma) -> Umh ----------------
__global__ __launch_bounds__(192) void k2_attn_h(const float* __restrict__ mask)
{
    extern __shared__ uint32_t smem[];
    uint32_t* sfq = smem;
    uint32_t* sfk = sfq + 192 * SPAD;
    float2* sbv = reinterpret_cast<float2*>(sfk + 192 * SPAD);

    const int b = blockIdx.x, p = blockIdx.y;
    const int tid = threadIdx.x;
    const int base = (b * KPn + p) * KQn;

    const float4* fq4 = reinterpret_cast<const float4*>(g_fq + base * Tn);
    const float4* fk4 = reinterpret_cast<const float4*>(g_fk + base * Tn);
    for (int i = tid; i < 192 * 8; i += 192) {
        const int row = i >> 3, f4 = i & 7;
        float4 v = fq4[i];
        uint32_t* dq = sfq + row * SPAD + f4 * 4;
        dq[0] = tf32cvt(v.x); dq[1] = tf32cvt(v.y); dq[2] = tf32cvt(v.z); dq[3] = tf32cvt(v.w);
        float4 w = fk4[i];
        uint32_t* dk = sfk + row * SPAD + f4 * 4;
        dk[0] = tf32cvt(w.x); dk[1] = tf32cvt(w.y); dk[2] = tf32cvt(w.z); dk[3] = tf32cvt(w.w);
    }
    {
        const int i = tid;
        sbv[i] = make_float2((mask[base + i] < 0.5f) ? NEGV : 0.f, g_vw[base + i]);
    }
    __syncthreads();

    float s[4], t[4]; int rows[4];
    attn_mma_core(sfq, sfk, sbv, tid, s, t, rows);

    if ((tid & 3) == 0) {
        #pragma unroll
        for (int i = 0; i < 4; i++) g_Umh[base + rows[i]] = t[i] / s[i];
    }
}

// ---------------- K3: vertical attention (tf32 mma) -> Um ----------------
__global__ __launch_bounds__(192) void k3_attn_v(const float* __restrict__ mask)
{
    extern __shared__ uint32_t smem[];
    uint32_t* sfq = smem;
    uint32_t* sfk = sfq + 192 * SPAD;
    float2* sbv = reinterpret_cast<float2*>(sfk + 192 * SPAD);

    const int b = blockIdx.x, q = blockIdx.y;
    const int tid = threadIdx.x;

    const float4* fqg = reinterpret_cast<const float4*>(g_fq);
    const float4* fkg = reinterpret_cast<const float4*>(g_fk);
    for (int i = tid; i < 192 * 8; i += 192) {
        const int row = i >> 3, f4 = i & 7;
        const int gidx = ((b * KPn + row) * KQn + q) * 8 + f4;
        float4 v = fqg[gidx];
        uint32_t* dq = sfq + row * SPAD + f4 * 4;
        dq[0] = tf32cvt(v.x); dq[1] = tf32cvt(v.y); dq[2] = tf32cvt(v.z); dq[3] = tf32cvt(v.w);
        float4 w = fkg[gidx];
        uint32_t* dk = sfk + row * SPAD + f4 * 4;
        dk[0] = tf32cvt(w.x); dk[1] = tf32cvt(w.y); dk[2] = tf32cvt(w.z); dk[3] = tf32cvt(w.w);
    }
    {
        const int i = tid;
        const int idx = (b * KPn + i) * KQn + q;
        sbv[i] = make_float2((mask[idx] < 0.5f) ? NEGV : 0.f, g_vw[idx]);
    }
    __syncthreads();

    float s[4], t[4]; int rows[4];
    attn_mma_core(sfq, sfk, sbv, tid, s, t, rows);

    if ((tid & 3) == 0) {
        #pragma unroll
        for (int i = 0; i < 4; i++) {
            const int idx = (b * KPn + rows[i]) * KQn + q;
            g_Um[idx] = g_Umh[idx] + t[i] / s[i];
        }
    }
}

// ---------------- K4: U = Ep @ (Eq.w3)^T + u1 + u2 + Um, masked ----------------
__global__ __launch_bounds__(256) void k4_U(
    const float* __restrict__ Eq, const float* __restrict__ Ep,
    const float* __restrict__ W_out, const float* __restrict__ mask)
{
    const int b = blockIdx.z;
    const int row0 = blockIdx.y * 64;
    const int col0 = blockIdx.x * 64;
    __shared__ float sA[64][17];
    __shared__ float sB[64][17];
    __shared__ float sw3[Hn];
    const int tid = threadIdx.x;
    const int tx = tid & 15, ty = tid >> 4;
    const int r = tid >> 2, k4i = (tid & 3) * 4;
    float c[4][4] = {};

    for (int i = tid; i < Hn; i += 256) sw3[i] = W_out[2 * Hn + i];
    __syncthreads();

    for (int kc = 0; kc < Hn; kc += 16) {
        float4 av = *reinterpret_cast<const float4*>(Ep + (b * KPn + row0 + r) * Hn + kc + k4i);
        float4 bv = *reinterpret_cast<const float4*>(Eq + (b * KQn + col0 + r) * Hn + kc + k4i);
        bv.x *= sw3[kc + k4i]; bv.y *= sw3[kc + k4i + 1];
        bv.z *= sw3[kc + k4i + 2]; bv.w *= sw3[kc + k4i + 3];
        __syncthreads();
        sA[r][k4i] = av.x; sA[r][k4i + 1] = av.y; sA[r][k4i + 2] = av.z; sA[r][k4i + 3] = av.w;
        sB[r][k4i] = bv.x; sB[r][k4i + 1] = bv.y; sB[r][k4i + 2] = bv.z; sB[r][k4i + 3] = bv.w;
        __syncthreads();
        #pragma unroll
        for (int kk = 0; kk < 16; kk++) {
            float a[4], bb[4];
            #pragma unroll
            for (int i = 0; i < 4; i++) a[i] = sA[ty + 16 * i][kk];
            #pragma unroll
            for (int j = 0; j < 4; j++) bb[j] = sB[tx + 16 * j][kk];
            #pragma unroll
            for (int i = 0; i < 4; i++)
                #pragma unroll
                for (int j = 0; j < 4; j++) c[i][j] += a[i] * bb[j];
        }
    }
    #pragma unroll
    for (int i = 0; i < 4; i++) {
        const int rr = row0 + ty + 16 * i;
        #pragma unroll
        for (int j = 0; j < 4; j++) {
            const int cc = col0 + tx + 16 * j;
            const int idx = (b * KPn + rr) * KQn + cc;
            float Uv = c[i][j] + g_u1[b * KQn + cc] + g_u2[b * KPn + rr] + g_Um[idx];
            if (mask[idx] < 0.5f) Uv = NEGV;
            g_U[idx] = Uv;
        }
    }
}

// ---------------- K5a: softmax over q -> A''_p, build G_left ----------------
__global__ __launch_bounds__(256) void k5_rowsoft(const float* __restrict__ Eq, const float* __restrict__ Ep)
{
    const int b = blockIdx.x, p = blockIdx.y;
    __shared__ float sw[KQn];
    __shared__ float red[256];
    const int tid = threadIdx.x;
    const int base = (b * KPn + p) * KQn;

    float v = (tid < KQn) ? g_U[base + tid] : -3.4e38f;
    red[tid] = v; __syncthreads();
    for (int o = 128; o; o >>= 1) { if (tid < o) red[tid] = fmaxf(red[tid], red[tid + o]); __syncthreads(); }
    const float m = red[0]; __syncthreads();
    const float e = (tid < KQn) ? __expf(v - m) : 0.f;
    red[tid] = e; __syncthreads();
    for (int o = 128; o; o >>= 1) { if (tid < o) red[tid] += red[tid + o]; __syncthreads(); }
    const float inv = 1.f / red[0];
    if (tid < KQn) sw[tid] = e * inv;
    __syncthreads();

    const int h = tid;
    float a0 = 0.f, a1 = 0.f;
    for (int k = 0; k < KQn; k += 2) {
        a0 += sw[k] * Eq[(b * KQn + k) * Hn + h];
        a1 += sw[k + 1] * Eq[(b * KQn + k + 1) * Hn + h];
    }
    const float a = a0 + a1;
    const float ep = Ep[(b * KPn + p) * Hn + h];
    float* G = g_Gl + (b * KPn + p) * Rn;
    G[h] = ep; G[Hn + h] = a; G[2 * Hn + h] = ep * a;
}

// ---------------- K5b: softmax over p -> B''_p, build G_right ----------------
__global__ __launch_bounds__(256) void k5_colsoft(const float* __restrict__ Eq, const float* __restrict__ Ep)
{
    const int b = blockIdx.x, q = blockIdx.y;
    __shared__ float sw[KPn];
    __shared__ float red[256];
    const int tid = threadIdx.x;

    float v = (tid < KPn) ? g_U[(b * KPn + tid) * KQn + q] : -3.4e38f;
    red[tid] = v; __syncthreads();
    for (int o = 128; o; o >>= 1) { if (tid < o) red[tid] = fmaxf(red[tid], red[tid + o]); __syncthreads(); }
    const float m = red[0]; __syncthreads();
    const float e = (tid < KPn) ? __expf(v - m) : 0.f;
    red[tid] = e; __syncthreads();
    for (int o = 128; o; o >>= 1) { if (tid < o) red[tid] += red[tid + o]; __syncthreads(); }
    const float inv = 1.f / red[0];
    if (tid < KPn) sw[tid] = e * inv;
    __syncthreads();

    const int h = tid;
    float a0 = 0.f, a1 = 0.f;
    for (int k = 0; k < KPn; k += 2) {
        a0 += sw[k] * Ep[(b * KPn + k) * Hn + h];
        a1 += sw[k + 1] * Ep[(b * KPn + k + 1) * Hn + h];
    }
    const float a = a0 + a1;
    const float eq = Eq[(b * KQn + q) * Hn + h];
    float* G = g_Gr + (b * KQn + q) * Rn;
    G[h] = eq; G[Hn + h] = a; G[2 * Hn + h] = eq * a;
}

// ---------------- K6: gates via tf32 MMA, 64x64 tile ----------------
__global__ __launch_bounds__(256) void k6_gate(
    const float* __restrict__ Wl, const float* __restrict__ bl,
    const float* __restrict__ Wr, const float* __restrict__ br)
{
    __shared__ uint32_t sG[64 * 36];
    __shared__ uint32_t sW[64 * 36];

    const int side = blockIdx.z;
    const float* __restrict__ G = side ? g_Gr : g_Gl;
    const float* __restrict__ W = side ? Wr : Wl;
    const float* __restrict__ bias = side ? br : bl;
    float* __restrict__ outp = side ? g_right : g_left;
    const int row0 = blockIdx.y * 64;
    const int col0 = blockIdx.x * 64;

    const int tid = threadIdx.x;
    const int wid = tid >> 5, lane = tid & 31, g = lane >> 2, t4 = lane & 3;
    const int wr = wid >> 2, wc = wid & 3;
    float c[2][2][4] = {};

    for (int kc = 0; kc < Rn; kc += 32) {
        #pragma unroll
        for (int h = 0; h < 2; h++) {
            const int i = tid + h * 256;          // 0..511
            const int r = i >> 3, j4 = i & 7;
            float4 gv = *reinterpret_cast<const float4*>(G + (row0 + r) * Rn + kc + j4 * 4);
            uint32_t* dg = sG + r * 36 + j4 * 4;
            dg[0] = tf32cvt(gv.x); dg[1] = tf32cvt(gv.y); dg[2] = tf32cvt(gv.z); dg[3] = tf32cvt(gv.w);
            float4 wv = *reinterpret_cast<const float4*>(W + (col0 + r) * Rn + kc + j4 * 4);
            uint32_t* dw = sW + r * 36 + j4 * 4;
            dw[0] = tf32cvt(wv.x); dw[1] = tf32cvt(wv.y); dw[2] = tf32cvt(wv.z); dw[3] = tf32cvt(wv.w);
        }
        __syncthreads();
        #pragma unroll
        for (int ks = 0; ks < 4; ks++) {
            uint32_t a[2][4];
            #pragma unroll
            for (int mt = 0; mt < 2; mt++) {
                const int r = wr * 32 + mt * 16;
                a[mt][0] = sG[(r + g) * 36 + ks * 8 + t4];
                a[mt][1] = sG[(r + g + 8) * 36 + ks * 8 + t4];
                a[mt][2] = sG[(r + g) * 36 + ks * 8 + t4 + 4];
                a[mt][3] = sG[(r + g + 8) * 36 + ks * 8 + t4 + 4];
            }
            #pragma unroll
            for (int nt = 0; nt < 2; nt++) {
                const uint32_t b0 = sW[(wc * 16 + nt * 8 + g) * 36 + ks * 8 + t4];
                const uint32_t b1 = sW[(wc * 16 + nt * 8 + g) * 36 + ks * 8 + t4 + 4];
                mma_tf32(c[0][nt], a[0], b0, b1);
                mma_tf32(c[1][nt], a[1], b0, b1);
            }
        }
        __syncthreads();
    }

    #pragma unroll
    for (int mt = 0; mt < 2; mt++)
        #pragma unroll
        for (int nt = 0; nt < 2; nt++) {
            const int row = row0 + wr * 32 + mt * 16 + g;
            const int col = col0 + wc * 16 + nt * 8 + 2 * t4;
            const float b0f = bias[col], b1f = bias[col + 1];
            {
                float2 gv = *reinterpret_cast<const float2*>(G + row * Rn + col);
                const float s0 = 1.f / (1.f + __expf(-(c[mt][nt][0] + b0f)));
                const float s1 = 1.f / (1.f + __expf(-(c[mt][nt][1] + b1f)));
                *reinterpret_cast<float2*>(outp + row * Rn + col) = make_float2(s0 * gv.x, s1 * gv.y);
            }
            {
                float2 gv = *reinterpret_cast<const float2*>(G + (row + 8) * Rn + col);
                const float s2 = 1.f / (1.f + __expf(-(c[mt][nt][2] + b0f)));
                const float s3 = 1.f / (1.f + __expf(-(c[mt][nt][3] + b1f)));
                *reinterpret_cast<float2*>(outp + (row + 8) * Rn + col) = make_float2(s2 * gv.x, s3 * gv.y);
            }
        }
}

// ---------------- K7: split-K partials of left @ right^T ----------------
__global__ __launch_bounds__(256) void k7_partial()
{
    const int z = blockIdx.z;
    const int b = z >> 2, ks = z & 3;
    const int kbase = ks * 192;
    const float* __restrict__ A = g_left + b * KPn * Rn;
    const float* __restrict__ Bm = g_right + b * KQn * Rn;
    const int row0 = blockIdx.y * 64;
    const int col0 = blockIdx.x * 64;
    __shared__ float sA[64][17];
    __shared__ float sB[64][17];
    const int tid = threadIdx.x;
    const int tx = tid & 15, ty = tid >> 4;
    float c[4][4] = {};

    for (int kc = kbase; kc < kbase + 192; kc += 16) {
        const int r = tid >> 2, k4 = (tid & 3) * 4;
        float4 av = *reinterpret_cast<const float4*>(A + (row0 + r) * Rn + kc + k4);
        float4 bv = *reinterpret_cast<const float4*>(Bm + (col0 + r) * Rn + kc + k4);
        __syncthreads();
        sA[r][k4] = av.x; sA[r][k4 + 1] = av.y; sA[r][k4 + 2] = av.z; sA[r][k4 + 3] = av.w;
        sB[r][k4] = bv.x; sB[r][k4 + 1] = bv.y; sB[r][k4 + 2] = bv.z; sB[r][k4 + 3] = bv.w;
        __syncthreads();
        #pragma unroll
        for (int kk = 0; kk < 16; kk++) {
            float a[4], bb[4];
            #pragma unroll
            for (int i = 0; i < 4; i++) a[i] = sA[ty + 16 * i][kk];
            #pragma unroll
            for (int j = 0; j < 4; j++) bb[j] = sB[tx + 16 * j][kk];
            #pragma unroll
            for (int i = 0; i < 4; i++)
                #pragma unroll
                for (int j = 0; j < 4; j++) c[i][j] += a[i] * bb[j];
        }
    }
    float* dst = g_part + ks * (BB * KPn * KQn) + b * (KPn * KQn);
    #pragma unroll
    for (int i = 0; i < 4; i++) {
        const int r = row0 + ty + 16 * i;
        #pragma unroll
        for (int j = 0; j < 4; j++) {
            const int cc = col0 + tx + 16 * j;
            dst[r * KQn + cc] = c[i][j];
        }
    }
}

// ---------------- K8: reduce split-K + relu ----------------
__global__ __launch_bounds__(256) void k8_reduce(float* __restrict__ outp)
{
    const int idx = blockIdx.x * 256 + threadIdx.x;
    const int n = BB * KPn * KQn;
    if (idx < n) {
        float s = (g_part[idx] + g_part[n + idx]) + (g_part[2 * n + idx] + g_part[3 * n + idx]);
        outp[idx] = fmaxf(s, 0.f);
    }
}

// ---------------- launch ----------------
extern "C" void kernel_launch(void* const* d_in, const int* in_sizes, int n_in,
                              void* d_out, int out_size)
{
    const float* Eq    = (const float*)d_in[0];
    const float* Ep    = (const float*)d_in[1];
    const float* mask  = (const float*)d_in[2];
    const float* W_in  = (const float*)d_in[3];
    const float* Wq    = (const float*)d_in[4];
    const float* bq    = (const float*)d_in[5];
    const float* Wk    = (const float*)d_in[6];
    const float* bk    = (const float*)d_in[7];
    const float* Wv    = (const float*)d_in[8];
    const float* bv    = (const float*)d_in[9];
    const float* Wo1   = (const float*)d_in[10];
    const float* bo1   = (const float*)d_in[11];
    const float* Wo2   = (const float*)d_in[12];
    const float* bo2   = (const float*)d_in[13];
    const float* W_out = (const float*)d_in[14];
    const float* Wl    = (const float*)d_in[15];
    const float* bl    = (const float*)d_in[16];
    const float* Wr    = (const float*)d_in[17];
    const float* br    = (const float*)d_in[18];
    float* outp = (float*)d_out;

    const int smemAttn = 2 * 192 * SPAD * 4 + 192 * 8;                   // 56832 B
    const int smemK1 = (32 * 260 + 192 * 36) * 4 + (Hn + Tn + Tn) * 4;   // 62208 B
    cudaFuncSetAttribute(k2_attn_h, cudaFuncAttributeMaxDynamicSharedMemorySize, smemAttn);
    cudaFuncSetAttribute(k3_attn_v, cudaFuncAttributeMaxDynamicSharedMemorySize, smemAttn);
    cudaFuncSetAttribute(k1_pair, cudaFuncAttributeMaxDynamicSharedMemorySize, smemK1);

    k0_rowproj<<<dim3(BB, 2, 4), dim3(32, 8)>>>(Eq, Ep, W_in, W_out);
    k0b_wv4<<<1, 32>>>(Wv, bv, W_out);
    k1_pair<<<dim3(BB, KPn), 192, smemK1>>>(Eq, Ep, W_in, Wq, bq, Wk, bk, Wo1, bo1, Wo2, bo2);
    k2_attn_h<<<dim3(BB, KPn), 192, smemAttn>>>(mask);
    k3_attn_v<<<dim3(BB, KQn), 192, smemAttn>>>(mask);
    k4_U<<<dim3(3, 3, BB), 256>>>(Eq, Ep, W_out, mask);
    k5_rowsoft<<<dim3(BB, KPn), 256>>>(Eq, Ep);
    k5_colsoft<<<dim3(BB, KQn), 256>>>(Eq, Ep);
    k6_gate<<<dim3(12, 12, 2), 256>>>(Wl, bl, Wr, br);
    k7_partial<<<dim3(3, 3, 16), 256>>>();
    k8_reduce<<<dim3(576), 256>>>(outp);
}

// round 9
// speedup vs baseline: 4.4727x; 1.2740x over previous
#include <cuda_runtime.h>
#include <math.h>
#include <stdint.h>

#define BB 4
#define KQn 192
#define KPn 192
#define Hn 256
#define Tn 32
#define Rn 768
#define NEGV (-1e9f)
#define SCALEV (0.17677669529663687f)   // 1/sqrt(32)
#define SPAD 36                          // smem row stride (conflict-free frag loads)

// ---------------- scratch ----------------
static __device__ float g_A1[BB * KQn * Tn];
static __device__ float g_A2[BB * KPn * Tn];
static __device__ float g_u1[BB * KQn];
static __device__ float g_u2[BB * KPn];
static __device__ float g_fq[BB * KPn * KQn * Tn];  // tf32-rounded
static __device__ float g_fk[BB * KPn * KQn * Tn];  // tf32-rounded, pre-scaled by obv*SCALE
static __device__ float g_vw[BB * KPn * KQn];
static __device__ float g_wv4[Tn];
static __device__ float g_c0[1];
static __device__ float g_Umh[BB * KPn * KQn];
static __device__ float g_Um[BB * KPn * KQn];
static __device__ float g_U[BB * KPn * KQn];
static __device__ float g_Gl[BB * KPn * Rn];
static __device__ float g_Gr[BB * KQn * Rn];
static __device__ float g_left[BB * KPn * Rn];
static __device__ float g_right[BB * KQn * Rn];
static __device__ float g_part[4 * BB * KPn * KQn];

__device__ __forceinline__ float dot4(float4 a, float4 b) {
    return (a.x * b.x + a.y * b.y) + (a.z * b.z + a.w * b.w);
}

__device__ __forceinline__ uint32_t tf32cvt(float x) {
    uint32_t u;
    asm("cvt.rna.tf32.f32 %0, %1;" : "=r"(u) : "f"(x));
    return u;
}

__device__ __forceinline__ void mma_tf32(float c[4], const uint32_t a[4], uint32_t b0, uint32_t b1) {
    asm volatile("mma.sync.aligned.m16n8k8.row.col.f32.tf32.tf32.f32 "
        "{%0,%1,%2,%3}, {%4,%5,%6,%7}, {%8,%9}, {%0,%1,%2,%3};"
        : "+f"(c[0]), "+f"(c[1]), "+f"(c[2]), "+f"(c[3])
        : "r"(a[0]), "r"(a[1]), "r"(a[2]), "r"(a[3]), "r"(b0), "r"(b1));
}

// ---------------- K0: per-row projections A1/A2 and u1/u2 ----------------
__global__ __launch_bounds__(256) void k0_rowproj(
    const float* __restrict__ Eq, const float* __restrict__ Ep,
    const float* __restrict__ W_in, const float* __restrict__ W_out)
{
    const int b = blockIdx.x;
    const int side = blockIdx.y;
    const float* src = side ? (Ep + b * KPn * Hn) : (Eq + b * KQn * Hn);
    const int woff = side ? Hn : 0;
    float* A = side ? (g_A2 + b * KPn * Tn) : (g_A1 + b * KQn * Tn);
    float* u = side ? (g_u2 + b * KPn) : (g_u1 + b * KQn);

    __shared__ float sW[Tn][Hn + 1];
    __shared__ float swv[Hn];
    const int tid = threadIdx.y * 32 + threadIdx.x;
    for (int i = tid; i < Tn * Hn; i += 256) {
        int t = i >> 8, h = i & 255;
        sW[t][h] = W_in[t * Rn + woff + h];
    }
    for (int i = tid; i < Hn; i += 256) swv[i] = W_out[woff + i];
    __syncthreads();

    const int t = threadIdx.x;
    const int y0 = blockIdx.z * 48;
    for (int y = y0 + threadIdx.y; y < y0 + 48; y += 8) {
        const float* row = src + y * Hn;
        float p0 = 0.f, p1 = 0.f, p2 = 0.f, p3 = 0.f, up = 0.f;
        for (int h = 0; h < Hn; h += 4) {
            p0 += row[h] * sW[t][h];
            p1 += row[h + 1] * sW[t][h + 1];
            p2 += row[h + 2] * sW[t][h + 2];
            p3 += row[h + 3] * sW[t][h + 3];
        }
        for (int h = t; h < Hn; h += 32) up += row[h] * swv[h];
        #pragma unroll
        for (int o = 16; o; o >>= 1) up += __shfl_down_sync(0xffffffffu, up, o);
        A[y * Tn + t] = (p0 + p1) + (p2 + p3);
        if (t == 0) u[y] = up;
    }
}

// ---------------- K0b: wv4 = Wv^T @ w4, c0 = bv . w4 ----------------
__global__ void k0b_wv4(const float* __restrict__ Wv, const float* __restrict__ bv,
                        const float* __restrict__ W_out)
{
    const int t = threadIdx.x;
    float s = 0.f;
    for (int u = 0; u < Tn; u++) s += Wv[u * Tn + t] * W_out[Rn + u];
    g_wv4[t] = s;
    float c = bv[t] * W_out[Rn + t];
    #pragma unroll
    for (int o = 16; o; o >>= 1) c += __shfl_down_sync(0xffffffffu, c, o);
    if (t == 0) g_c0[0] = c;
}

// ---------------- K1: bilinear MMA -> E1 -> projection MMA (Wo1|Wq|Wk|wv4) ----------------
// smem: sW3[32*260] tf32 (reused as sWcat[104*36]); sA[192*36] (A chunks / fp32 spill / tf32 E1);
//       sEpRow[256]; sA2[32]
__global__ __launch_bounds__(192) void k1_pair(
    const float* __restrict__ Eq, const float* __restrict__ Ep,
    const float* __restrict__ W_in,
    const float* __restrict__ Wq, const float* __restrict__ bq,
    const float* __restrict__ Wk, const float* __restrict__ bk,
    const float* __restrict__ Wo1, const float* __restrict__ bo1,
    const float* __restrict__ Wo2, const float* __restrict__ bo2)
{
    extern __shared__ uint32_t smem[];
    uint32_t* sW3 = smem;                                   // 32*260 (>= 104*36)
    uint32_t* sA = sW3 + 32 * 260;                          // 192*36
    float* sE1f = reinterpret_cast<float*>(sA);
    float* sEpRow = reinterpret_cast<float*>(sA + 192 * 36);
    float* sA2 = sEpRow + Hn;

    const int b = blockIdx.x, p = blockIdx.y;
    const int tid = threadIdx.x;
    const int wid = tid >> 5, lane = tid & 31, g = lane >> 2, t4 = lane & 3;
    const int m0 = wid * 32;

    // stage W3 (tf32), Ep row, A2
    for (int i = tid; i < 32 * 64; i += 192) {
        const int t = i >> 6, h4 = i & 63;
        float4 w = reinterpret_cast<const float4*>(W_in + t * Rn + 2 * Hn)[h4];
        uint32_t* d = sW3 + t * 260 + h4 * 4;
        d[0] = tf32cvt(w.x); d[1] = tf32cvt(w.y); d[2] = tf32cvt(w.z); d[3] = tf32cvt(w.w);
    }
    for (int i = tid; i < Hn / 4; i += 192)
        reinterpret_cast<float4*>(sEpRow)[i] =
            reinterpret_cast<const float4*>(Ep + (b * KPn + p) * Hn)[i];
    if (tid < Tn) sA2[tid] = g_A2[(b * KPn + p) * Tn + tid];
    __syncthreads();

    // ---- stage 1: bilinear E1 = (Eq o Ep) @ W3^T ----
    float c1[2][4][4] = {};
    const float4* eqrow = reinterpret_cast<const float4*>(Eq + (b * KQn + tid) * Hn);
    const float4* sEpRow4 = reinterpret_cast<const float4*>(sEpRow);

    for (int kc = 0; kc < 8; kc++) {
        #pragma unroll
        for (int j = 0; j < 8; j++) {
            float4 e = eqrow[kc * 8 + j];
            float4 pp = sEpRow4[kc * 8 + j];
            uint32_t* d = sA + tid * 36 + j * 4;
            d[0] = tf32cvt(e.x * pp.x); d[1] = tf32cvt(e.y * pp.y);
            d[2] = tf32cvt(e.z * pp.z); d[3] = tf32cvt(e.w * pp.w);
        }
        __syncthreads();
        #pragma unroll
        for (int ks = 0; ks < 4; ks++) {
            uint32_t a[2][4];
            #pragma unroll
            for (int mt = 0; mt < 2; mt++) {
                const int r = m0 + mt * 16;
                a[mt][0] = sA[(r + g) * 36 + ks * 8 + t4];
                a[mt][1] = sA[(r + g + 8) * 36 + ks * 8 + t4];
                a[mt][2] = sA[(r + g) * 36 + ks * 8 + t4 + 4];
                a[mt][3] = sA[(r + g + 8) * 36 + ks * 8 + t4 + 4];
            }
            #pragma unroll
            for (int nt = 0; nt < 4; nt++) {
                const uint32_t b0 = sW3[(nt * 8 + g) * 260 + kc * 32 + ks * 8 + t4];
                const uint32_t b1 = sW3[(nt * 8 + g) * 260 + kc * 32 + ks * 8 + t4 + 4];
                mma_tf32(c1[0][nt], a[0], b0, b1);
                mma_tf32(c1[1][nt], a[1], b0, b1);
            }
        }
        __syncthreads();
    }

    // spill bilinear C to sE1f (fp32)
    #pragma unroll
    for (int mt = 0; mt < 2; mt++)
        #pragma unroll
        for (int nt = 0; nt < 4; nt++) {
            const int r0 = m0 + mt * 16 + g;
            const int col = nt * 8 + 2 * t4;
            sE1f[r0 * 36 + col] = c1[mt][nt][0];
            sE1f[r0 * 36 + col + 1] = c1[mt][nt][1];
            sE1f[(r0 + 8) * 36 + col] = c1[mt][nt][2];
            sE1f[(r0 + 8) * 36 + col + 1] = c1[mt][nt][3];
        }
    __syncthreads();

    // finalize E1 (add A1 + A2), convert to tf32 in place; load Wcat into sW3 region
    {
        const int q = tid;
        const float4* a1 = reinterpret_cast<const float4*>(g_A1 + (b * KQn + q) * Tn);
        #pragma unroll
        for (int i4 = 0; i4 < 8; i4++) {
            float4 ev = *reinterpret_cast<const float4*>(&sE1f[q * 36 + i4 * 4]);
            float4 a = a1[i4];
            uint32_t* d = sA + q * 36 + i4 * 4;
            d[0] = tf32cvt(ev.x + a.x + sA2[i4 * 4 + 0]);
            d[1] = tf32cvt(ev.y + a.y + sA2[i4 * 4 + 1]);
            d[2] = tf32cvt(ev.z + a.z + sA2[i4 * 4 + 2]);
            d[3] = tf32cvt(ev.w + a.w + sA2[i4 * 4 + 3]);
        }
    }
    // Wcat: rows 0-31 Wo1, 32-63 Wq, 64-95 Wk, 96 wv4, 97-103 zero; [n][k] stride 36
    for (int i = tid; i < 96 * 32; i += 192) {
        const int n = i >> 5, t = i & 31;
        float w = (n < 32) ? Wo1[n * 32 + t] : (n < 64) ? Wq[(n - 32) * 32 + t] : Wk[(n - 64) * 32 + t];
        sW3[n * 36 + t] = tf32cvt(w);
    }
    if (tid < 32) sW3[96 * 36 + tid] = tf32cvt(g_wv4[tid]);
    for (int i = tid; i < 7 * 36; i += 192) sW3[97 * 36 + i] = 0u;
    __syncthreads();

    // ---- stage 2: projections via MMA on tf32 E1 ----
    const int pairbase = (b * KPn + p) * KQn;
    const float bo2v = bo2[0];
    const float c0v = g_c0[0];
    float scReg[4];

    // G0: Wo1 rows 0-31 -> sc per row-slot
    {
        float c[2][4][4] = {};
        #pragma unroll
        for (int ks = 0; ks < 4; ks++) {
            uint32_t a[2][4];
            #pragma unroll
            for (int mt = 0; mt < 2; mt++) {
                const int r = m0 + mt * 16;
                a[mt][0] = sA[(r + g) * 36 + ks * 8 + t4];
                a[mt][1] = sA[(r + g + 8) * 36 + ks * 8 + t4];
                a[mt][2] = sA[(r + g) * 36 + ks * 8 + t4 + 4];
                a[mt][3] = sA[(r + g + 8) * 36 + ks * 8 + t4 + 4];
            }
            #pragma unroll
            for (int nt = 0; nt < 4; nt++) {
                const uint32_t b0 = sW3[(nt * 8 + g) * 36 + ks * 8 + t4];
                const uint32_t b1 = sW3[(nt * 8 + g) * 36 + ks * 8 + t4 + 4];
                mma_tf32(c[0][nt], a[0], b0, b1);
                mma_tf32(c[1][nt], a[1], b0, b1);
            }
        }
        #pragma unroll
        for (int mt = 0; mt < 2; mt++)
            #pragma unroll
            for (int half = 0; half < 2; half++) {
                float part = 0.f;
                #pragma unroll
                for (int nt = 0; nt < 4; nt++) {
                    const int col = nt * 8 + 2 * t4;
                    part += fmaxf(c[mt][nt][half * 2 + 0] + bo1[col], 0.f) * Wo2[col]
                          + fmaxf(c[mt][nt][half * 2 + 1] + bo1[col + 1], 0.f) * Wo2[col + 1];
                }
                part += __shfl_xor_sync(0xffffffffu, part, 1);
                part += __shfl_xor_sync(0xffffffffu, part, 2);
                scReg[mt * 2 + half] = SCALEV / (1.f + __expf(-(part + bo2v)));
            }
    }

    // G1: Wq rows 32-63 -> g_fq (tf32-rounded)
    {
        float c[2][4][4] = {};
        #pragma unroll
        for (int ks = 0; ks < 4; ks++) {
            uint32_t a[2][4];
            #pragma unroll
            for (int mt = 0; mt < 2; mt++) {
                const int r = m0 + mt * 16;
                a[mt][0] = sA[(r + g) * 36 + ks * 8 + t4];
                a[mt][1] = sA[(r + g + 8) * 36 + ks * 8 + t4];
                a[mt][2] = sA[(r + g) * 36 + ks * 8 + t4 + 4];
                a[mt][3] = sA[(r + g + 8) * 36 + ks * 8 + t4 + 4];
            }
            #pragma unroll
            for (int nt = 0; nt < 4; nt++) {
                const uint32_t b0 = sW3[(32 + nt * 8 + g) * 36 + ks * 8 + t4];
                const uint32_t b1 = sW3[(32 + nt * 8 + g) * 36 + ks * 8 + t4 + 4];
                mma_tf32(c[0][nt], a[0], b0, b1);
                mma_tf32(c[1][nt], a[1], b0, b1);
            }
        }
        #pragma unroll
        for (int mt = 0; mt < 2; mt++)
            #pragma unroll
            for (int nt = 0; nt < 4; nt++) {
                const int r0 = m0 + mt * 16 + g;
                const int col = nt * 8 + 2 * t4;
                const float b0f = bq[col], b1f = bq[col + 1];
                float2 v0 = make_float2(__uint_as_float(tf32cvt(c[mt][nt][0] + b0f)),
                                        __uint_as_float(tf32cvt(c[mt][nt][1] + b1f)));
                float2 v1 = make_float2(__uint_as_float(tf32cvt(c[mt][nt][2] + b0f)),
                                        __uint_as_float(tf32cvt(c[mt][nt][3] + b1f)));
                *reinterpret_cast<float2*>(g_fq + (pairbase + r0) * Tn + col) = v0;
                *reinterpret_cast<float2*>(g_fq + (pairbase + r0 + 8) * Tn + col) = v1;
            }
    }

    // G2: Wk rows 64-95 + wv4 row 96 -> g_fk (scaled, tf32-rounded) + g_vw
    {
        float c[2][5][4] = {};
        #pragma unroll
        for (int ks = 0; ks < 4; ks++) {
            uint32_t a[2][4];
            #pragma unroll
            for (int mt = 0; mt < 2; mt++) {
                const int r = m0 + mt * 16;
                a[mt][0] = sA[(r + g) * 36 + ks * 8 + t4];
                a[mt][1] = sA[(r + g + 8) * 36 + ks * 8 + t4];
                a[mt][2] = sA[(r + g) * 36 + ks * 8 + t4 + 4];
                a[mt][3] = sA[(r + g + 8) * 36 + ks * 8 + t4 + 4];
            }
            #pragma unroll
            for (int nt = 0; nt < 5; nt++) {
                const uint32_t b0 = sW3[(64 + nt * 8 + g) * 36 + ks * 8 + t4];
                const uint32_t b1 = sW3[(64 + nt * 8 + g) * 36 + ks * 8 + t4 + 4];
                mma_tf32(c[0][nt], a[0], b0, b1);
                mma_tf32(c[1][nt], a[1], b0, b1);
            }
        }
        #pragma unroll
        for (int mt = 0; mt < 2; mt++)
            #pragma unroll
            for (int nt = 0; nt < 4; nt++) {
                const int r0 = m0 + mt * 16 + g;
                const int col = nt * 8 + 2 * t4;
                const float b0f = bk[col], b1f = bk[col + 1];
                const float s0 = scReg[mt * 2 + 0], s1 = scReg[mt * 2 + 1];
                float2 v0 = make_float2(__uint_as_float(tf32cvt((c[mt][nt][0] + b0f) * s0)),
                                        __uint_as_float(tf32cvt((c[mt][nt][1] + b1f) * s0)));
                float2 v1 = make_float2(__uint_as_float(tf32cvt((c[mt][nt][2] + b0f) * s1)),
                                        __uint_as_float(tf32cvt((c[mt][nt][3] + b1f) * s1)));
                *reinterpret_cast<float2*>(g_fk + (pairbase + r0) * Tn + col) = v0;
                *reinterpret_cast<float2*>(g_fk + (pairbase + r0 + 8) * Tn + col) = v1;
            }
        if (t4 == 0) {
            #pragma unroll
            for (int mt = 0; mt < 2; mt++) {
                const int r0 = m0 + mt * 16 + g;
                g_vw[pairbase + r0] = c[mt][4][0] + c0v;
                g_vw[pairbase + r0 + 8] = c[mt][4][2] + c0v;
            }
        }
    }
}

// ================= tensor-core attention core (shared by k2/k3) =================
__device__ __forceinline__ void attn_mma_core(
    const uint32_t* __restrict__ sfq, const uint32_t* __restrict__ sfk,
    const float2* __restrict__ sbv, int tid, float sOut[4], float tOut[4], int rows[4])
{
    const int wid = tid >> 5, lane = tid & 31;
    const int g = lane >> 2, t4 = lane & 3;
    const int m0 = wid * 32;

    float s[4] = {0.f, 0.f, 0.f, 0.f}, tt[4] = {0.f, 0.f, 0.f, 0.f};

    for (int nc = 0; nc < 192; nc += 32) {
        float c[2][4][4];
        #pragma unroll
        for (int mt = 0; mt < 2; mt++)
            #pragma unroll
            for (int nt = 0; nt < 4; nt++)
                #pragma unroll
                for (int r = 0; r < 4; r++) c[mt][nt][r] = 0.f;

        #pragma unroll
        for (int ks = 0; ks < 4; ks++) {
            uint32_t a[2][4];
            #pragma unroll
            for (int mt = 0; mt < 2; mt++) {
                const int r = m0 + mt * 16;
                a[mt][0] = sfq[(r + g) * SPAD + ks * 8 + t4];
                a[mt][1] = sfq[(r + g + 8) * SPAD + ks * 8 + t4];
                a[mt][2] = sfq[(r + g) * SPAD + ks * 8 + t4 + 4];
                a[mt][3] = sfq[(r + g + 8) * SPAD + ks * 8 + t4 + 4];
            }
            #pragma unroll
            for (int nt = 0; nt < 4; nt++) {
                const uint32_t b0 = sfk[(nc + nt * 8 + g) * SPAD + ks * 8 + t4];
                const uint32_t b1 = sfk[(nc + nt * 8 + g) * SPAD + ks * 8 + t4 + 4];
                mma_tf32(c[0][nt], a[0], b0, b1);
                mma_tf32(c[1][nt], a[1], b0, b1);
            }
        }

        #pragma unroll
        for (int nt = 0; nt < 4; nt++) {
            const int col0 = nc + nt * 8 + 2 * t4;
            const float2 bv0 = sbv[col0];
            const float2 bv1 = sbv[col0 + 1];
            #pragma unroll
            for (int mt = 0; mt < 2; mt++) {
                const float e0 = __expf(c[mt][nt][0] + bv0.x);
                const float e1 = __expf(c[mt][nt][1] + bv1.x);
                const float e2 = __expf(c[mt][nt][2] + bv0.x);
                const float e3 = __expf(c[mt][nt][3] + bv1.x);
                s[mt * 2 + 0] += e0 + e1;
                tt[mt * 2 + 0] += e0 * bv0.y + e1 * bv1.y;
                s[mt * 2 + 1] += e2 + e3;
                tt[mt * 2 + 1] += e2 * bv0.y + e3 * bv1.y;
            }
        }
    }

    #pragma unroll
    for (int i = 0; i < 4; i++) {
        s[i] += __shfl_xor_sync(0xffffffffu, s[i], 1);
        s[i] += __shfl_xor_sync(0xffffffffu, s[i], 2);
        tt[i] += __shfl_xor_sync(0xffffffffu, tt[i], 1);
        tt[i] += __shfl_xor_sync(0xffffffffu, tt[i], 2);
        sOut[i] = s[i]; tOut[i] = tt[i];
    }
    rows[0] = m0 + g;
    rows[1] = m0 + g + 8;
    rows[2] = m0 + 16 + g;
    rows[3] = m0 + 24 + g;
}

// ---------------- K2: horizontal attention (tf32 mma) -> Umh ----------------
__global__ __launch_bounds__(192) void k2_attn_h(const float* __restrict__ mask)
{
    extern __shared__ uint32_t smem[];
    uint32_t* sfq = smem;
    uint32_t* sfk = sfq + 192 * SPAD;
    float2* sbv = reinterpret_cast<float2*>(sfk + 192 * SPAD);

    const int b = blockIdx.x, p = blockIdx.y;
    const int tid = threadIdx.x;
    const int base = (b * KPn + p) * KQn;

    const uint4* fq4 = reinterpret_cast<const uint4*>(g_fq + base * Tn);
    const uint4* fk4 = reinterpret_cast<const uint4*>(g_fk + base * Tn);
    for (int i = tid; i < 192 * 8; i += 192) {
        const int row = i >> 3, f4 = i & 7;
        uint4 v = fq4[i];
        uint32_t* dq = sfq + row * SPAD + f4 * 4;
        dq[0] = v.x; dq[1] = v.y; dq[2] = v.z; dq[3] = v.w;
        uint4 w = fk4[i];
        uint32_t* dk = sfk + row * SPAD + f4 * 4;
        dk[0] = w.x; dk[1] = w.y; dk[2] = w.z; dk[3] = w.w;
    }
    sbv[tid] = make_float2((mask[base + tid] < 0.5f) ? NEGV : 0.f, g_vw[base + tid]);
    __syncthreads();

    float s[4], t[4]; int rows[4];
    attn_mma_core(sfq, sfk, sbv, tid, s, t, rows);

    if ((tid & 3) == 0) {
        #pragma unroll
        for (int i = 0; i < 4; i++) g_Umh[base + rows[i]] = t[i] / s[i];
    }
}

// ---------------- K3: vertical attention (tf32 mma) -> Um ----------------
__global__ __launch_bounds__(192) void k3_attn_v(const float* __restrict__ mask)
{
    extern __shared__ uint32_t smem[];
    uint32_t* sfq = smem;
    uint32_t* sfk = sfq + 192 * SPAD;
    float2* sbv = reinterpret_cast<float2*>(sfk + 192 * SPAD);

    const int b = blockIdx.x, q = blockIdx.y;
    const int tid = threadIdx.x;

    const uint4* fqg = reinterpret_cast<const uint4*>(g_fq);
    const uint4* fkg = reinterpret_cast<const uint4*>(g_fk);
    for (int i = tid; i < 192 * 8; i += 192) {
        const int row = i >> 3, f4 = i & 7;
        const int gidx = ((b * KPn + row) * KQn + q) * 8 + f4;
        uint4 v = fqg[gidx];
        uint32_t* dq = sfq + row * SPAD + f4 * 4;
        dq[0] = v.x; dq[1] = v.y; dq[2] = v.z; dq[3] = v.w;
        uint4 w = fkg[gidx];
        uint32_t* dk = sfk + row * SPAD + f4 * 4;
        dk[0] = w.x; dk[1] = w.y; dk[2] = w.z; dk[3] = w.w;
    }
    {
        const int idx = (b * KPn + tid) * KQn + q;
        sbv[tid] = make_float2((mask[idx] < 0.5f) ? NEGV : 0.f, g_vw[idx]);
    }
    __syncthreads();

    float s[4], t[4]; int rows[4];
    attn_mma_core(sfq, sfk, sbv, tid, s, t, rows);

    if ((tid & 3) == 0) {
        #pragma unroll
        for (int i = 0; i < 4; i++) {
            const int idx = (b * KPn + rows[i]) * KQn + q;
            g_Um[idx] = g_Umh[idx] + t[i] / s[i];
        }
    }
}

// ---------------- K4: U = Ep @ (Eq.w3)^T + u1 + u2 + Um, masked ----------------
__global__ __launch_bounds__(256) void k4_U(
    const float* __restrict__ Eq, const float* __restrict__ Ep,
    const float* __restrict__ W_out, const float* __restrict__ mask)
{
    const int b = blockIdx.z;
    const int row0 = blockIdx.y * 64;
    const int col0 = blockIdx.x * 64;
    __shared__ float sA[64][17];
    __shared__ float sB[64][17];
    __shared__ float sw3[Hn];
    const int tid = threadIdx.x;
    const int tx = tid & 15, ty = tid >> 4;
    const int r = tid >> 2, k4i = (tid & 3) * 4;
    float c[4][4] = {};

    for (int i = tid; i < Hn; i += 256) sw3[i] = W_out[2 * Hn + i];
    __syncthreads();

    for (int kc = 0; kc < Hn; kc += 16) {
        float4 av = *reinterpret_cast<const float4*>(Ep + (b * KPn + row0 + r) * Hn + kc + k4i);
        float4 bv = *reinterpret_cast<const float4*>(Eq + (b * KQn + col0 + r) * Hn + kc + k4i);
        bv.x *= sw3[kc + k4i]; bv.y *= sw3[kc + k4i + 1];
        bv.z *= sw3[kc + k4i + 2]; bv.w *= sw3[kc + k4i + 3];
        __syncthreads();
        sA[r][k4i] = av.x; sA[r][k4i + 1] = av.y; sA[r][k4i + 2] = av.z; sA[r][k4i + 3] = av.w;
        sB[r][k4i] = bv.x; sB[r][k4i + 1] = bv.y; sB[r][k4i + 2] = bv.z; sB[r][k4i + 3] = bv.w;
        __syncthreads();
        #pragma unroll
        for (int kk = 0; kk < 16; kk++) {
            float a[4], bb[4];
            #pragma unroll
            for (int i = 0; i < 4; i++) a[i] = sA[ty + 16 * i][kk];
            #pragma unroll
            for (int j = 0; j < 4; j++) bb[j] = sB[tx + 16 * j][kk];
            #pragma unroll
            for (int i = 0; i < 4; i++)
                #pragma unroll
                for (int j = 0; j < 4; j++) c[i][j] += a[i] * bb[j];
        }
    }
    #pragma unroll
    for (int i = 0; i < 4; i++) {
        const int rr = row0 + ty + 16 * i;
        #pragma unroll
        for (int j = 0; j < 4; j++) {
            const int cc = col0 + tx + 16 * j;
            const int idx = (b * KPn + rr) * KQn + cc;
            float Uv = c[i][j] + g_u1[b * KQn + cc] + g_u2[b * KPn + rr] + g_Um[idx];
            if (mask[idx] < 0.5f) Uv = NEGV;
            g_U[idx] = Uv;
        }
    }
}

// ---------------- K5a: softmax over q -> A''_p, build G_left ----------------
__global__ __launch_bounds__(256) void k5_rowsoft(const float* __restrict__ Eq, const float* __restrict__ Ep)
{
    const int b = blockIdx.x, p = blockIdx.y;
    __shared__ float sw[KQn];
    __shared__ float red[256];
    const int tid = threadIdx.x;
    const int base = (b * KPn + p) * KQn;

    float v = (tid < KQn) ? g_U[base + tid] : -3.4e38f;
    red[tid] = v; __syncthreads();
    for (int o = 128; o; o >>= 1) { if (tid < o) red[tid] = fmaxf(red[tid], red[tid + o]); __syncthreads(); }
    const float m = red[0]; __syncthreads();
    const float e = (tid < KQn) ? __expf(v - m) : 0.f;
    red[tid] = e; __syncthreads();
    for (int o = 128; o; o >>= 1) { if (tid < o) red[tid] += red[tid + o]; __syncthreads(); }
    const float inv = 1.f / red[0];
    if (tid < KQn) sw[tid] = e * inv;
    __syncthreads();

    const int h = tid;
    float a0 = 0.f, a1 = 0.f;
    for (int k = 0; k < KQn; k += 2) {
        a0 += sw[k] * Eq[(b * KQn + k) * Hn + h];
        a1 += sw[k + 1] * Eq[(b * KQn + k + 1) * Hn + h];
    }
    const float a = a0 + a1;
    const float ep = Ep[(b * KPn + p) * Hn + h];
    float* G = g_Gl + (b * KPn + p) * Rn;
    G[h] = ep; G[Hn + h] = a; G[2 * Hn + h] = ep * a;
}

// ---------------- K5b: softmax over p -> B''_p, build G_right ----------------
__global__ __launch_bounds__(256) void k5_colsoft(const float* __restrict__ Eq, const float* __restrict__ Ep)
{
    const int b = blockIdx.x, q = blockIdx.y;
    __shared__ float sw[KPn];
    __shared__ float red[256];
    const int tid = threadIdx.x;

    float v = (tid < KPn) ? g_U[(b * KPn + tid) * KQn + q] : -3.4e38f;
    red[tid] = v; __syncthreads();
    for (int o = 128; o; o >>= 1) { if (tid < o) red[tid] = fmaxf(red[tid], red[tid + o]); __syncthreads(); }
    const float m = red[0]; __syncthreads();
    const float e = (tid < KPn) ? __expf(v - m) : 0.f;
    red[tid] = e; __syncthreads();
    for (int o = 128; o; o >>= 1) { if (tid < o) red[tid] += red[tid + o]; __syncthreads(); }
    const float inv = 1.f / red[0];
    if (tid < KPn) sw[tid] = e * inv;
    __syncthreads();

    const int h = tid;
    float a0 = 0.f, a1 = 0.f;
    for (int k = 0; k < KPn; k += 2) {
        a0 += sw[k] * Ep[(b * KPn + k) * Hn + h];
        a1 += sw[k + 1] * Ep[(b * KPn + k + 1) * Hn + h];
    }
    const float a = a0 + a1;
    const float eq = Eq[(b * KQn + q) * Hn + h];
    float* G = g_Gr + (b * KQn + q) * Rn;
    G[h] = eq; G[Hn + h] = a; G[2 * Hn + h] = eq * a;
}

// ---------------- K6: gates via tf32 MMA, 64x64 tile ----------------
__global__ __launch_bounds__(256) void k6_gate(
    const float* __restrict__ Wl, const float* __restrict__ bl,
    const float* __restrict__ Wr, const float* __restrict__ br)
{
    __shared__ uint32_t sG[64 * 36];
    __shared__ uint32_t sW[64 * 36];

    const int side = blockIdx.z;
    const float* __restrict__ G = side ? g_Gr : g_Gl;
    const float* __restrict__ W = side ? Wr : Wl;
    const float* __restrict__ bias = side ? br : bl;
    float* __restrict__ outp = side ? g_right : g_left;
    const int row0 = blockIdx.y * 64;
    const int col0 = blockIdx.x * 64;

    const int tid = threadIdx.x;
    const int wid = tid >> 5, lane = tid & 31, g = lane >> 2, t4 = lane & 3;
    const int wr = wid >> 2, wc = wid & 3;
    float c[2][2][4] = {};

    for (int kc = 0; kc < Rn; kc += 32) {
        #pragma unroll
        for (int h = 0; h < 2; h++) {
            const int i = tid + h * 256;
            const int r = i >> 3, j4 = i & 7;
            float4 gv = *reinterpret_cast<const float4*>(G + (row0 + r) * Rn + kc + j4 * 4);
            uint32_t* dg = sG + r * 36 + j4 * 4;
            dg[0] = tf32cvt(gv.x); dg[1] = tf32cvt(gv.y); dg[2] = tf32cvt(gv.z); dg[3] = tf32cvt(gv.w);
            float4 wv = *reinterpret_cast<const float4*>(W + (col0 + r) * Rn + kc + j4 * 4);
            uint32_t* dw = sW + r * 36 + j4 * 4;
            dw[0] = tf32cvt(wv.x); dw[1] = tf32cvt(wv.y); dw[2] = tf32cvt(wv.z); dw[3] = tf32cvt(wv.w);
        }
        __syncthreads();
        #pragma unroll
        for (int ks = 0; ks < 4; ks++) {
            uint32_t a[2][4];
            #pragma unroll
            for (int mt = 0; mt < 2; mt++) {
                const int r = wr * 32 + mt * 16;
                a[mt][0] = sG[(r + g) * 36 + ks * 8 + t4];
                a[mt][1] = sG[(r + g + 8) * 36 + ks * 8 + t4];
                a[mt][2] = sG[(r + g) * 36 + ks * 8 + t4 + 4];
                a[mt][3] = sG[(r + g + 8) * 36 + ks * 8 + t4 + 4];
            }
            #pragma unroll
            for (int nt = 0; nt < 2; nt++) {
                const uint32_t b0 = sW[(wc * 16 + nt * 8 + g) * 36 + ks * 8 + t4];
                const uint32_t b1 = sW[(wc * 16 + nt * 8 + g) * 36 + ks * 8 + t4 + 4];
                mma_tf32(c[0][nt], a[0], b0, b1);
                mma_tf32(c[1][nt], a[1], b0, b1);
            }
        }
        __syncthreads();
    }

    #pragma unroll
    for (int mt = 0; mt < 2; mt++)
        #pragma unroll
        for (int nt = 0; nt < 2; nt++) {
            const int row = row0 + wr * 32 + mt * 16 + g;
            const int col = col0 + wc * 16 + nt * 8 + 2 * t4;
            const float b0f = bias[col], b1f = bias[col + 1];
            {
                float2 gv = *reinterpret_cast<const float2*>(G + row * Rn + col);
                const float s0 = 1.f / (1.f + __expf(-(c[mt][nt][0] + b0f)));
                const float s1 = 1.f / (1.f + __expf(-(c[mt][nt][1] + b1f)));
                *reinterpret_cast<float2*>(outp + row * Rn + col) = make_float2(s0 * gv.x, s1 * gv.y);
            }
            {
                float2 gv = *reinterpret_cast<const float2*>(G + (row + 8) * Rn + col);
                const float s2 = 1.f / (1.f + __expf(-(c[mt][nt][2] + b0f)));
                const float s3 = 1.f / (1.f + __expf(-(c[mt][nt][3] + b1f)));
                *reinterpret_cast<float2*>(outp + (row + 8) * Rn + col) = make_float2(s2 * gv.x, s3 * gv.y);
            }
        }
}

// ---------------- K7: split-K partials of left @ right^T ----------------
__global__ __launch_bounds__(256) void k7_partial()
{
    const int z = blockIdx.z;
    const int b = z >> 2, ks = z & 3;
    const int kbase = ks * 192;
    const float* __restrict__ A = g_left + b * KPn * Rn;
    const float* __restrict__ Bm = g_right + b * KQn * Rn;
    const int row0 = blockIdx.y * 64;
    const int col0 = blockIdx.x * 64;
    __shared__ float sA[64][17];
    __shared__ float sB[64][17];
    const int tid = threadIdx.x;
    const int tx = tid & 15, ty = tid >> 4;
    float c[4][4] = {};

    for (int kc = kbase; kc < kbase + 192; kc += 16) {
        const int r = tid >> 2, k4 = (tid & 3) * 4;
        float4 av = *reinterpret_cast<const float4*>(A + (row0 + r) * Rn + kc + k4);
        float4 bv = *reinterpret_cast<const float4*>(Bm + (col0 + r) * Rn + kc + k4);
        __syncthreads();
        sA[r][k4] = av.x; sA[r][k4 + 1] = av.y; sA[r][k4 + 2] = av.z; sA[r][k4 + 3] = av.w;
        sB[r][k4] = bv.x; sB[r][k4 + 1] = bv.y; sB[r][k4 + 2] = bv.z; sB[r][k4 + 3] = bv.w;
        __syncthreads();
        #pragma unroll
        for (int kk = 0; kk < 16; kk++) {
            float a[4], bb[4];
            #pragma unroll
            for (int i = 0; i < 4; i++) a[i] = sA[ty + 16 * i][kk];
            #pragma unroll
            for (int j = 0; j < 4; j++) bb[j] = sB[tx + 16 * j][kk];
            #pragma unroll
            for (int i = 0; i < 4; i++)
                #pragma unroll
                for (int j = 0; j < 4; j++) c[i][j] += a[i] * bb[j];
        }
    }
    float* dst = g_part + ks * (BB * KPn * KQn) + b * (KPn * KQn);
    #pragma unroll
    for (int i = 0; i < 4; i++) {
        const int r = row0 + ty + 16 * i;
        #pragma unroll
        for (int j = 0; j < 4; j++) {
            const int cc = col0 + tx + 16 * j;
            dst[r * KQn + cc] = c[i][j];
        }
    }
}

// ---------------- K8: reduce split-K + relu ----------------
__global__ __launch_bounds__(256) void k8_reduce(float* __restrict__ outp)
{
    const int idx = blockIdx.x * 256 + threadIdx.x;
    const int n = BB * KPn * KQn;
    if (idx < n) {
        float s = (g_part[idx] + g_part[n + idx]) + (g_part[2 * n + idx] + g_part[3 * n + idx]);
        outp[idx] = fmaxf(s, 0.f);
    }
}

// ---------------- launch ----------------
extern "C" void kernel_launch(void* const* d_in, const int* in_sizes, int n_in,
                              void* d_out, int out_size)
{
    const float* Eq    = (const float*)d_in[0];
    const float* Ep    = (const float*)d_in[1];
    const float* mask  = (const float*)d_in[2];
    const float* W_in  = (const float*)d_in[3];
    const float* Wq    = (const float*)d_in[4];
    const float* bq    = (const float*)d_in[5];
    const float* Wk    = (const float*)d_in[6];
    const float* bk    = (const float*)d_in[7];
    const float* Wv    = (const float*)d_in[8];
    const float* bv    = (const float*)d_in[9];
    const float* Wo1   = (const float*)d_in[10];
    const float* bo1   = (const float*)d_in[11];
    const float* Wo2   = (const float*)d_in[12];
    const float* bo2   = (const float*)d_in[13];
    const float* W_out = (const float*)d_in[14];
    const float* Wl    = (const float*)d_in[15];
    const float* bl    = (const float*)d_in[16];
    const float* Wr    = (const float*)d_in[17];
    const float* br    = (const float*)d_in[18];
    float* outp = (float*)d_out;

    const int smemAttn = 2 * 192 * SPAD * 4 + 192 * 8;                 // 56832 B
    const int smemK1 = (32 * 260 + 192 * 36) * 4 + (Hn + Tn) * 4;      // 62080 B
    cudaFuncSetAttribute(k2_attn_h, cudaFuncAttributeMaxDynamicSharedMemorySize, smemAttn);
    cudaFuncSetAttribute(k3_attn_v, cudaFuncAttributeMaxDynamicSharedMemorySize, smemAttn);
    cudaFuncSetAttribute(k1_pair, cudaFuncAttributeMaxDynamicSharedMemorySize, smemK1);

    k0_rowproj<<<dim3(BB, 2, 4), dim3(32, 8)>>>(Eq, Ep, W_in, W_out);
    k0b_wv4<<<1, 32>>>(Wv, bv, W_out);
    k1_pair<<<dim3(BB, KPn), 192, smemK1>>>(Eq, Ep, W_in, Wq, bq, Wk, bk, Wo1, bo1, Wo2, bo2);
    k2_attn_h<<<dim3(BB, KPn), 192, smemAttn>>>(mask);
    k3_attn_v<<<dim3(BB, KQn), 192, smemAttn>>>(mask);
    k4_U<<<dim3(3, 3, BB), 256>>>(Eq, Ep, W_out, mask);
    k5_rowsoft<<<dim3(BB, KPn), 256>>>(Eq, Ep);
    k5_colsoft<<<dim3(BB, KQn), 256>>>(Eq, Ep);
    k6_gate<<<dim3(12, 12, 2), 256>>>(Wl, bl, Wr, br);
    k7_partial<<<dim3(3, 3, 16), 256>>>();
    k8_reduce<<<dim3(576), 256>>>(outp);
}

// round 10
// speedup vs baseline: 5.1092x; 1.1423x over previous
#include <cuda_runtime.h>
#include <math.h>
#include <stdint.h>

#define BB 4
#define KQn 192
#define KPn 192
#define Hn 256
#define Tn 32
#define Rn 768
#define NEGV (-1e9f)
#define SCALEV (0.17677669529663687f)   // 1/sqrt(32)
#define SPAD 36                          // smem row stride (conflict-free frag loads)

// ---------------- scratch ----------------
static __device__ float g_A1[BB * KQn * Tn];
static __device__ float g_A2[BB * KPn * Tn];
static __device__ float g_u1[BB * KQn];
static __device__ float g_u2[BB * KPn];
static __device__ float g_fq[BB * KPn * KQn * Tn];  // tf32-rounded
static __device__ float g_fk[BB * KPn * KQn * Tn];  // tf32-rounded, pre-scaled by obv*SCALE
static __device__ float g_vw[BB * KPn * KQn];
static __device__ float g_wv4[Tn];
static __device__ float g_c0[1];
static __device__ float g_Umh[BB * KPn * KQn];
static __device__ float g_Umv[BB * KPn * KQn];
static __device__ float g_U[BB * KPn * KQn];
static __device__ float g_Gl[BB * KPn * Rn];
static __device__ float g_Gr[BB * KQn * Rn];
static __device__ float g_left[BB * KPn * Rn];
static __device__ float g_right[BB * KQn * Rn];
static __device__ float g_part[4 * BB * KPn * KQn];

__device__ __forceinline__ uint32_t tf32cvt(float x) {
    uint32_t u;
    asm("cvt.rna.tf32.f32 %0, %1;" : "=r"(u) : "f"(x));
    return u;
}

__device__ __forceinline__ void mma_tf32(float c[4], const uint32_t a[4], uint32_t b0, uint32_t b1) {
    asm volatile("mma.sync.aligned.m16n8k8.row.col.f32.tf32.tf32.f32 "
        "{%0,%1,%2,%3}, {%4,%5,%6,%7}, {%8,%9}, {%0,%1,%2,%3};"
        : "+f"(c[0]), "+f"(c[1]), "+f"(c[2]), "+f"(c[3])
        : "r"(a[0]), "r"(a[1]), "r"(a[2]), "r"(a[3]), "r"(b0), "r"(b1));
}

// ---------------- K0: per-row projections A1/A2 and u1/u2 ----------------
__global__ __launch_bounds__(256) void k0_rowproj(
    const float* __restrict__ Eq, const float* __restrict__ Ep,
    const float* __restrict__ W_in, const float* __restrict__ W_out)
{
    const int b = blockIdx.x;
    const int side = blockIdx.y;
    const float* src = side ? (Ep + b * KPn * Hn) : (Eq + b * KQn * Hn);
    const int woff = side ? Hn : 0;
    float* A = side ? (g_A2 + b * KPn * Tn) : (g_A1 + b * KQn * Tn);
    float* u = side ? (g_u2 + b * KPn) : (g_u1 + b * KQn);

    __shared__ float sW[Tn][Hn + 1];
    __shared__ float swv[Hn];
    const int tid = threadIdx.y * 32 + threadIdx.x;
    for (int i = tid; i < Tn * Hn; i += 256) {
        int t = i >> 8, h = i & 255;
        sW[t][h] = W_in[t * Rn + woff + h];
    }
    for (int i = tid; i < Hn; i += 256) swv[i] = W_out[woff + i];
    __syncthreads();

    const int t = threadIdx.x;
    const int y0 = blockIdx.z * 48;
    for (int y = y0 + threadIdx.y; y < y0 + 48; y += 8) {
        const float* row = src + y * Hn;
        float p0 = 0.f, p1 = 0.f, p2 = 0.f, p3 = 0.f, up = 0.f;
        for (int h = 0; h < Hn; h += 4) {
            p0 += row[h] * sW[t][h];
            p1 += row[h + 1] * sW[t][h + 1];
            p2 += row[h + 2] * sW[t][h + 2];
            p3 += row[h + 3] * sW[t][h + 3];
        }
        for (int h = t; h < Hn; h += 32) up += row[h] * swv[h];
        #pragma unroll
        for (int o = 16; o; o >>= 1) up += __shfl_down_sync(0xffffffffu, up, o);
        A[y * Tn + t] = (p0 + p1) + (p2 + p3);
        if (t == 0) u[y] = up;
    }
}

// ---------------- K0b: wv4 = Wv^T @ w4, c0 = bv . w4 ----------------
__global__ void k0b_wv4(const float* __restrict__ Wv, const float* __restrict__ bv,
                        const float* __restrict__ W_out)
{
    const int t = threadIdx.x;
    float s = 0.f;
    for (int u = 0; u < Tn; u++) s += Wv[u * Tn + t] * W_out[Rn + u];
    g_wv4[t] = s;
    float c = bv[t] * W_out[Rn + t];
    #pragma unroll
    for (int o = 16; o; o >>= 1) c += __shfl_down_sync(0xffffffffu, c, o);
    if (t == 0) g_c0[0] = c;
}

// ---------------- K1: bilinear MMA -> E1 -> projection MMA; warp-local barriers ----------------
__global__ __launch_bounds__(192) void k1_pair(
    const float* __restrict__ Eq, const float* __restrict__ Ep,
    const float* __restrict__ W_in,
    const float* __restrict__ Wq, const float* __restrict__ bq,
    const float* __restrict__ Wk, const float* __restrict__ bk,
    const float* __restrict__ Wo1, const float* __restrict__ bo1,
    const float* __restrict__ Wo2, const float* __restrict__ bo2)
{
    extern __shared__ uint32_t smem[];
    uint32_t* sW3 = smem;                                   // 32*260 (>= 104*36)
    uint32_t* sA = sW3 + 32 * 260;                          // 192*36
    float* sE1f = reinterpret_cast<float*>(sA);
    float* sEpRow = reinterpret_cast<float*>(sA + 192 * 36);
    float* sA2 = sEpRow + Hn;

    const int b = blockIdx.x, p = blockIdx.y;
    const int tid = threadIdx.x;
    const int wid = tid >> 5, lane = tid & 31, g = lane >> 2, t4 = lane & 3;
    const int m0 = wid * 32;

    for (int i = tid; i < 32 * 64; i += 192) {
        const int t = i >> 6, h4 = i & 63;
        float4 w = reinterpret_cast<const float4*>(W_in + t * Rn + 2 * Hn)[h4];
        uint32_t* d = sW3 + t * 260 + h4 * 4;
        d[0] = tf32cvt(w.x); d[1] = tf32cvt(w.y); d[2] = tf32cvt(w.z); d[3] = tf32cvt(w.w);
    }
    for (int i = tid; i < Hn / 4; i += 192)
        reinterpret_cast<float4*>(sEpRow)[i] =
            reinterpret_cast<const float4*>(Ep + (b * KPn + p) * Hn)[i];
    if (tid < Tn) sA2[tid] = g_A2[(b * KPn + p) * Tn + tid];
    __syncthreads();

    // ---- stage 1: bilinear E1 = (Eq o Ep) @ W3^T (warp-local A tiles) ----
    float c1[2][4][4] = {};
    const float4* eqrow = reinterpret_cast<const float4*>(Eq + (b * KQn + tid) * Hn);
    const float4* sEpRow4 = reinterpret_cast<const float4*>(sEpRow);

    for (int kc = 0; kc < 8; kc++) {
        #pragma unroll
        for (int j = 0; j < 8; j++) {
            float4 e = eqrow[kc * 8 + j];
            float4 pp = sEpRow4[kc * 8 + j];
            uint32_t* d = sA + tid * 36 + j * 4;
            d[0] = tf32cvt(e.x * pp.x); d[1] = tf32cvt(e.y * pp.y);
            d[2] = tf32cvt(e.z * pp.z); d[3] = tf32cvt(e.w * pp.w);
        }
        __syncwarp();
        #pragma unroll
        for (int ks = 0; ks < 4; ks++) {
            uint32_t a[2][4];
            #pragma unroll
            for (int mt = 0; mt < 2; mt++) {
                const int r = m0 + mt * 16;
                a[mt][0] = sA[(r + g) * 36 + ks * 8 + t4];
                a[mt][1] = sA[(r + g + 8) * 36 + ks * 8 + t4];
                a[mt][2] = sA[(r + g) * 36 + ks * 8 + t4 + 4];
                a[mt][3] = sA[(r + g + 8) * 36 + ks * 8 + t4 + 4];
            }
            #pragma unroll
            for (int nt = 0; nt < 4; nt++) {
                const uint32_t b0 = sW3[(nt * 8 + g) * 260 + kc * 32 + ks * 8 + t4];
                const uint32_t b1 = sW3[(nt * 8 + g) * 260 + kc * 32 + ks * 8 + t4 + 4];
                mma_tf32(c1[0][nt], a[0], b0, b1);
                mma_tf32(c1[1][nt], a[1], b0, b1);
            }
        }
        __syncwarp();
    }

    // spill bilinear C (warp-local rows)
    #pragma unroll
    for (int mt = 0; mt < 2; mt++)
        #pragma unroll
        for (int nt = 0; nt < 4; nt++) {
            const int r0 = m0 + mt * 16 + g;
            const int col = nt * 8 + 2 * t4;
            sE1f[r0 * 36 + col] = c1[mt][nt][0];
            sE1f[r0 * 36 + col + 1] = c1[mt][nt][1];
            sE1f[(r0 + 8) * 36 + col] = c1[mt][nt][2];
            sE1f[(r0 + 8) * 36 + col + 1] = c1[mt][nt][3];
        }
    __syncwarp();

    // finalize E1 (add A1 + A2) -> tf32 in place (row tid, warp-local)
    {
        const int q = tid;
        const float4* a1 = reinterpret_cast<const float4*>(g_A1 + (b * KQn + q) * Tn);
        #pragma unroll
        for (int i4 = 0; i4 < 8; i4++) {
            float4 ev = *reinterpret_cast<const float4*>(&sE1f[q * 36 + i4 * 4]);
            float4 a = a1[i4];
            uint32_t* d = sA + q * 36 + i4 * 4;
            d[0] = tf32cvt(ev.x + a.x + sA2[i4 * 4 + 0]);
            d[1] = tf32cvt(ev.y + a.y + sA2[i4 * 4 + 1]);
            d[2] = tf32cvt(ev.z + a.z + sA2[i4 * 4 + 2]);
            d[3] = tf32cvt(ev.w + a.w + sA2[i4 * 4 + 3]);
        }
    }
    __syncthreads();   // all warps done with sW3 stage-1 reads

    // Wcat: rows 0-31 Wo1, 32-63 Wq, 64-95 Wk, 96 wv4, 97-103 zero; [n][k] stride 36
    for (int i = tid; i < 96 * 32; i += 192) {
        const int n = i >> 5, t = i & 31;
        float w = (n < 32) ? Wo1[n * 32 + t] : (n < 64) ? Wq[(n - 32) * 32 + t] : Wk[(n - 64) * 32 + t];
        sW3[n * 36 + t] = tf32cvt(w);
    }
    if (tid < 32) sW3[96 * 36 + tid] = tf32cvt(g_wv4[tid]);
    for (int i = tid; i < 7 * 36; i += 192) sW3[97 * 36 + i] = 0u;
    __syncthreads();

    // ---- stage 2: projections via MMA on tf32 E1 ----
    const int pairbase = (b * KPn + p) * KQn;
    const float bo2v = bo2[0];
    const float c0v = g_c0[0];
    float scReg[4];

    // G0: Wo1 -> sc per row-slot
    {
        float c[2][4][4] = {};
        #pragma unroll
        for (int ks = 0; ks < 4; ks++) {
            uint32_t a[2][4];
            #pragma unroll
            for (int mt = 0; mt < 2; mt++) {
                const int r = m0 + mt * 16;
                a[mt][0] = sA[(r + g) * 36 + ks * 8 + t4];
                a[mt][1] = sA[(r + g + 8) * 36 + ks * 8 + t4];
                a[mt][2] = sA[(r + g) * 36 + ks * 8 + t4 + 4];
                a[mt][3] = sA[(r + g + 8) * 36 + ks * 8 + t4 + 4];
            }
            #pragma unroll
            for (int nt = 0; nt < 4; nt++) {
                const uint32_t b0 = sW3[(nt * 8 + g) * 36 + ks * 8 + t4];
                const uint32_t b1 = sW3[(nt * 8 + g) * 36 + ks * 8 + t4 + 4];
                mma_tf32(c[0][nt], a[0], b0, b1);
                mma_tf32(c[1][nt], a[1], b0, b1);
            }
        }
        #pragma unroll
        for (int mt = 0; mt < 2; mt++)
            #pragma unroll
            for (int half = 0; half < 2; half++) {
                float part = 0.f;
                #pragma unroll
                for (int nt = 0; nt < 4; nt++) {
                    const int col = nt * 8 + 2 * t4;
                    part += fmaxf(c[mt][nt][half * 2 + 0] + bo1[col], 0.f) * Wo2[col]
                          + fmaxf(c[mt][nt][half * 2 + 1] + bo1[col + 1], 0.f) * Wo2[col + 1];
                }
                part += __shfl_xor_sync(0xffffffffu, part, 1);
                part += __shfl_xor_sync(0xffffffffu, part, 2);
                scReg[mt * 2 + half] = SCALEV / (1.f + __expf(-(part + bo2v)));
            }
    }

    // G1: Wq -> g_fq (tf32-rounded)
    {
        float c[2][4][4] = {};
        #pragma unroll
        for (int ks = 0; ks < 4; ks++) {
            uint32_t a[2][4];
            #pragma unroll
            for (int mt = 0; mt < 2; mt++) {
                const int r = m0 + mt * 16;
                a[mt][0] = sA[(r + g) * 36 + ks * 8 + t4];
                a[mt][1] = sA[(r + g + 8) * 36 + ks * 8 + t4];
                a[mt][2] = sA[(r + g) * 36 + ks * 8 + t4 + 4];
                a[mt][3] = sA[(r + g + 8) * 36 + ks * 8 + t4 + 4];
            }
            #pragma unroll
            for (int nt = 0; nt < 4; nt++) {
                const uint32_t b0 = sW3[(32 + nt * 8 + g) * 36 + ks * 8 + t4];
                const uint32_t b1 = sW3[(32 + nt * 8 + g) * 36 + ks * 8 + t4 + 4];
                mma_tf32(c[0][nt], a[0], b0, b1);
                mma_tf32(c[1][nt], a[1], b0, b1);
            }
        }
        #pragma unroll
        for (int mt = 0; mt < 2; mt++)
            #pragma unroll
            for (int nt = 0; nt < 4; nt++) {
                const int r0 = m0 + mt * 16 + g;
                const int col = nt * 8 + 2 * t4;
                const float b0f = bq[col], b1f = bq[col + 1];
                float2 v0 = make_float2(__uint_as_float(tf32cvt(c[mt][nt][0] + b0f)),
                                        __uint_as_float(tf32cvt(c[mt][nt][1] + b1f)));
                float2 v1 = make_float2(__uint_as_float(tf32cvt(c[mt][nt][2] + b0f)),
                                        __uint_as_float(tf32cvt(c[mt][nt][3] + b1f)));
                *reinterpret_cast<float2*>(g_fq + (pairbase + r0) * Tn + col) = v0;
                *reinterpret_cast<float2*>(g_fq + (pairbase + r0 + 8) * Tn + col) = v1;
            }
    }

    // G2: Wk + wv4 -> g_fk (scaled, tf32-rounded) + g_vw
    {
        float c[2][5][4] = {};
        #pragma unroll
        for (int ks = 0; ks < 4; ks++) {
            uint32_t a[2][4];
            #pragma unroll
            for (int mt = 0; mt < 2; mt++) {
                const int r = m0 + mt * 16;
                a[mt][0] = sA[(r + g) * 36 + ks * 8 + t4];
                a[mt][1] = sA[(r + g + 8) * 36 + ks * 8 + t4];
                a[mt][2] = sA[(r + g) * 36 + ks * 8 + t4 + 4];
                a[mt][3] = sA[(r + g + 8) * 36 + ks * 8 + t4 + 4];
            }
            #pragma unroll
            for (int nt = 0; nt < 5; nt++) {
                const uint32_t b0 = sW3[(64 + nt * 8 + g) * 36 + ks * 8 + t4];
                const uint32_t b1 = sW3[(64 + nt * 8 + g) * 36 + ks * 8 + t4 + 4];
                mma_tf32(c[0][nt], a[0], b0, b1);
                mma_tf32(c[1][nt], a[1], b0, b1);
            }
        }
        #pragma unroll
        for (int mt = 0; mt < 2; mt++)
            #pragma unroll
            for (int nt = 0; nt < 4; nt++) {
                const int r0 = m0 + mt * 16 + g;
                const int col = nt * 8 + 2 * t4;
                const float b0f = bk[col], b1f = bk[col + 1];
                const float s0 = scReg[mt * 2 + 0], s1 = scReg[mt * 2 + 1];
                float2 v0 = make_float2(__uint_as_float(tf32cvt((c[mt][nt][0] + b0f) * s0)),
                                        __uint_as_float(tf32cvt((c[mt][nt][1] + b1f) * s0)));
                float2 v1 = make_float2(__uint_as_float(tf32cvt((c[mt][nt][2] + b0f) * s1)),
                                        __uint_as_float(tf32cvt((c[mt][nt][3] + b1f) * s1)));
                *reinterpret_cast<float2*>(g_fk + (pairbase + r0) * Tn + col) = v0;
                *reinterpret_cast<float2*>(g_fk + (pairbase + r0 + 8) * Tn + col) = v1;
            }
        if (t4 == 0) {
            #pragma unroll
            for (int mt = 0; mt < 2; mt++) {
                const int r0 = m0 + mt * 16 + g;
                g_vw[pairbase + r0] = c[mt][4][0] + c0v;
                g_vw[pairbase + r0 + 8] = c[mt][4][2] + c0v;
            }
        }
    }
}

// ================= tensor-core attention core =================
__device__ __forceinline__ void attn_mma_core(
    const uint32_t* __restrict__ sfq, const uint32_t* __restrict__ sfk,
    const float2* __restrict__ sbv, int tid, float sOut[4], float tOut[4], int rows[4])
{
    const int wid = tid >> 5, lane = tid & 31;
    const int g = lane >> 2, t4 = lane & 3;
    const int m0 = wid * 32;

    float s[4] = {0.f, 0.f, 0.f, 0.f}, tt[4] = {0.f, 0.f, 0.f, 0.f};

    for (int nc = 0; nc < 192; nc += 32) {
        float c[2][4][4];
        #pragma unroll
        for (int mt = 0; mt < 2; mt++)
            #pragma unroll
            for (int nt = 0; nt < 4; nt++)
                #pragma unroll
                for (int r = 0; r < 4; r++) c[mt][nt][r] = 0.f;

        #pragma unroll
        for (int ks = 0; ks < 4; ks++) {
            uint32_t a[2][4];
            #pragma unroll
            for (int mt = 0; mt < 2; mt++) {
                const int r = m0 + mt * 16;
                a[mt][0] = sfq[(r + g) * SPAD + ks * 8 + t4];
                a[mt][1] = sfq[(r + g + 8) * SPAD + ks * 8 + t4];
                a[mt][2] = sfq[(r + g) * SPAD + ks * 8 + t4 + 4];
                a[mt][3] = sfq[(r + g + 8) * SPAD + ks * 8 + t4 + 4];
            }
            #pragma unroll
            for (int nt = 0; nt < 4; nt++) {
                const uint32_t b0 = sfk[(nc + nt * 8 + g) * SPAD + ks * 8 + t4];
                const uint32_t b1 = sfk[(nc + nt * 8 + g) * SPAD + ks * 8 + t4 + 4];
                mma_tf32(c[0][nt], a[0], b0, b1);
                mma_tf32(c[1][nt], a[1], b0, b1);
            }
        }

        #pragma unroll
        for (int nt = 0; nt < 4; nt++) {
            const int col0 = nc + nt * 8 + 2 * t4;
            const float2 bv0 = sbv[col0];
            const float2 bv1 = sbv[col0 + 1];
            #pragma unroll
            for (int mt = 0; mt < 2; mt++) {
                const float e0 = __expf(c[mt][nt][0] + bv0.x);
                const float e1 = __expf(c[mt][nt][1] + bv1.x);
                const float e2 = __expf(c[mt][nt][2] + bv0.x);
                const float e3 = __expf(c[mt][nt][3] + bv1.x);
                s[mt * 2 + 0] += e0 + e1;
                tt[mt * 2 + 0] += e0 * bv0.y + e1 * bv1.y;
                s[mt * 2 + 1] += e2 + e3;
                tt[mt * 2 + 1] += e2 * bv0.y + e3 * bv1.y;
            }
        }
    }

    #pragma unroll
    for (int i = 0; i < 4; i++) {
        s[i] += __shfl_xor_sync(0xffffffffu, s[i], 1);
        s[i] += __shfl_xor_sync(0xffffffffu, s[i], 2);
        tt[i] += __shfl_xor_sync(0xffffffffu, tt[i], 1);
        tt[i] += __shfl_xor_sync(0xffffffffu, tt[i], 2);
        sOut[i] = s[i]; tOut[i] = tt[i];
    }
    rows[0] = m0 + g;
    rows[1] = m0 + g + 8;
    rows[2] = m0 + 16 + g;
    rows[3] = m0 + 24 + g;
}

// ---------------- K23: both attention directions in one launch (z = dir) ----------------
__global__ __launch_bounds__(192) void k23_attn(const float* __restrict__ mask)
{
    extern __shared__ uint32_t smem[];
    uint32_t* sfq = smem;
    uint32_t* sfk = sfq + 192 * SPAD;
    float2* sbv = reinterpret_cast<float2*>(sfk + 192 * SPAD);

    const int b = blockIdx.x, y = blockIdx.y, dir = blockIdx.z;
    const int tid = threadIdx.x;

    if (dir == 0) {
        const int base = (b * KPn + y) * KQn;   // y = p
        const uint4* fq4 = reinterpret_cast<const uint4*>(g_fq + base * Tn);
        const uint4* fk4 = reinterpret_cast<const uint4*>(g_fk + base * Tn);
        for (int i = tid; i < 192 * 8; i += 192) {
            const int row = i >> 3, f4 = i & 7;
            uint4 v = fq4[i];
            uint32_t* dq = sfq + row * SPAD + f4 * 4;
            dq[0] = v.x; dq[1] = v.y; dq[2] = v.z; dq[3] = v.w;
            uint4 w = fk4[i];
            uint32_t* dk = sfk + row * SPAD + f4 * 4;
            dk[0] = w.x; dk[1] = w.y; dk[2] = w.z; dk[3] = w.w;
        }
        sbv[tid] = make_float2((mask[base + tid] < 0.5f) ? NEGV : 0.f, g_vw[base + tid]);
        __syncthreads();

        float s[4], t[4]; int rows[4];
        attn_mma_core(sfq, sfk, sbv, tid, s, t, rows);
        if ((tid & 3) == 0) {
            #pragma unroll
            for (int i = 0; i < 4; i++) g_Umh[base + rows[i]] = t[i] / s[i];
        }
    } else {
        const int q = y;
        const uint4* fqg = reinterpret_cast<const uint4*>(g_fq);
        const uint4* fkg = reinterpret_cast<const uint4*>(g_fk);
        for (int i = tid; i < 192 * 8; i += 192) {
            const int row = i >> 3, f4 = i & 7;
            const int gidx = ((b * KPn + row) * KQn + q) * 8 + f4;
            uint4 v = fqg[gidx];
            uint32_t* dq = sfq + row * SPAD + f4 * 4;
            dq[0] = v.x; dq[1] = v.y; dq[2] = v.z; dq[3] = v.w;
            uint4 w = fkg[gidx];
            uint32_t* dk = sfk + row * SPAD + f4 * 4;
            dk[0] = w.x; dk[1] = w.y; dk[2] = w.z; dk[3] = w.w;
        }
        {
            const int idx = (b * KPn + tid) * KQn + q;
            sbv[tid] = make_float2((mask[idx] < 0.5f) ? NEGV : 0.f, g_vw[idx]);
        }
        __syncthreads();

        float s[4], t[4]; int rows[4];
        attn_mma_core(sfq, sfk, sbv, tid, s, t, rows);
        if ((tid & 3) == 0) {
            #pragma unroll
            for (int i = 0; i < 4; i++)
                g_Umv[(b * KPn + rows[i]) * KQn + q] = t[i] / s[i];
        }
    }
}

// ---------------- K4: U via tf32 MMA: Ep @ (Eq.w3)^T + u1 + u2 + Umh + Umv ----------------
__global__ __launch_bounds__(256) void k4_U(
    const float* __restrict__ Eq, const float* __restrict__ Ep,
    const float* __restrict__ W_out, const float* __restrict__ mask)
{
    __shared__ uint32_t sA[64 * 36];
    __shared__ uint32_t sB[64 * 36];
    __shared__ float sw3[Hn];

    const int b = blockIdx.z;
    const int row0 = blockIdx.y * 64;   // p
    const int col0 = blockIdx.x * 64;   // q
    const int tid = threadIdx.x;
    const int wid = tid >> 5, lane = tid & 31, g = lane >> 2, t4 = lane & 3;
    const int wr = wid >> 2, wc = wid & 3;
    float c[2][2][4] = {};

    for (int i = tid; i < Hn; i += 256) sw3[i] = W_out[2 * Hn + i];
    __syncthreads();

    for (int kc = 0; kc < Hn; kc += 32) {
        #pragma unroll
        for (int h = 0; h < 2; h++) {
            const int i = tid + h * 256;
            const int r = i >> 3, j4 = i & 7;
            float4 av = *reinterpret_cast<const float4*>(Ep + (b * KPn + row0 + r) * Hn + kc + j4 * 4);
            uint32_t* da = sA + r * 36 + j4 * 4;
            da[0] = tf32cvt(av.x); da[1] = tf32cvt(av.y); da[2] = tf32cvt(av.z); da[3] = tf32cvt(av.w);
            float4 bv = *reinterpret_cast<const float4*>(Eq + (b * KQn + col0 + r) * Hn + kc + j4 * 4);
            uint32_t* db = sB + r * 36 + j4 * 4;
            db[0] = tf32cvt(bv.x * sw3[kc + j4 * 4 + 0]);
            db[1] = tf32cvt(bv.y * sw3[kc + j4 * 4 + 1]);
            db[2] = tf32cvt(bv.z * sw3[kc + j4 * 4 + 2]);
            db[3] = tf32cvt(bv.w * sw3[kc + j4 * 4 + 3]);
        }
        __syncthreads();
        #pragma unroll
        for (int ks = 0; ks < 4; ks++) {
            uint32_t a[2][4];
            #pragma unroll
            for (int mt = 0; mt < 2; mt++) {
                const int r = wr * 32 + mt * 16;
                a[mt][0] = sA[(r + g) * 36 + ks * 8 + t4];
                a[mt][1] = sA[(r + g + 8) * 36 + ks * 8 + t4];
                a[mt][2] = sA[(r + g) * 36 + ks * 8 + t4 + 4];
                a[mt][3] = sA[(r + g + 8) * 36 + ks * 8 + t4 + 4];
            }
            #pragma unroll
            for (int nt = 0; nt < 2; nt++) {
                const uint32_t b0 = sB[(wc * 16 + nt * 8 + g) * 36 + ks * 8 + t4];
                const uint32_t b1 = sB[(wc * 16 + nt * 8 + g) * 36 + ks * 8 + t4 + 4];
                mma_tf32(c[0][nt], a[0], b0, b1);
                mma_tf32(c[1][nt], a[1], b0, b1);
            }
        }
        __syncthreads();
    }

    #pragma unroll
    for (int mt = 0; mt < 2; mt++)
        #pragma unroll
        for (int nt = 0; nt < 2; nt++) {
            #pragma unroll
            for (int half = 0; half < 2; half++) {
                const int row = row0 + wr * 32 + mt * 16 + g + half * 8;
                const int col = col0 + wc * 16 + nt * 8 + 2 * t4;
                const int idx = (b * KPn + row) * KQn + col;
                const float u2v = g_u2[b * KPn + row];
                float U0 = c[mt][nt][half * 2 + 0] + g_u1[b * KQn + col] + u2v + g_Umh[idx] + g_Umv[idx];
                float U1 = c[mt][nt][half * 2 + 1] + g_u1[b * KQn + col + 1] + u2v + g_Umh[idx + 1] + g_Umv[idx + 1];
                if (mask[idx] < 0.5f) U0 = NEGV;
                if (mask[idx + 1] < 0.5f) U1 = NEGV;
                *reinterpret_cast<float2*>(g_U + idx) = make_float2(U0, U1);
            }
        }
}

// ---------------- K5: both softmax aggregations (z = dir) ----------------
__global__ __launch_bounds__(256) void k5_soft(const float* __restrict__ Eq, const float* __restrict__ Ep)
{
    const int b = blockIdx.x, y = blockIdx.y, dir = blockIdx.z;
    __shared__ float sw[192];
    __shared__ float red[256];
    const int tid = threadIdx.x;

    float v;
    if (dir == 0) v = (tid < KQn) ? g_U[(b * KPn + y) * KQn + tid] : -3.4e38f;
    else          v = (tid < KPn) ? g_U[(b * KPn + tid) * KQn + y] : -3.4e38f;
    red[tid] = v; __syncthreads();
    for (int o = 128; o; o >>= 1) { if (tid < o) red[tid] = fmaxf(red[tid], red[tid + o]); __syncthreads(); }
    const float m = red[0]; __syncthreads();
    const float e = (tid < 192) ? __expf(v - m) : 0.f;
    red[tid] = e; __syncthreads();
    for (int o = 128; o; o >>= 1) { if (tid < o) red[tid] += red[tid + o]; __syncthreads(); }
    const float inv = 1.f / red[0];
    if (tid < 192) sw[tid] = e * inv;
    __syncthreads();

    const int h = tid;
    float a0 = 0.f, a1 = 0.f;
    if (dir == 0) {
        for (int k = 0; k < KQn; k += 2) {
            a0 += sw[k] * Eq[(b * KQn + k) * Hn + h];
            a1 += sw[k + 1] * Eq[(b * KQn + k + 1) * Hn + h];
        }
        const float a = a0 + a1;
        const float ep = Ep[(b * KPn + y) * Hn + h];
        float* G = g_Gl + (b * KPn + y) * Rn;
        G[h] = ep; G[Hn + h] = a; G[2 * Hn + h] = ep * a;
    } else {
        for (int k = 0; k < KPn; k += 2) {
            a0 += sw[k] * Ep[(b * KPn + k) * Hn + h];
            a1 += sw[k + 1] * Ep[(b * KPn + k + 1) * Hn + h];
        }
        const float a = a0 + a1;
        const float eq = Eq[(b * KQn + y) * Hn + h];
        float* G = g_Gr + (b * KQn + y) * Rn;
        G[h] = eq; G[Hn + h] = a; G[2 * Hn + h] = eq * a;
    }
}

// ---------------- K6: gates via tf32 MMA, 64x64 tile ----------------
__global__ __launch_bounds__(256) void k6_gate(
    const float* __restrict__ Wl, const float* __restrict__ bl,
    const float* __restrict__ Wr, const float* __restrict__ br)
{
    __shared__ uint32_t sG[64 * 36];
    __shared__ uint32_t sW[64 * 36];

    const int side = blockIdx.z;
    const float* __restrict__ G = side ? g_Gr : g_Gl;
    const float* __restrict__ W = side ? Wr : Wl;
    const float* __restrict__ bias = side ? br : bl;
    float* __restrict__ outp = side ? g_right : g_left;
    const int row0 = blockIdx.y * 64;
    const int col0 = blockIdx.x * 64;

    const int tid = threadIdx.x;
    const int wid = tid >> 5, lane = tid & 31, g = lane >> 2, t4 = lane & 3;
    const int wr = wid >> 2, wc = wid & 3;
    float c[2][2][4] = {};

    for (int kc = 0; kc < Rn; kc += 32) {
        #pragma unroll
        for (int h = 0; h < 2; h++) {
            const int i = tid + h * 256;
            const int r = i >> 3, j4 = i & 7;
            float4 gv = *reinterpret_cast<const float4*>(G + (row0 + r) * Rn + kc + j4 * 4);
            uint32_t* dg = sG + r * 36 + j4 * 4;
            dg[0] = tf32cvt(gv.x); dg[1] = tf32cvt(gv.y); dg[2] = tf32cvt(gv.z); dg[3] = tf32cvt(gv.w);
            float4 wv = *reinterpret_cast<const float4*>(W + (col0 + r) * Rn + kc + j4 * 4);
            uint32_t* dw = sW + r * 36 + j4 * 4;
            dw[0] = tf32cvt(wv.x); dw[1] = tf32cvt(wv.y); dw[2] = tf32cvt(wv.z); dw[3] = tf32cvt(wv.w);
        }
        __syncthreads();
        #pragma unroll
        for (int ks = 0; ks < 4; ks++) {
            uint32_t a[2][4];
            #pragma unroll
            for (int mt = 0; mt < 2; mt++) {
                const int r = wr * 32 + mt * 16;
                a[mt][0] = sG[(r + g) * 36 + ks * 8 + t4];
                a[mt][1] = sG[(r + g + 8) * 36 + ks * 8 + t4];
                a[mt][2] = sG[(r + g) * 36 + ks * 8 + t4 + 4];
                a[mt][3] = sG[(r + g + 8) * 36 + ks * 8 + t4 + 4];
            }
            #pragma unroll
            for (int nt = 0; nt < 2; nt++) {
                const uint32_t b0 = sW[(wc * 16 + nt * 8 + g) * 36 + ks * 8 + t4];
                const uint32_t b1 = sW[(wc * 16 + nt * 8 + g) * 36 + ks * 8 + t4 + 4];
                mma_tf32(c[0][nt], a[0], b0, b1);
                mma_tf32(c[1][nt], a[1], b0, b1);
            }
        }
        __syncthreads();
    }

    #pragma unroll
    for (int mt = 0; mt < 2; mt++)
        #pragma unroll
        for (int nt = 0; nt < 2; nt++) {
            const int row = row0 + wr * 32 + mt * 16 + g;
            const int col = col0 + wc * 16 + nt * 8 + 2 * t4;
            const float b0f = bias[col], b1f = bias[col + 1];
            {
                float2 gv = *reinterpret_cast<const float2*>(G + row * Rn + col);
                const float s0 = 1.f / (1.f + __expf(-(c[mt][nt][0] + b0f)));
                const float s1 = 1.f / (1.f + __expf(-(c[mt][nt][1] + b1f)));
                *reinterpret_cast<float2*>(outp + row * Rn + col) = make_float2(s0 * gv.x, s1 * gv.y);
            }
            {
                float2 gv = *reinterpret_cast<const float2*>(G + (row + 8) * Rn + col);
                const float s2 = 1.f / (1.f + __expf(-(c[mt][nt][2] + b0f)));
                const float s3 = 1.f / (1.f + __expf(-(c[mt][nt][3] + b1f)));
                *reinterpret_cast<float2*>(outp + (row + 8) * Rn + col) = make_float2(s2 * gv.x, s3 * gv.y);
            }
        }
}

// ---------------- K7: split-K partials via 3-term split-tf32 MMA ----------------
__global__ __launch_bounds__(256) void k7_partial()
{
    __shared__ uint32_t hA[64 * 36], lA[64 * 36], hB[64 * 36], lB[64 * 36];

    const int z = blockIdx.z;
    const int b = z >> 2, ksz = z & 3;
    const int kbase = ksz * 192;
    const float* __restrict__ A = g_left + b * KPn * Rn;
    const float* __restrict__ Bm = g_right + b * KQn * Rn;
    const int row0 = blockIdx.y * 64;
    const int col0 = blockIdx.x * 64;
    const int tid = threadIdx.x;
    const int wid = tid >> 5, lane = tid & 31, g = lane >> 2, t4 = lane & 3;
    const int wr = wid >> 2, wc = wid & 3;
    float c[2][2][4] = {};

    for (int kc = kbase; kc < kbase + 192; kc += 32) {
        #pragma unroll
        for (int h = 0; h < 2; h++) {
            const int i = tid + h * 256;
            const int r = i >> 3, j4 = i & 7;
            float4 av = *reinterpret_cast<const float4*>(A + (row0 + r) * Rn + kc + j4 * 4);
            float4 bv = *reinterpret_cast<const float4*>(Bm + (col0 + r) * Rn + kc + j4 * 4);
            #pragma unroll
            for (int e = 0; e < 4; e++) {
                const float xa = (&av.x)[e];
                const uint32_t ha = tf32cvt(xa);
                hA[r * 36 + j4 * 4 + e] = ha;
                lA[r * 36 + j4 * 4 + e] = tf32cvt(xa - __uint_as_float(ha));
                const float xb = (&bv.x)[e];
                const uint32_t hb = tf32cvt(xb);
                hB[r * 36 + j4 * 4 + e] = hb;
                lB[r * 36 + j4 * 4 + e] = tf32cvt(xb - __uint_as_float(hb));
            }
        }
        __syncthreads();
        #pragma unroll
        for (int ks = 0; ks < 4; ks++) {
            uint32_t aH[2][4], aL[2][4];
            #pragma unroll
            for (int mt = 0; mt < 2; mt++) {
                const int r = wr * 32 + mt * 16;
                aH[mt][0] = hA[(r + g) * 36 + ks * 8 + t4];
                aH[mt][1] = hA[(r + g + 8) * 36 + ks * 8 + t4];
                aH[mt][2] = hA[(r + g) * 36 + ks * 8 + t4 + 4];
                aH[mt][3] = hA[(r + g + 8) * 36 + ks * 8 + t4 + 4];
                aL[mt][0] = lA[(r + g) * 36 + ks * 8 + t4];
                aL[mt][1] = lA[(r + g + 8) * 36 + ks * 8 + t4];
                aL[mt][2] = lA[(r + g) * 36 + ks * 8 + t4 + 4];
                aL[mt][3] = lA[(r + g + 8) * 36 + ks * 8 + t4 + 4];
            }
            #pragma unroll
            for (int nt = 0; nt < 2; nt++) {
                const int rb = wc * 16 + nt * 8 + g;
                const uint32_t bh0 = hB[rb * 36 + ks * 8 + t4];
                const uint32_t bh1 = hB[rb * 36 + ks * 8 + t4 + 4];
                const uint32_t bl0 = lB[rb * 36 + ks * 8 + t4];
                const uint32_t bl1 = lB[rb * 36 + ks * 8 + t4 + 4];
                #pragma unroll
                for (int mt = 0; mt < 2; mt++) {
                    mma_tf32(c[mt][nt], aH[mt], bh0, bh1);
                    mma_tf32(c[mt][nt], aH[mt], bl0, bl1);
                    mma_tf32(c[mt][nt], aL[mt], bh0, bh1);
                }
            }
        }
        __syncthreads();
    }

    float* dst = g_part + ksz * (BB * KPn * KQn) + b * (KPn * KQn);
    #pragma unroll
    for (int mt = 0; mt < 2; mt++)
        #pragma unroll
        for (int nt = 0; nt < 2; nt++)
            #pragma unroll
            for (int half = 0; half < 2; half++) {
                const int row = row0 + wr * 32 + mt * 16 + g + half * 8;
                const int col = col0 + wc * 16 + nt * 8 + 2 * t4;
                *reinterpret_cast<float2*>(dst + row * KQn + col) =
                    make_float2(c[mt][nt][half * 2 + 0], c[mt][nt][half * 2 + 1]);
            }
}

// ---------------- K8: reduce split-K + relu ----------------
__global__ __launch_bounds__(256) void k8_reduce(float* __restrict__ outp)
{
    const int idx = blockIdx.x * 256 + threadIdx.x;
    const int n = BB * KPn * KQn;
    if (idx < n) {
        float s = (g_part[idx] + g_part[n + idx]) + (g_part[2 * n + idx] + g_part[3 * n + idx]);
        outp[idx] = fmaxf(s, 0.f);
    }
}

// ---------------- launch ----------------
extern "C" void kernel_launch(void* const* d_in, const int* in_sizes, int n_in,
                              void* d_out, int out_size)
{
    const float* Eq    = (const float*)d_in[0];
    const float* Ep    = (const float*)d_in[1];
    const float* mask  = (const float*)d_in[2];
    const float* W_in  = (const float*)d_in[3];
    const float* Wq    = (const float*)d_in[4];
    const float* bq    = (const float*)d_in[5];
    const float* Wk    = (const float*)d_in[6];
    const float* bk    = (const float*)d_in[7];
    const float* Wv    = (const float*)d_in[8];
    const float* bv    = (const float*)d_in[9];
    const float* Wo1   = (const float*)d_in[10];
    const float* bo1   = (const float*)d_in[11];
    const float* Wo2   = (const float*)d_in[12];
    const float* bo2   = (const float*)d_in[13];
    const float* W_out = (const float*)d_in[14];
    const float* Wl    = (const float*)d_in[15];
    const float* bl    = (const float*)d_in[16];
    const float* Wr    = (const float*)d_in[17];
    const float* br    = (const float*)d_in[18];
    float* outp = (float*)d_out;

    const int smemAttn = 2 * 192 * SPAD * 4 + 192 * 8;                 // 56832 B
    const int smemK1 = (32 * 260 + 192 * 36) * 4 + (Hn + Tn) * 4;      // 62080 B
    cudaFuncSetAttribute(k23_attn, cudaFuncAttributeMaxDynamicSharedMemorySize, smemAttn);
    cudaFuncSetAttribute(k1_pair, cudaFuncAttributeMaxDynamicSharedMemorySize, smemK1);

    k0_rowproj<<<dim3(BB, 2, 4), dim3(32, 8)>>>(Eq, Ep, W_in, W_out);
    k0b_wv4<<<1, 32>>>(Wv, bv, W_out);
    k1_pair<<<dim3(BB, KPn), 192, smemK1>>>(Eq, Ep, W_in, Wq, bq, Wk, bk, Wo1, bo1, Wo2, bo2);
    k23_attn<<<dim3(BB, 192, 2), 192, smemAttn>>>(mask);
    k4_U<<<dim3(3, 3, BB), 256>>>(Eq, Ep, W_out, mask);
    k5_soft<<<dim3(BB, 192, 2), 256>>>(Eq, Ep);
    k6_gate<<<dim3(12, 12, 2), 256>>>(Wl, bl, Wr, br);
    k7_partial<<<dim3(3, 3, 16), 256>>>();
    k8_reduce<<<dim3(576), 256>>>(outp);
}